// round 2
// baseline (speedup 1.0000x reference)
#include <cuda_runtime.h>
#include <cuda_bf16.h>
#include <math.h>

// ---------------------------------------------------------------------------
// Problem constants
// ---------------------------------------------------------------------------
#define QLEN     1024
#define HID      3584
#define NHEADS   28
#define NKV      4
#define HDIM     128
#define PASTLEN  3072
#define KVTOT    4096
#define NREP     7            // NHEADS / NKV
#define QKV_N    4608         // 3584 + 512 + 512

typedef unsigned long long ull;

// ---------------------------------------------------------------------------
// Scratch (device globals: the sanctioned no-alloc workaround)
// ---------------------------------------------------------------------------
__device__ float g_Q[QLEN * HID];        // [q][h*128+d]
__device__ float g_K[QLEN * (NKV*HDIM)]; // [q][kvh*128+d]
__device__ float g_V[QLEN * (NKV*HDIM)];
__device__ float g_A[QLEN * HID];        // attention output, [q][h*128+d]

// ---------------------------------------------------------------------------
// Packed f32x2 helpers (sm_103a): doubles fp32 FMA throughput
// ---------------------------------------------------------------------------
__device__ __forceinline__ ull dup2(float x) {
    ull r; asm("mov.b64 %0, {%1, %1};" : "=l"(r) : "f"(x)); return r;
}
__device__ __forceinline__ void fma2(ull& d, ull a, ull b) {
    asm("fma.rn.f32x2 %0, %1, %2, %0;" : "+l"(d) : "l"(a), "l"(b));
}
__device__ __forceinline__ void mul2(ull& d, ull a) {
    asm("mul.rn.f32x2 %0, %0, %1;" : "+l"(d) : "l"(a));
}
__device__ __forceinline__ float2 unpk(ull v) {
    float2 r; asm("mov.b64 {%0, %1}, %2;" : "=f"(r.x), "=f"(r.y) : "l"(v)); return r;
}

// ---------------------------------------------------------------------------
// 128x128x8 register-blocked GEMM tile (8x8 microtile per thread, 256 thr)
// C[128,128] = A[128,K] @ B[K,128] (+bias).  A,B,C row-major.
// A: points at row-block start. B/bias/C: point at column-block start.
// Requires K % 8 == 0, 16B-aligned rows (all shapes here satisfy this).
// ---------------------------------------------------------------------------
__device__ __forceinline__ void sgemm_tile(
    const float* __restrict__ A, int lda,
    const float* __restrict__ B, int ldb,
    const float* __restrict__ bias,
    float* __restrict__ C, int ldc, int K)
{
    __shared__ float As[8][128];   // transposed: As[k][m]
    __shared__ float Bs[8][128];   // natural:    Bs[k][n]

    const int tid  = threadIdx.x;
    const int aRow = tid >> 1;            // 0..127
    const int aCol = (tid & 1) << 2;      // 0 or 4
    const int bRow = tid >> 5;            // 0..7
    const int bCol = (tid & 31) << 2;     // 0..124
    const int tr   = (tid >> 4) << 3;     // 0..120
    const int tc   = (tid & 15) << 3;     // 0..120

    ull acc[8][4];
    #pragma unroll
    for (int i = 0; i < 8; i++)
        #pragma unroll
        for (int j = 0; j < 4; j++) acc[i][j] = 0ull;

    for (int k0 = 0; k0 < K; k0 += 8) {
        float4 av = *(const float4*)(A + (size_t)aRow * lda + k0 + aCol);
        As[aCol + 0][aRow] = av.x;
        As[aCol + 1][aRow] = av.y;
        As[aCol + 2][aRow] = av.z;
        As[aCol + 3][aRow] = av.w;
        *(float4*)&Bs[bRow][bCol] =
            *(const float4*)(B + (size_t)(k0 + bRow) * ldb + bCol);
        __syncthreads();
        #pragma unroll
        for (int kk = 0; kk < 8; kk++) {
            float4 a0 = *(const float4*)&As[kk][tr];
            float4 a1 = *(const float4*)&As[kk][tr + 4];
            ulonglong2 b01 = *(const ulonglong2*)&Bs[kk][tc];
            ulonglong2 b23 = *(const ulonglong2*)&Bs[kk][tc + 4];
            ull rb[4] = { b01.x, b01.y, b23.x, b23.y };
            float ra[8] = { a0.x, a0.y, a0.z, a0.w, a1.x, a1.y, a1.z, a1.w };
            #pragma unroll
            for (int i = 0; i < 8; i++) {
                ull ad = dup2(ra[i]);
                #pragma unroll
                for (int j = 0; j < 4; j++) fma2(acc[i][j], ad, rb[j]);
            }
        }
        __syncthreads();
    }

    #pragma unroll
    for (int i = 0; i < 8; i++) {
        float o[8];
        #pragma unroll
        for (int j = 0; j < 4; j++) {
            float2 u = unpk(acc[i][j]);
            o[2 * j] = u.x; o[2 * j + 1] = u.y;
        }
        if (bias) {
            #pragma unroll
            for (int j = 0; j < 8; j++) o[j] += bias[tc + j];
        }
        float* Cp = C + (size_t)(tr + i) * ldc + tc;
        *(float4*)Cp       = make_float4(o[0], o[1], o[2], o[3]);
        *(float4*)(Cp + 4) = make_float4(o[4], o[5], o[6], o[7]);
    }
}

// Fused QKV projection: grid (36, 8). bx<28 -> Q, 28..31 -> K, 32..35 -> V.
__global__ __launch_bounds__(256)
void qkv_kernel(const float* __restrict__ hid,
                const float* __restrict__ Wq, const float* __restrict__ bq,
                const float* __restrict__ Wk, const float* __restrict__ bk,
                const float* __restrict__ Wv, const float* __restrict__ bv,
                float* __restrict__ Qo, float* __restrict__ Ko, float* __restrict__ Vo)
{
    const int bx = blockIdx.x, by = blockIdx.y;
    const float* A = hid + (size_t)by * 128 * HID;
    if (bx < 28) {
        int c = bx * 128;
        sgemm_tile(A, HID, Wq + c, HID, bq + c,
                   Qo + (size_t)by * 128 * HID + c, HID, HID);
    } else if (bx < 32) {
        int c = (bx - 28) * 128;
        sgemm_tile(A, HID, Wk + c, NKV * HDIM, bk + c,
                   Ko + (size_t)by * 128 * (NKV * HDIM) + c, NKV * HDIM, HID);
    } else {
        int c = (bx - 32) * 128;
        sgemm_tile(A, HID, Wv + c, NKV * HDIM, bv + c,
                   Vo + (size_t)by * 128 * (NKV * HDIM) + c, NKV * HDIM, HID);
    }
}

// Output projection: grid (28, 8)
__global__ __launch_bounds__(256)
void oproj_kernel(const float* __restrict__ A, const float* __restrict__ Wo,
                  float* __restrict__ out)
{
    const int bx = blockIdx.x, by = blockIdx.y;
    sgemm_tile(A + (size_t)by * 128 * HID, HID, Wo + bx * 128, HID, nullptr,
               out + (size_t)by * 128 * HID + bx * 128, HID, HID);
}

// ---------------------------------------------------------------------------
// RoPE (in place). X layout [q][h*128+d], stride = row stride in floats.
// Replicates jax fp32 math: invf = 1/(1e6^(i/64)), ang = pos*invf (fp32).
// ---------------------------------------------------------------------------
__global__ void rope_kernel(float* __restrict__ X, const int* __restrict__ pos,
                            int stride, int nh)
{
    const int q = blockIdx.x;
    const float p = (float)pos[q];
    for (int t = threadIdx.x; t < nh * 64; t += blockDim.x) {
        int hh = t >> 6;
        int i  = t & 63;
        float e = (float)i * (1.0f / 64.0f);
        float invf = 1.0f / powf(1000000.0f, e);
        float ang = p * invf;
        float s, c;
        sincosf(ang, &s, &c);
        float* base = X + (size_t)q * stride + hh * HDIM;
        float x1 = base[i];
        float x2 = base[i + 64];
        base[i]      = x1 * c - x2 * s;
        base[i + 64] = x2 * c + x1 * s;
    }
}

// ---------------------------------------------------------------------------
// Flash attention: grid (16 q-tiles, 28 heads), 256 threads.
// 64 q x 64 kv tiles, D=128. Online softmax kept per-thread in registers
// (each 16-lane half-warp owns 4 q-rows; shuffles reduce across lanes).
// smem: Qt[128][64] (transposed), KV[8192] (Kt[d][k] then Vs[k][d]), Ps[64][64].
// ---------------------------------------------------------------------------
#define FLASH_SMEM_FLOATS (128*64 + 128*64 + 64*64)

__global__ __launch_bounds__(256)
void flash_kernel(const float* __restrict__ Q, const float* __restrict__ Knew,
                  const float* __restrict__ Vnew, const float* __restrict__ kcache,
                  const float* __restrict__ vcache, float* __restrict__ Out)
{
    extern __shared__ float sm[];
    float* Qt = sm;                    // [128][64]
    float* KV = sm + 128 * 64;         // Kt [128][64]  or  Vs [64][128]
    float* Ps = KV + 128 * 64;         // [64][64]

    const int tid = threadIdx.x;
    const int qt  = blockIdx.x;        // 0..15
    const int h   = blockIdx.y;        // 0..27
    const int kvh = h / NREP;
    const int q0  = qt * 64;

    const int sr = (tid >> 4) << 2;    // q-row base (0..60), one half-warp per group
    const int sc = (tid & 15) << 2;    // S col base (0..60)
    const int oc = (tid & 15) << 3;    // O col base (0..120)

    // ---- load Q tile, transposed ----
    {
        const float* Qg = Q + (size_t)q0 * HID + (size_t)h * HDIM;
        #pragma unroll
        for (int it = 0; it < 8; it++) {
            int idx = tid + it * 256;
            int r = idx >> 5, d4 = (idx & 31) << 2;
            float4 v = *(const float4*)(Qg + (size_t)r * HID + d4);
            Qt[(d4 + 0) * 64 + r] = v.x;
            Qt[(d4 + 1) * 64 + r] = v.y;
            Qt[(d4 + 2) * 64 + r] = v.z;
            Qt[(d4 + 3) * 64 + r] = v.w;
        }
    }

    float m_i[4], l_i[4];
    #pragma unroll
    for (int i = 0; i < 4; i++) { m_i[i] = -INFINITY; l_i[i] = 0.0f; }
    ull Oa[4][4];
    #pragma unroll
    for (int i = 0; i < 4; i++)
        #pragma unroll
        for (int j = 0; j < 4; j++) Oa[i][j] = 0ull;

    const int ntiles = (PASTLEN / 64) + qt + 1;
    const float scale = 0.088388347648318447f;  // 1/sqrt(128)

    for (int t = 0; t < ntiles; t++) {
        const int kvbase = t << 6;
        __syncthreads();   // prior PV done with KV & Ps

        // ---- load K tile, transposed into KV as Kt[d][k] ----
        {
            const float* Kg; int kst;
            if (kvbase < PASTLEN) {
                Kg = kcache + ((size_t)kvh * PASTLEN + kvbase) * HDIM; kst = HDIM;
            } else {
                Kg = Knew + (size_t)(kvbase - PASTLEN) * (NKV * HDIM) + (size_t)kvh * HDIM;
                kst = NKV * HDIM;
            }
            #pragma unroll
            for (int it = 0; it < 8; it++) {
                int idx = tid + it * 256;
                int r = idx >> 5, d4 = (idx & 31) << 2;
                float4 v = *(const float4*)(Kg + (size_t)r * kst + d4);
                KV[(d4 + 0) * 64 + r] = v.x;
                KV[(d4 + 1) * 64 + r] = v.y;
                KV[(d4 + 2) * 64 + r] = v.z;
                KV[(d4 + 3) * 64 + r] = v.w;
            }
        }
        __syncthreads();

        // ---- S = Q K^T  (4x4 per thread) ----
        ull Sa[4][2];
        #pragma unroll
        for (int i = 0; i < 4; i++) { Sa[i][0] = 0ull; Sa[i][1] = 0ull; }
        #pragma unroll 4
        for (int d = 0; d < 128; d++) {
            float4 qa = *(const float4*)&Qt[d * 64 + sr];
            ulonglong2 kb = *(const ulonglong2*)&KV[d * 64 + sc];
            float qv[4] = { qa.x, qa.y, qa.z, qa.w };
            #pragma unroll
            for (int i = 0; i < 4; i++) {
                ull qd = dup2(qv[i]);
                fma2(Sa[i][0], qd, kb.x);
                fma2(Sa[i][1], qd, kb.y);
            }
        }
        float S[4][4];
        #pragma unroll
        for (int i = 0; i < 4; i++) {
            float2 u0 = unpk(Sa[i][0]);
            float2 u1 = unpk(Sa[i][1]);
            S[i][0] = u0.x * scale; S[i][1] = u0.y * scale;
            S[i][2] = u1.x * scale; S[i][3] = u1.y * scale;
        }
        if (t == ntiles - 1) {   // diagonal tile: k_local > q_local is masked
            #pragma unroll
            for (int i = 0; i < 4; i++)
                #pragma unroll
                for (int j = 0; j < 4; j++)
                    if (sc + j > sr + i) S[i][j] = -INFINITY;
        }

        // ---- online softmax (registers + half-warp shuffles) ----
        #pragma unroll
        for (int i = 0; i < 4; i++) {
            float mx = fmaxf(fmaxf(S[i][0], S[i][1]), fmaxf(S[i][2], S[i][3]));
            #pragma unroll
            for (int off = 8; off; off >>= 1)
                mx = fmaxf(mx, __shfl_xor_sync(0xffffffffu, mx, off));
            float mnew = fmaxf(m_i[i], mx);
            float p0 = expf(S[i][0] - mnew);
            float p1 = expf(S[i][1] - mnew);
            float p2 = expf(S[i][2] - mnew);
            float p3 = expf(S[i][3] - mnew);
            float rs = (p0 + p1) + (p2 + p3);
            #pragma unroll
            for (int off = 8; off; off >>= 1)
                rs += __shfl_xor_sync(0xffffffffu, rs, off);
            float corr = expf(m_i[i] - mnew);
            m_i[i] = mnew;
            l_i[i] = l_i[i] * corr + rs;
            ull cd = dup2(corr);
            #pragma unroll
            for (int j = 0; j < 4; j++) mul2(Oa[i][j], cd);
            *(float4*)&Ps[(sr + i) * 64 + sc] = make_float4(p0, p1, p2, p3);
        }
        __syncthreads();   // Ps visible; all threads done reading Kt

        // ---- load V tile into KV as Vs[k][d] ----
        {
            const float* Vg; int vst;
            if (kvbase < PASTLEN) {
                Vg = vcache + ((size_t)kvh * PASTLEN + kvbase) * HDIM; vst = HDIM;
            } else {
                Vg = Vnew + (size_t)(kvbase - PASTLEN) * (NKV * HDIM) + (size_t)kvh * HDIM;
                vst = NKV * HDIM;
            }
            #pragma unroll
            for (int it = 0; it < 8; it++) {
                int idx = tid + it * 256;
                int r = idx >> 5, d4 = (idx & 31) << 2;
                *(float4*)&KV[r * 128 + d4] = *(const float4*)(Vg + (size_t)r * vst + d4);
            }
        }
        __syncthreads();

        // ---- O += P @ V  (4 rows x 8 cols per thread) ----
        #pragma unroll 2
        for (int kk = 0; kk < 64; kk++) {
            ulonglong2 v01 = *(const ulonglong2*)&KV[kk * 128 + oc];
            ulonglong2 v23 = *(const ulonglong2*)&KV[kk * 128 + oc + 4];
            #pragma unroll
            for (int i = 0; i < 4; i++) {
                ull pd = dup2(Ps[(sr + i) * 64 + kk]);
                fma2(Oa[i][0], pd, v01.x);
                fma2(Oa[i][1], pd, v01.y);
                fma2(Oa[i][2], pd, v23.x);
                fma2(Oa[i][3], pd, v23.y);
            }
        }
    }

    // ---- epilogue: normalize and store ----
    #pragma unroll
    for (int i = 0; i < 4; i++) {
        float inv = 1.0f / l_i[i];
        float o[8];
        #pragma unroll
        for (int j = 0; j < 4; j++) {
            float2 u = unpk(Oa[i][j]);
            o[2 * j] = u.x * inv; o[2 * j + 1] = u.y * inv;
        }
        float* Op = Out + (size_t)(q0 + sr + i) * HID + (size_t)h * HDIM + oc;
        *(float4*)Op       = make_float4(o[0], o[1], o[2], o[3]);
        *(float4*)(Op + 4) = make_float4(o[4], o[5], o[6], o[7]);
    }
}

// ---------------------------------------------------------------------------
// Launch
// ---------------------------------------------------------------------------
extern "C" void kernel_launch(void* const* d_in, const int* in_sizes, int n_in,
                              void* d_out, int out_size)
{
    const float* hid = (const float*)d_in[0];
    const float* kc  = (const float*)d_in[1];
    const float* vc  = (const float*)d_in[2];
    const float* Wq  = (const float*)d_in[3];
    const float* bq  = (const float*)d_in[4];
    const float* Wk  = (const float*)d_in[5];
    const float* bk  = (const float*)d_in[6];
    const float* Wv  = (const float*)d_in[7];
    const float* bv  = (const float*)d_in[8];
    const float* Wo  = (const float*)d_in[9];
    const int*   pos = (const int*)d_in[10];
    float* out = (float*)d_out;

    float *gQ, *gK, *gV, *gA;
    cudaGetSymbolAddress((void**)&gQ, g_Q);
    cudaGetSymbolAddress((void**)&gK, g_K);
    cudaGetSymbolAddress((void**)&gV, g_V);
    cudaGetSymbolAddress((void**)&gA, g_A);

    const int flash_smem = FLASH_SMEM_FLOATS * (int)sizeof(float);  // 81920 B
    cudaFuncSetAttribute(flash_kernel,
                         cudaFuncAttributeMaxDynamicSharedMemorySize, flash_smem);

    dim3 gq(36, 8);
    qkv_kernel<<<gq, 256>>>(hid, Wq, bq, Wk, bk, Wv, bv, gQ, gK, gV);

    rope_kernel<<<QLEN, 256>>>(gQ, pos, HID, NHEADS);
    rope_kernel<<<QLEN, 256>>>(gK, pos, NKV * HDIM, NKV);

    dim3 gf(16, 28);
    flash_kernel<<<gf, 256, flash_smem>>>(gQ, gK, gV, kc, vc, gA);

    dim3 go(28, 8);
    oproj_kernel<<<go, 256>>>(gA, Wo, out);
}

// round 5
// speedup vs baseline: 1.1273x; 1.1273x over previous
#include <cuda_runtime.h>
#include <cuda_bf16.h>
#include <cstdint>
#include <math.h>

// ---------------------------------------------------------------------------
// Problem constants
// ---------------------------------------------------------------------------
#define QLEN     1024
#define HID      3584
#define NHEADS   28
#define NKV      4
#define HDIM     128
#define PASTLEN  3072
#define NREP     7

typedef unsigned long long ull;

// ---------------------------------------------------------------------------
// Scratch (device globals: the sanctioned no-alloc workaround)
// ---------------------------------------------------------------------------
__device__ float g_Q[QLEN * HID];
__device__ float g_K[QLEN * (NKV*HDIM)];
__device__ float g_V[QLEN * (NKV*HDIM)];
__device__ float g_A[QLEN * HID];

// split-bf16 operands
__device__ __nv_bfloat16 g_hid_hi[QLEN * HID];
__device__ __nv_bfloat16 g_hid_lo[QLEN * HID];
__device__ __nv_bfloat16 g_att_hi[QLEN * HID];
__device__ __nv_bfloat16 g_att_lo[QLEN * HID];
__device__ __nv_bfloat16 g_WqT_hi[HID * HID];
__device__ __nv_bfloat16 g_WqT_lo[HID * HID];
__device__ __nv_bfloat16 g_WkT_hi[(NKV*HDIM) * HID];
__device__ __nv_bfloat16 g_WkT_lo[(NKV*HDIM) * HID];
__device__ __nv_bfloat16 g_WvT_hi[(NKV*HDIM) * HID];
__device__ __nv_bfloat16 g_WvT_lo[(NKV*HDIM) * HID];
__device__ __nv_bfloat16 g_WoT_hi[HID * HID];
__device__ __nv_bfloat16 g_WoT_lo[HID * HID];

// ---------------------------------------------------------------------------
// Helpers (plain-sm_103-legal: cp.async + ldmatrix + mma.sync only)
// ---------------------------------------------------------------------------
__device__ __forceinline__ uint32_t smem_to_u32(const void* p) {
    uint32_t a;
    asm("{ .reg .u64 t; cvta.to.shared.u64 t, %1; cvt.u32.u64 %0, t; }" : "=r"(a) : "l"(p));
    return a;
}
#define SMEM_SWIZZLE_128B(b) ((b) ^ (((b) >> 3) & 0x70))

__device__ __forceinline__ void cp_async16(uint32_t dst, const void* src) {
    asm volatile("cp.async.cg.shared.global [%0], [%1], 16;" :: "r"(dst), "l"(src) : "memory");
}
__device__ __forceinline__ void cp_commit() {
    asm volatile("cp.async.commit_group;" ::: "memory");
}
template <int N> __device__ __forceinline__ void cp_wait() {
    asm volatile("cp.async.wait_group %0;" :: "n"(N) : "memory");
}

__device__ __forceinline__ void ldm_x4(uint32_t* r, uint32_t addr) {
    asm volatile("ldmatrix.sync.aligned.m8n8.x4.shared.b16 {%0,%1,%2,%3}, [%4];"
                 : "=r"(r[0]), "=r"(r[1]), "=r"(r[2]), "=r"(r[3]) : "r"(addr));
}
__device__ __forceinline__ void mma_bf16(float* c, const uint32_t* a, const uint32_t* b) {
    asm volatile("mma.sync.aligned.m16n8k16.row.col.f32.bf16.bf16.f32 "
                 "{%0,%1,%2,%3}, {%4,%5,%6,%7}, {%8,%9}, {%0,%1,%2,%3};"
                 : "+f"(c[0]), "+f"(c[1]), "+f"(c[2]), "+f"(c[3])
                 : "r"(a[0]), "r"(a[1]), "r"(a[2]), "r"(a[3]), "r"(b[0]), "r"(b[1]));
}

// ---------------------------------------------------------------------------
// f32 -> split bf16 (hi + lo)
// ---------------------------------------------------------------------------
__global__ void split_kernel(const float* __restrict__ X,
                             __nv_bfloat16* __restrict__ hi,
                             __nv_bfloat16* __restrict__ lo, int n4)
{
    int i = blockIdx.x * blockDim.x + threadIdx.x;
    if (i >= n4) return;
    float4 x = ((const float4*)X)[i];
    float v[4] = { x.x, x.y, x.z, x.w };
    __nv_bfloat16 h[4], l[4];
    #pragma unroll
    for (int j = 0; j < 4; j++) {
        h[j] = __float2bfloat16(v[j]);
        l[j] = __float2bfloat16(v[j] - __bfloat162float(h[j]));
    }
    __nv_bfloat162* H = (__nv_bfloat162*)hi;
    __nv_bfloat162* L = (__nv_bfloat162*)lo;
    H[2*i]   = __nv_bfloat162(h[0], h[1]);
    H[2*i+1] = __nv_bfloat162(h[2], h[3]);
    L[2*i]   = __nv_bfloat162(l[0], l[1]);
    L[2*i+1] = __nv_bfloat162(l[2], l[3]);
}

// W [K][N] f32  ->  T_hi/T_lo [N][K] bf16  (K-major rows for MMA B operand)
__global__ void transpose_split_kernel(const float* __restrict__ W, int K, int N,
                                       __nv_bfloat16* __restrict__ Thi,
                                       __nv_bfloat16* __restrict__ Tlo)
{
    __shared__ float t[32][33];
    int n0 = blockIdx.x * 32, k0 = blockIdx.y * 32;
    int tx = threadIdx.x, ty = threadIdx.y;
    #pragma unroll
    for (int r = 0; r < 4; r++)
        t[ty + r*8][tx] = W[(size_t)(k0 + ty + r*8) * N + n0 + tx];
    __syncthreads();
    #pragma unroll
    for (int r = 0; r < 4; r++) {
        int n = n0 + ty + r*8;
        float v = t[tx][ty + r*8];
        __nv_bfloat16 h = __float2bfloat16(v);
        __nv_bfloat16 l = __float2bfloat16(v - __bfloat162float(h));
        Thi[(size_t)n * K + k0 + tx] = h;
        Tlo[(size_t)n * K + k0 + tx] = l;
    }
}

// ---------------------------------------------------------------------------
// mma.sync bf16 split-precision GEMM: C[1024][N] = A[1024][3584] @ B^T (+bias)
// A,B as hi/lo bf16; 3 accumulation passes (hi*hi + hi*lo + lo*hi).
// CTA tile 128x128, 8 warps (2x4) of 64x32 each. K-stage 64.
// 4-stage cp.async pipeline into SW128-swizzled smem; ldmatrix.x4 fragments.
// ---------------------------------------------------------------------------
#define MM_STAGES      4
#define MM_STAGE_BYTES 32768            // A 16KB + B 16KB per stage
#define MM_SMEM        (1024 + MM_STAGES * MM_STAGE_BYTES)
#define MM_NST         168              // 3 segments * 56 stages of K=64

__global__ __launch_bounds__(256)
void mm_kernel(const __nv_bfloat16* __restrict__ Ahi, const __nv_bfloat16* __restrict__ Alo,
               const __nv_bfloat16* __restrict__ Bhi, const __nv_bfloat16* __restrict__ Blo,
               const float* __restrict__ bias, float* __restrict__ C, int ldc)
{
    extern __shared__ char smem[];
    const uint32_t sb   = smem_to_u32(smem);
    const uint32_t DATA = (sb + 1023u) & ~1023u;
    const int tid = threadIdx.x, wid = tid >> 5, lane = tid & 31;
    const int n0 = blockIdx.x * 128, m0 = blockIdx.y * 128;
    const int wm = (wid & 1) * 64;       // warp row offset within tile
    const int wn = (wid >> 1) * 32;      // warp col offset within tile

    // per-thread gmem->smem chunk map (16B chunks; 1024 chunks per 16KB operand)
    uint32_t offs[4]; int rr[4], cc[4];
    #pragma unroll
    for (int i = 0; i < 4; i++) {
        int c = tid + i * 256;
        rr[i] = c >> 3;                            // logical row 0..127
        cc[i] = (c & 7) * 8;                       // bf16 col within row
        offs[i] = SMEM_SWIZZLE_128B((uint32_t)(rr[i] * 128 + (c & 7) * 16));
    }

    auto load_stage = [&](int g) {
        int seg = g / 56, kk = (g % 56) * 64;
        const __nv_bfloat16* A = (seg == 2) ? Alo : Ahi;
        const __nv_bfloat16* B = (seg == 1) ? Blo : Bhi;
        uint32_t ab = DATA + (uint32_t)(g & 3) * MM_STAGE_BYTES;
        uint32_t bb = ab + 16384;
        #pragma unroll
        for (int i = 0; i < 4; i++) {
            cp_async16(ab + offs[i], A + (size_t)(m0 + rr[i]) * HID + kk + cc[i]);
            cp_async16(bb + offs[i], B + (size_t)(n0 + rr[i]) * HID + kk + cc[i]);
        }
        cp_commit();
    };

    float acc[4][4][4];                  // [mi 16-row][ni 8-col][frag]
    #pragma unroll
    for (int a = 0; a < 4; a++)
        #pragma unroll
        for (int b = 0; b < 4; b++)
            #pragma unroll
            for (int c = 0; c < 4; c++) acc[a][b][c] = 0.0f;

    // precompute per-lane ldmatrix row/col pieces
    const int a_row = wm + (lane & 15);            // + mi*16
    const int a_kb  = (lane >> 4) * 16;            // + ks*32
    const int b_row = wn + ((lane >> 4) & 1) * 8 + (lane & 7);   // + nb2*16
    const int b_kb  = ((lane >> 3) & 1) * 16;                    // + ks*32

    load_stage(0); load_stage(1); load_stage(2);

    for (int g = 0; g < MM_NST; g++) {
        int spre = g + 3;
        if (spre < MM_NST) load_stage(spre);
        int committed = (spre < MM_NST) ? (spre + 1) : MM_NST;
        int nout = committed - (g + 1);
        if      (nout >= 3) cp_wait<3>();
        else if (nout == 2) cp_wait<2>();
        else if (nout == 1) cp_wait<1>();
        else                cp_wait<0>();
        __syncthreads();

        uint32_t ab = DATA + (uint32_t)(g & 3) * MM_STAGE_BYTES;
        uint32_t bb = ab + 16384;

        #pragma unroll
        for (int ks = 0; ks < 4; ks++) {
            uint32_t aF[4][4];
            #pragma unroll
            for (int mi = 0; mi < 4; mi++) {
                uint32_t byte = (uint32_t)((a_row + mi * 16) * 128 + ks * 32 + a_kb);
                ldm_x4(aF[mi], ab + SMEM_SWIZZLE_128B(byte));
            }
            uint32_t bF[4][2];
            #pragma unroll
            for (int nb2 = 0; nb2 < 2; nb2++) {
                uint32_t byte = (uint32_t)((b_row + nb2 * 16) * 128 + ks * 32 + b_kb);
                uint32_t r[4];
                ldm_x4(r, bb + SMEM_SWIZZLE_128B(byte));
                bF[nb2*2+0][0] = r[0]; bF[nb2*2+0][1] = r[1];
                bF[nb2*2+1][0] = r[2]; bF[nb2*2+1][1] = r[3];
            }
            #pragma unroll
            for (int mi = 0; mi < 4; mi++)
                #pragma unroll
                for (int ni = 0; ni < 4; ni++)
                    mma_bf16(acc[mi][ni], aF[mi], bF[ni]);
        }
        __syncthreads();   // all warps done with buffer before reuse
    }

    // epilogue
    const int group = lane >> 2, tig = lane & 3;
    #pragma unroll
    for (int mi = 0; mi < 4; mi++) {
        #pragma unroll
        for (int ni = 0; ni < 4; ni++) {
            int r0 = m0 + wm + mi * 16 + group;
            int c0 = n0 + wn + ni * 8 + tig * 2;
            float b0 = 0.f, b1 = 0.f;
            if (bias) { b0 = bias[c0]; b1 = bias[c0 + 1]; }
            float2 v0 = make_float2(acc[mi][ni][0] + b0, acc[mi][ni][1] + b1);
            float2 v1 = make_float2(acc[mi][ni][2] + b0, acc[mi][ni][3] + b1);
            *(float2*)(C + (size_t)r0 * ldc + c0)       = v0;
            *(float2*)(C + (size_t)(r0 + 8) * ldc + c0) = v1;
        }
    }
}

// ---------------------------------------------------------------------------
// RoPE (unchanged)
// ---------------------------------------------------------------------------
__global__ void rope_kernel(float* __restrict__ X, const int* __restrict__ pos,
                            int stride, int nh)
{
    const int q = blockIdx.x;
    const float p = (float)pos[q];
    for (int t = threadIdx.x; t < nh * 64; t += blockDim.x) {
        int hh = t >> 6, i = t & 63;
        float e = (float)i * (1.0f / 64.0f);
        float invf = 1.0f / powf(1000000.0f, e);
        float ang = p * invf;
        float s, c;
        sincosf(ang, &s, &c);
        float* base = X + (size_t)q * stride + hh * HDIM;
        float x1 = base[i];
        float x2 = base[i + 64];
        base[i]      = x1 * c - x2 * s;
        base[i + 64] = x2 * c + x1 * s;
    }
}

// ---------------------------------------------------------------------------
// Packed f32x2 helpers
// ---------------------------------------------------------------------------
__device__ __forceinline__ ull dup2(float x) {
    ull r; asm("mov.b64 %0, {%1, %1};" : "=l"(r) : "f"(x)); return r;
}
__device__ __forceinline__ void fma2(ull& d, ull a, ull b) {
    asm("fma.rn.f32x2 %0, %1, %2, %0;" : "+l"(d) : "l"(a), "l"(b));
}
__device__ __forceinline__ void mul2(ull& d, ull a) {
    asm("mul.rn.f32x2 %0, %0, %1;" : "+l"(d) : "l"(a));
}
__device__ __forceinline__ float2 unpk(ull v) {
    float2 r; asm("mov.b64 {%0, %1}, %2;" : "=f"(r.x), "=f"(r.y) : "l"(v)); return r;
}

// ---------------------------------------------------------------------------
// Flash attention (SIMT fp32, f32x2 FMA, __expf softmax)
// ---------------------------------------------------------------------------
#define FLASH_SMEM_FLOATS (128*64 + 128*64 + 64*64)

__global__ __launch_bounds__(256)
void flash_kernel(const float* __restrict__ Q, const float* __restrict__ Knew,
                  const float* __restrict__ Vnew, const float* __restrict__ kcache,
                  const float* __restrict__ vcache, float* __restrict__ Out)
{
    extern __shared__ float sm[];
    float* Qt = sm;
    float* KV = sm + 128 * 64;
    float* Ps = KV + 128 * 64;

    const int tid = threadIdx.x;
    const int qt  = blockIdx.x;
    const int h   = blockIdx.y;
    const int kvh = h / NREP;
    const int q0  = qt * 64;

    const int sr = (tid >> 4) << 2;
    const int sc = (tid & 15) << 2;
    const int oc = (tid & 15) << 3;

    {
        const float* Qg = Q + (size_t)q0 * HID + (size_t)h * HDIM;
        #pragma unroll
        for (int it = 0; it < 8; it++) {
            int idx = tid + it * 256;
            int r = idx >> 5, d4 = (idx & 31) << 2;
            float4 v = *(const float4*)(Qg + (size_t)r * HID + d4);
            Qt[(d4 + 0) * 64 + r] = v.x;
            Qt[(d4 + 1) * 64 + r] = v.y;
            Qt[(d4 + 2) * 64 + r] = v.z;
            Qt[(d4 + 3) * 64 + r] = v.w;
        }
    }

    float m_i[4], l_i[4];
    #pragma unroll
    for (int i = 0; i < 4; i++) { m_i[i] = -INFINITY; l_i[i] = 0.0f; }
    ull Oa[4][4];
    #pragma unroll
    for (int i = 0; i < 4; i++)
        #pragma unroll
        for (int j = 0; j < 4; j++) Oa[i][j] = 0ull;

    const int ntiles = (PASTLEN / 64) + qt + 1;
    const float scale = 0.088388347648318447f;

    for (int t = 0; t < ntiles; t++) {
        const int kvbase = t << 6;
        __syncthreads();

        {
            const float* Kg; int kst;
            if (kvbase < PASTLEN) {
                Kg = kcache + ((size_t)kvh * PASTLEN + kvbase) * HDIM; kst = HDIM;
            } else {
                Kg = Knew + (size_t)(kvbase - PASTLEN) * (NKV * HDIM) + (size_t)kvh * HDIM;
                kst = NKV * HDIM;
            }
            #pragma unroll
            for (int it = 0; it < 8; it++) {
                int idx = tid + it * 256;
                int r = idx >> 5, d4 = (idx & 31) << 2;
                float4 v = *(const float4*)(Kg + (size_t)r * kst + d4);
                KV[(d4 + 0) * 64 + r] = v.x;
                KV[(d4 + 1) * 64 + r] = v.y;
                KV[(d4 + 2) * 64 + r] = v.z;
                KV[(d4 + 3) * 64 + r] = v.w;
            }
        }
        __syncthreads();

        ull Sa[4][2];
        #pragma unroll
        for (int i = 0; i < 4; i++) { Sa[i][0] = 0ull; Sa[i][1] = 0ull; }
        #pragma unroll 4
        for (int d = 0; d < 128; d++) {
            float4 qa = *(const float4*)&Qt[d * 64 + sr];
            ulonglong2 kb = *(const ulonglong2*)&KV[d * 64 + sc];
            float qv[4] = { qa.x, qa.y, qa.z, qa.w };
            #pragma unroll
            for (int i = 0; i < 4; i++) {
                ull qd = dup2(qv[i]);
                fma2(Sa[i][0], qd, kb.x);
                fma2(Sa[i][1], qd, kb.y);
            }
        }
        float S[4][4];
        #pragma unroll
        for (int i = 0; i < 4; i++) {
            float2 u0 = unpk(Sa[i][0]);
            float2 u1 = unpk(Sa[i][1]);
            S[i][0] = u0.x * scale; S[i][1] = u0.y * scale;
            S[i][2] = u1.x * scale; S[i][3] = u1.y * scale;
        }
        if (t == ntiles - 1) {
            #pragma unroll
            for (int i = 0; i < 4; i++)
                #pragma unroll
                for (int j = 0; j < 4; j++)
                    if (sc + j > sr + i) S[i][j] = -INFINITY;
        }

        #pragma unroll
        for (int i = 0; i < 4; i++) {
            float mx = fmaxf(fmaxf(S[i][0], S[i][1]), fmaxf(S[i][2], S[i][3]));
            #pragma unroll
            for (int off = 8; off; off >>= 1)
                mx = fmaxf(mx, __shfl_xor_sync(0xffffffffu, mx, off));
            float mnew = fmaxf(m_i[i], mx);
            float p0 = __expf(S[i][0] - mnew);
            float p1 = __expf(S[i][1] - mnew);
            float p2 = __expf(S[i][2] - mnew);
            float p3 = __expf(S[i][3] - mnew);
            float rs = (p0 + p1) + (p2 + p3);
            #pragma unroll
            for (int off = 8; off; off >>= 1)
                rs += __shfl_xor_sync(0xffffffffu, rs, off);
            float corr = __expf(m_i[i] - mnew);
            m_i[i] = mnew;
            l_i[i] = l_i[i] * corr + rs;
            ull cd = dup2(corr);
            #pragma unroll
            for (int j = 0; j < 4; j++) mul2(Oa[i][j], cd);
            *(float4*)&Ps[(sr + i) * 64 + sc] = make_float4(p0, p1, p2, p3);
        }
        __syncthreads();

        {
            const float* Vg; int vst;
            if (kvbase < PASTLEN) {
                Vg = vcache + ((size_t)kvh * PASTLEN + kvbase) * HDIM; vst = HDIM;
            } else {
                Vg = Vnew + (size_t)(kvbase - PASTLEN) * (NKV * HDIM) + (size_t)kvh * HDIM;
                vst = NKV * HDIM;
            }
            #pragma unroll
            for (int it = 0; it < 8; it++) {
                int idx = tid + it * 256;
                int r = idx >> 5, d4 = (idx & 31) << 2;
                *(float4*)&KV[r * 128 + d4] = *(const float4*)(Vg + (size_t)r * vst + d4);
            }
        }
        __syncthreads();

        #pragma unroll 2
        for (int kk = 0; kk < 64; kk++) {
            ulonglong2 v01 = *(const ulonglong2*)&KV[kk * 128 + oc];
            ulonglong2 v23 = *(const ulonglong2*)&KV[kk * 128 + oc + 4];
            #pragma unroll
            for (int i = 0; i < 4; i++) {
                ull pd = dup2(Ps[(sr + i) * 64 + kk]);
                fma2(Oa[i][0], pd, v01.x);
                fma2(Oa[i][1], pd, v01.y);
                fma2(Oa[i][2], pd, v23.x);
                fma2(Oa[i][3], pd, v23.y);
            }
        }
    }

    #pragma unroll
    for (int i = 0; i < 4; i++) {
        float inv = 1.0f / l_i[i];
        float o[8];
        #pragma unroll
        for (int j = 0; j < 4; j++) {
            float2 u = unpk(Oa[i][j]);
            o[2*j] = u.x * inv; o[2*j+1] = u.y * inv;
        }
        float* Op = Out + (size_t)(q0 + sr + i) * HID + (size_t)h * HDIM + oc;
        *(float4*)Op       = make_float4(o[0], o[1], o[2], o[3]);
        *(float4*)(Op + 4) = make_float4(o[4], o[5], o[6], o[7]);
    }
}

// ---------------------------------------------------------------------------
// Launch
// ---------------------------------------------------------------------------
extern "C" void kernel_launch(void* const* d_in, const int* in_sizes, int n_in,
                              void* d_out, int out_size)
{
    const float* hid = (const float*)d_in[0];
    const float* kc  = (const float*)d_in[1];
    const float* vc  = (const float*)d_in[2];
    const float* Wq  = (const float*)d_in[3];
    const float* bq  = (const float*)d_in[4];
    const float* Wk  = (const float*)d_in[5];
    const float* bk  = (const float*)d_in[6];
    const float* Wv  = (const float*)d_in[7];
    const float* bv  = (const float*)d_in[8];
    const float* Wo  = (const float*)d_in[9];
    const int*   pos = (const int*)d_in[10];
    float* out = (float*)d_out;

    float *gQ, *gK, *gV, *gA;
    cudaGetSymbolAddress((void**)&gQ, g_Q);
    cudaGetSymbolAddress((void**)&gK, g_K);
    cudaGetSymbolAddress((void**)&gV, g_V);
    cudaGetSymbolAddress((void**)&gA, g_A);
    __nv_bfloat16 *hHi, *hLo, *aHi, *aLo;
    __nv_bfloat16 *qHi, *qLo, *kHi, *kLo, *vHi, *vLo, *oHi, *oLo;
    cudaGetSymbolAddress((void**)&hHi, g_hid_hi);
    cudaGetSymbolAddress((void**)&hLo, g_hid_lo);
    cudaGetSymbolAddress((void**)&aHi, g_att_hi);
    cudaGetSymbolAddress((void**)&aLo, g_att_lo);
    cudaGetSymbolAddress((void**)&qHi, g_WqT_hi);
    cudaGetSymbolAddress((void**)&qLo, g_WqT_lo);
    cudaGetSymbolAddress((void**)&kHi, g_WkT_hi);
    cudaGetSymbolAddress((void**)&kLo, g_WkT_lo);
    cudaGetSymbolAddress((void**)&vHi, g_WvT_hi);
    cudaGetSymbolAddress((void**)&vLo, g_WvT_lo);
    cudaGetSymbolAddress((void**)&oHi, g_WoT_hi);
    cudaGetSymbolAddress((void**)&oLo, g_WoT_lo);

    cudaFuncSetAttribute(mm_kernel, cudaFuncAttributeMaxDynamicSharedMemorySize, MM_SMEM);
    const int flash_smem = FLASH_SMEM_FLOATS * (int)sizeof(float);
    cudaFuncSetAttribute(flash_kernel, cudaFuncAttributeMaxDynamicSharedMemorySize, flash_smem);

    // 1. operand preparation
    const int n4 = QLEN * HID / 4;
    split_kernel<<<(n4 + 255) / 256, 256>>>(hid, hHi, hLo, n4);
    dim3 tb(32, 8);
    transpose_split_kernel<<<dim3(HID/32, HID/32), tb>>>(Wq, HID, HID, qHi, qLo);
    transpose_split_kernel<<<dim3((NKV*HDIM)/32, HID/32), tb>>>(Wk, HID, NKV*HDIM, kHi, kLo);
    transpose_split_kernel<<<dim3((NKV*HDIM)/32, HID/32), tb>>>(Wv, HID, NKV*HDIM, vHi, vLo);
    transpose_split_kernel<<<dim3(HID/32, HID/32), tb>>>(Wo, HID, HID, oHi, oLo);

    // 2. projections (mma.sync bf16, split precision)
    mm_kernel<<<dim3(28, 8), 256, MM_SMEM>>>(hHi, hLo, qHi, qLo, bq, gQ, HID);
    mm_kernel<<<dim3(4, 8),  256, MM_SMEM>>>(hHi, hLo, kHi, kLo, bk, gK, NKV*HDIM);
    mm_kernel<<<dim3(4, 8),  256, MM_SMEM>>>(hHi, hLo, vHi, vLo, bv, gV, NKV*HDIM);

    // 3. RoPE
    rope_kernel<<<QLEN, 256>>>(gQ, pos, HID, NHEADS);
    rope_kernel<<<QLEN, 256>>>(gK, pos, NKV*HDIM, NKV);

    // 4. attention
    dim3 gf(16, 28);
    flash_kernel<<<gf, 256, flash_smem>>>(gQ, gK, gV, kc, vc, gA);

    // 5. output projection (mma.sync bf16, split precision)
    split_kernel<<<(n4 + 255) / 256, 256>>>(gA, aHi, aLo, n4);
    mm_kernel<<<dim3(28, 8), 256, MM_SMEM>>>(aHi, aLo, oHi, oLo, nullptr, out, HID);
}

// round 6
// speedup vs baseline: 3.3300x; 2.9540x over previous
#include <cuda_runtime.h>
#include <cuda_bf16.h>
#include <cstdint>
#include <math.h>

// ---------------------------------------------------------------------------
// Problem constants
// ---------------------------------------------------------------------------
#define QLEN     1024
#define HID      3584
#define NHEADS   28
#define NKV      4
#define HDIM     128
#define PASTLEN  3072
#define KVTOT    4096
#define NREP     7

typedef unsigned long long ull;

// ---------------------------------------------------------------------------
// Scratch (device globals)
// ---------------------------------------------------------------------------
__device__ float g_Q[QLEN * HID];
__device__ float g_K[QLEN * (NKV*HDIM)];
__device__ float g_V[QLEN * (NKV*HDIM)];
__device__ float g_A[QLEN * HID];

__device__ __nv_bfloat16 g_hid_hi[QLEN * HID];
__device__ __nv_bfloat16 g_hid_lo[QLEN * HID];
__device__ __nv_bfloat16 g_att_hi[QLEN * HID];
__device__ __nv_bfloat16 g_att_lo[QLEN * HID];
__device__ __nv_bfloat16 g_WqT_hi[HID * HID];
__device__ __nv_bfloat16 g_WqT_lo[HID * HID];
__device__ __nv_bfloat16 g_WkT_hi[(NKV*HDIM) * HID];
__device__ __nv_bfloat16 g_WkT_lo[(NKV*HDIM) * HID];
__device__ __nv_bfloat16 g_WvT_hi[(NKV*HDIM) * HID];
__device__ __nv_bfloat16 g_WvT_lo[(NKV*HDIM) * HID];
__device__ __nv_bfloat16 g_WoT_hi[HID * HID];
__device__ __nv_bfloat16 g_WoT_lo[HID * HID];

// attention operands (split bf16)
__device__ __nv_bfloat16 g_Qb_hi[QLEN * HID];
__device__ __nv_bfloat16 g_Qb_lo[QLEN * HID];
__device__ __nv_bfloat16 g_Kb_hi[NKV * KVTOT * HDIM];
__device__ __nv_bfloat16 g_Kb_lo[NKV * KVTOT * HDIM];
__device__ __nv_bfloat16 g_Vb_hi[NKV * KVTOT * HDIM];
__device__ __nv_bfloat16 g_Vb_lo[NKV * KVTOT * HDIM];

// ---------------------------------------------------------------------------
// Helpers (plain-sm_103-legal: cp.async + ldmatrix + mma.sync only)
// ---------------------------------------------------------------------------
__device__ __forceinline__ uint32_t smem_to_u32(const void* p) {
    uint32_t a;
    asm("{ .reg .u64 t; cvta.to.shared.u64 t, %1; cvt.u32.u64 %0, t; }" : "=r"(a) : "l"(p));
    return a;
}
#define SMEM_SWIZZLE_128B(b) ((b) ^ (((b) >> 3) & 0x70))

__device__ __forceinline__ void cp_async16(uint32_t dst, const void* src) {
    asm volatile("cp.async.cg.shared.global [%0], [%1], 16;" :: "r"(dst), "l"(src) : "memory");
}
__device__ __forceinline__ void cp_commit() {
    asm volatile("cp.async.commit_group;" ::: "memory");
}
template <int N> __device__ __forceinline__ void cp_wait() {
    asm volatile("cp.async.wait_group %0;" :: "n"(N) : "memory");
}

__device__ __forceinline__ void ldm_x4(uint32_t* r, uint32_t addr) {
    asm volatile("ldmatrix.sync.aligned.m8n8.x4.shared.b16 {%0,%1,%2,%3}, [%4];"
                 : "=r"(r[0]), "=r"(r[1]), "=r"(r[2]), "=r"(r[3]) : "r"(addr));
}
__device__ __forceinline__ void ldm_x4t(uint32_t* r, uint32_t addr) {
    asm volatile("ldmatrix.sync.aligned.m8n8.x4.trans.shared.b16 {%0,%1,%2,%3}, [%4];"
                 : "=r"(r[0]), "=r"(r[1]), "=r"(r[2]), "=r"(r[3]) : "r"(addr));
}
__device__ __forceinline__ void mma_bf16(float* c, const uint32_t* a, const uint32_t* b) {
    asm volatile("mma.sync.aligned.m16n8k16.row.col.f32.bf16.bf16.f32 "
                 "{%0,%1,%2,%3}, {%4,%5,%6,%7}, {%8,%9}, {%0,%1,%2,%3};"
                 : "+f"(c[0]), "+f"(c[1]), "+f"(c[2]), "+f"(c[3])
                 : "r"(a[0]), "r"(a[1]), "r"(a[2]), "r"(a[3]), "r"(b[0]), "r"(b[1]));
}
__device__ __forceinline__ float fexp2(float x) {
    float y; asm("ex2.approx.ftz.f32 %0, %1;" : "=f"(y) : "f"(x)); return y;
}
__device__ __forceinline__ uint32_t packbf(__nv_bfloat16 a, __nv_bfloat16 b) {
    __nv_bfloat162 t(a, b);     // a -> low half (element k), b -> high (k+1)
    return *(uint32_t*)&t;
}

// ---------------------------------------------------------------------------
// f32 -> split bf16 (hi + lo)
// ---------------------------------------------------------------------------
__global__ void split_kernel(const float* __restrict__ X,
                             __nv_bfloat16* __restrict__ hi,
                             __nv_bfloat16* __restrict__ lo, int n4)
{
    int i = blockIdx.x * blockDim.x + threadIdx.x;
    if (i >= n4) return;
    float4 x = ((const float4*)X)[i];
    float v[4] = { x.x, x.y, x.z, x.w };
    __nv_bfloat16 h[4], l[4];
    #pragma unroll
    for (int j = 0; j < 4; j++) {
        h[j] = __float2bfloat16(v[j]);
        l[j] = __float2bfloat16(v[j] - __bfloat162float(h[j]));
    }
    __nv_bfloat162* H = (__nv_bfloat162*)hi;
    __nv_bfloat162* L = (__nv_bfloat162*)lo;
    H[2*i]   = __nv_bfloat162(h[0], h[1]);
    H[2*i+1] = __nv_bfloat162(h[2], h[3]);
    L[2*i]   = __nv_bfloat162(l[0], l[1]);
    L[2*i+1] = __nv_bfloat162(l[2], l[3]);
}

// W [K][N] f32  ->  T_hi/T_lo [N][K] bf16
__global__ void transpose_split_kernel(const float* __restrict__ W, int K, int N,
                                       __nv_bfloat16* __restrict__ Thi,
                                       __nv_bfloat16* __restrict__ Tlo)
{
    __shared__ float t[32][33];
    int n0 = blockIdx.x * 32, k0 = blockIdx.y * 32;
    int tx = threadIdx.x, ty = threadIdx.y;
    #pragma unroll
    for (int r = 0; r < 4; r++)
        t[ty + r*8][tx] = W[(size_t)(k0 + ty + r*8) * N + n0 + tx];
    __syncthreads();
    #pragma unroll
    for (int r = 0; r < 4; r++) {
        int n = n0 + ty + r*8;
        float v = t[tx][ty + r*8];
        __nv_bfloat16 h = __float2bfloat16(v);
        __nv_bfloat16 l = __float2bfloat16(v - __bfloat162float(h));
        Thi[(size_t)n * K + k0 + tx] = h;
        Tlo[(size_t)n * K + k0 + tx] = l;
    }
}

// Build contiguous split-bf16 KV: out[kvh][4096][128] from cache (f32, [kvh][3072][128])
// and new rows (f32, [1024][4*128]).
__global__ void pack_kv_kernel(const float* __restrict__ cache,
                               const float* __restrict__ newb,
                               __nv_bfloat16* __restrict__ hi,
                               __nv_bfloat16* __restrict__ lo)
{
    int i = blockIdx.x * blockDim.x + threadIdx.x;
    const int total = NKV * KVTOT * (HDIM / 4);
    if (i >= total) return;
    int kvh = i / (KVTOT * 32);
    int rem = i % (KVTOT * 32);
    int pos = rem >> 5;
    int d4  = (rem & 31) * 4;
    const float* src = (pos < PASTLEN)
        ? cache + ((size_t)(kvh * PASTLEN + pos) * HDIM + d4)
        : newb + ((size_t)(pos - PASTLEN) * (NKV * HDIM) + kvh * HDIM + d4);
    float4 v = *(const float4*)src;
    float a[4] = { v.x, v.y, v.z, v.w };
    __nv_bfloat16 h[4], l[4];
    #pragma unroll
    for (int j = 0; j < 4; j++) {
        h[j] = __float2bfloat16(a[j]);
        l[j] = __float2bfloat16(a[j] - __bfloat162float(h[j]));
    }
    size_t o = ((size_t)(kvh * KVTOT + pos) * HDIM + d4) >> 1;
    ((__nv_bfloat162*)hi)[o]     = __nv_bfloat162(h[0], h[1]);
    ((__nv_bfloat162*)hi)[o + 1] = __nv_bfloat162(h[2], h[3]);
    ((__nv_bfloat162*)lo)[o]     = __nv_bfloat162(l[0], l[1]);
    ((__nv_bfloat162*)lo)[o + 1] = __nv_bfloat162(l[2], l[3]);
}

// ---------------------------------------------------------------------------
// mma.sync split-precision GEMM (unchanged from passing R5 kernel)
// ---------------------------------------------------------------------------
#define MM_STAGES      4
#define MM_STAGE_BYTES 32768
#define MM_SMEM        (1024 + MM_STAGES * MM_STAGE_BYTES)
#define MM_NST         168

__global__ __launch_bounds__(256)
void mm_kernel(const __nv_bfloat16* __restrict__ Ahi, const __nv_bfloat16* __restrict__ Alo,
               const __nv_bfloat16* __restrict__ Bhi, const __nv_bfloat16* __restrict__ Blo,
               const float* __restrict__ bias, float* __restrict__ C, int ldc)
{
    extern __shared__ char smem[];
    const uint32_t sb   = smem_to_u32(smem);
    const uint32_t DATA = (sb + 1023u) & ~1023u;
    const int tid = threadIdx.x, wid = tid >> 5, lane = tid & 31;
    const int n0 = blockIdx.x * 128, m0 = blockIdx.y * 128;
    const int wm = (wid & 1) * 64;
    const int wn = (wid >> 1) * 32;

    uint32_t offs[4]; int rr[4], cc[4];
    #pragma unroll
    for (int i = 0; i < 4; i++) {
        int c = tid + i * 256;
        rr[i] = c >> 3;
        cc[i] = (c & 7) * 8;
        offs[i] = SMEM_SWIZZLE_128B((uint32_t)(rr[i] * 128 + (c & 7) * 16));
    }

    auto load_stage = [&](int g) {
        int seg = g / 56, kk = (g % 56) * 64;
        const __nv_bfloat16* A = (seg == 2) ? Alo : Ahi;
        const __nv_bfloat16* B = (seg == 1) ? Blo : Bhi;
        uint32_t ab = DATA + (uint32_t)(g & 3) * MM_STAGE_BYTES;
        uint32_t bb = ab + 16384;
        #pragma unroll
        for (int i = 0; i < 4; i++) {
            cp_async16(ab + offs[i], A + (size_t)(m0 + rr[i]) * HID + kk + cc[i]);
            cp_async16(bb + offs[i], B + (size_t)(n0 + rr[i]) * HID + kk + cc[i]);
        }
        cp_commit();
    };

    float acc[4][4][4];
    #pragma unroll
    for (int a = 0; a < 4; a++)
        #pragma unroll
        for (int b = 0; b < 4; b++)
            #pragma unroll
            for (int c = 0; c < 4; c++) acc[a][b][c] = 0.0f;

    const int a_row = wm + (lane & 15);
    const int a_kb  = (lane >> 4) * 16;
    const int b_row = wn + ((lane >> 4) & 1) * 8 + (lane & 7);
    const int b_kb  = ((lane >> 3) & 1) * 16;

    load_stage(0); load_stage(1); load_stage(2);

    for (int g = 0; g < MM_NST; g++) {
        int spre = g + 3;
        if (spre < MM_NST) load_stage(spre);
        int committed = (spre < MM_NST) ? (spre + 1) : MM_NST;
        int nout = committed - (g + 1);
        if      (nout >= 3) cp_wait<3>();
        else if (nout == 2) cp_wait<2>();
        else if (nout == 1) cp_wait<1>();
        else                cp_wait<0>();
        __syncthreads();

        uint32_t ab = DATA + (uint32_t)(g & 3) * MM_STAGE_BYTES;
        uint32_t bb = ab + 16384;

        #pragma unroll
        for (int ks = 0; ks < 4; ks++) {
            uint32_t aF[4][4];
            #pragma unroll
            for (int mi = 0; mi < 4; mi++) {
                uint32_t byte = (uint32_t)((a_row + mi * 16) * 128 + ks * 32 + a_kb);
                ldm_x4(aF[mi], ab + SMEM_SWIZZLE_128B(byte));
            }
            uint32_t bF[4][2];
            #pragma unroll
            for (int nb2 = 0; nb2 < 2; nb2++) {
                uint32_t byte = (uint32_t)((b_row + nb2 * 16) * 128 + ks * 32 + b_kb);
                uint32_t r[4];
                ldm_x4(r, bb + SMEM_SWIZZLE_128B(byte));
                bF[nb2*2+0][0] = r[0]; bF[nb2*2+0][1] = r[1];
                bF[nb2*2+1][0] = r[2]; bF[nb2*2+1][1] = r[3];
            }
            #pragma unroll
            for (int mi = 0; mi < 4; mi++)
                #pragma unroll
                for (int ni = 0; ni < 4; ni++)
                    mma_bf16(acc[mi][ni], aF[mi], bF[ni]);
        }
        __syncthreads();
    }

    const int group = lane >> 2, tig = lane & 3;
    #pragma unroll
    for (int mi = 0; mi < 4; mi++) {
        #pragma unroll
        for (int ni = 0; ni < 4; ni++) {
            int r0 = m0 + wm + mi * 16 + group;
            int c0 = n0 + wn + ni * 8 + tig * 2;
            float b0 = 0.f, b1 = 0.f;
            if (bias) { b0 = bias[c0]; b1 = bias[c0 + 1]; }
            float2 v0 = make_float2(acc[mi][ni][0] + b0, acc[mi][ni][1] + b1);
            float2 v1 = make_float2(acc[mi][ni][2] + b0, acc[mi][ni][3] + b1);
            *(float2*)(C + (size_t)r0 * ldc + c0)       = v0;
            *(float2*)(C + (size_t)(r0 + 8) * ldc + c0) = v1;
        }
    }
}

// ---------------------------------------------------------------------------
// RoPE
// ---------------------------------------------------------------------------
__global__ void rope_kernel(float* __restrict__ X, const int* __restrict__ pos,
                            int stride, int nh)
{
    const int q = blockIdx.x;
    const float p = (float)pos[q];
    for (int t = threadIdx.x; t < nh * 64; t += blockDim.x) {
        int hh = t >> 6, i = t & 63;
        float e = (float)i * (1.0f / 64.0f);
        float invf = 1.0f / powf(1000000.0f, e);
        float ang = p * invf;
        float s, c;
        sincosf(ang, &s, &c);
        float* base = X + (size_t)q * stride + hh * HDIM;
        float x1 = base[i];
        float x2 = base[i + 64];
        base[i]      = x1 * c - x2 * s;
        base[i + 64] = x2 * c + x1 * s;
    }
}

// ---------------------------------------------------------------------------
// Tensorized flash attention (mma.sync bf16, split precision, FA2 style)
// grid (8 q-tiles of 128, 28 heads), 256 threads = 8 warps x 16 q-rows.
// smem: Q region 64KB (Qhi 32K + Qlo 32K, 2 panels of 128x128B each),
//       2 KV stages x 64KB (Khi,Klo,Vhi,Vlo each 16KB = 2 panels of 64x128B).
// ---------------------------------------------------------------------------
#define FL_SMEM (65536 * 3)

__global__ __launch_bounds__(256, 1)
void flash_mma_kernel(const __nv_bfloat16* __restrict__ Qhi,
                      const __nv_bfloat16* __restrict__ Qlo,
                      const __nv_bfloat16* __restrict__ Kbh,
                      const __nv_bfloat16* __restrict__ Kbl,
                      const __nv_bfloat16* __restrict__ Vbh,
                      const __nv_bfloat16* __restrict__ Vbl,
                      float* __restrict__ Out)
{
    extern __shared__ char smraw[];
    const uint32_t sb = smem_to_u32(smraw);
    const int tid = threadIdx.x, wid = tid >> 5, lane = tid & 31;
    const int qt = blockIdx.x, h = blockIdx.y;
    const int kvh = h / NREP;
    const int q0 = qt * 128;
    const int w16 = wid * 16;
    const int nt = 50 + 2 * qt;      // (PASTLEN + q0 + 128) / 64

    // ---- Q tile load (once): 2 comps x 2048 16B-chunks ----
    #pragma unroll
    for (int i = 0; i < 16; i++) {
        int cg = tid + i * 256;
        int comp = i >> 3;                   // 0 = hi, 1 = lo
        int c = cg & 2047;
        int row = c >> 4, d8 = (c & 15) * 8;
        uint32_t dst = sb + (uint32_t)comp * 32768 + (uint32_t)((c >> 3) & 1) * 16384
                     + SMEM_SWIZZLE_128B((uint32_t)(row * 128 + (c & 7) * 16));
        const __nv_bfloat16* src = (comp ? Qlo : Qhi);
        cp_async16(dst, src + (size_t)(q0 + row) * HID + h * HDIM + d8);
    }
    cp_commit();

    auto load_stage = [&](int t) {
        uint32_t base = sb + 65536u + (uint32_t)(t & 1) * 65536u;
        int kvbase = t * 64;
        #pragma unroll
        for (int i = 0; i < 16; i++) {
            int comp = i >> 2;               // 0 Khi, 1 Klo, 2 Vhi, 3 Vlo
            int c = (tid + i * 256) & 1023;
            int kv = c >> 4, d8 = (c & 15) * 8;
            uint32_t dst = base + (uint32_t)comp * 16384 + (uint32_t)((c >> 3) & 1) * 8192
                         + SMEM_SWIZZLE_128B((uint32_t)(kv * 128 + (c & 7) * 16));
            const __nv_bfloat16* src =
                (comp == 0) ? Kbh : (comp == 1) ? Kbl : (comp == 2) ? Vbh : Vbl;
            cp_async16(dst, src + ((size_t)(kvh * KVTOT + kvbase + kv) * HDIM + d8));
        }
        cp_commit();
    };

    load_stage(0);

    float Oacc[16][4];
    #pragma unroll
    for (int i = 0; i < 16; i++)
        #pragma unroll
        for (int j = 0; j < 4; j++) Oacc[i][j] = 0.0f;
    float m0 = -INFINITY, m1 = -INFINITY, l0 = 0.0f, l1 = 0.0f;

    const float SL = 0.08838834764831845f * 1.4426950408889634f;  // scale*log2(e)
    const int r0 = lane >> 2;

    for (int t = 0; t < nt; t++) {
        if (t + 1 < nt) { load_stage(t + 1); cp_wait<1>(); }
        else            { cp_wait<0>(); }
        __syncthreads();

        const uint32_t stage = sb + 65536u + (uint32_t)(t & 1) * 65536u;
        const int kvbase = t * 64;

        // ---- S = Q K^T (3-pass split) ----
        float S[8][4];
        #pragma unroll
        for (int i = 0; i < 8; i++)
            #pragma unroll
            for (int j = 0; j < 4; j++) S[i][j] = 0.0f;

        #pragma unroll
        for (int kc = 0; kc < 8; kc++) {
            uint32_t qh[4], ql[4];
            uint32_t qoff = (uint32_t)((w16 + (lane & 15)) * 128 + (kc & 3) * 32 + (lane >> 4) * 16);
            uint32_t qa = sb + (uint32_t)(kc >> 2) * 16384 + SMEM_SWIZZLE_128B(qoff);
            ldm_x4(qh, qa);
            ldm_x4(ql, qa + 32768);
            uint32_t kcol = (uint32_t)((kc & 3) * 32 + ((lane >> 3) & 1) * 16);
            #pragma unroll
            for (int np = 0; np < 4; np++) {
                uint32_t koff = (uint32_t)((np * 16 + ((lane >> 4) & 1) * 8 + (lane & 7)) * 128) + kcol;
                uint32_t ka = stage + (uint32_t)(kc >> 2) * 8192 + SMEM_SWIZZLE_128B(koff);
                uint32_t kh[4], kl[4];
                ldm_x4(kh, ka);
                ldm_x4(kl, ka + 16384);
                mma_bf16(S[2*np],   qh, kh);     mma_bf16(S[2*np],   ql, kh);
                mma_bf16(S[2*np],   qh, kl);
                mma_bf16(S[2*np+1], qh, kh + 2); mma_bf16(S[2*np+1], ql, kh + 2);
                mma_bf16(S[2*np+1], qh, kl + 2);
            }
        }

        // ---- causal mask (last two tiles only) ----
        if (t >= nt - 2) {
            const int lim0 = PASTLEN + q0 + w16 + r0;       // row r0
            const int lim1 = lim0 + 8;                       // row r0+8
            #pragma unroll
            for (int nc = 0; nc < 8; nc++) {
                int col = kvbase + nc * 8 + (lane & 3) * 2;
                if (col     > lim0) S[nc][0] = -1e30f;
                if (col + 1 > lim0) S[nc][1] = -1e30f;
                if (col     > lim1) S[nc][2] = -1e30f;
                if (col + 1 > lim1) S[nc][3] = -1e30f;
            }
        }

        // ---- online softmax ----
        float mx0 = -INFINITY, mx1 = -INFINITY;
        #pragma unroll
        for (int nc = 0; nc < 8; nc++) {
            mx0 = fmaxf(mx0, fmaxf(S[nc][0], S[nc][1]));
            mx1 = fmaxf(mx1, fmaxf(S[nc][2], S[nc][3]));
        }
        mx0 = fmaxf(mx0, __shfl_xor_sync(0xffffffffu, mx0, 1));
        mx0 = fmaxf(mx0, __shfl_xor_sync(0xffffffffu, mx0, 2));
        mx1 = fmaxf(mx1, __shfl_xor_sync(0xffffffffu, mx1, 1));
        mx1 = fmaxf(mx1, __shfl_xor_sync(0xffffffffu, mx1, 2));
        float mn0 = fmaxf(m0, mx0 * SL);
        float mn1 = fmaxf(m1, mx1 * SL);
        float cor0 = fexp2(m0 - mn0);
        float cor1 = fexp2(m1 - mn1);
        m0 = mn0; m1 = mn1;

        uint32_t pH[8][2], pL[8][2];
        float rs0 = 0.0f, rs1 = 0.0f;
        #pragma unroll
        for (int nc = 0; nc < 8; nc++) {
            float p0 = fexp2(S[nc][0] * SL - mn0);
            float p1 = fexp2(S[nc][1] * SL - mn0);
            float p2 = fexp2(S[nc][2] * SL - mn1);
            float p3 = fexp2(S[nc][3] * SL - mn1);
            rs0 += p0 + p1;  rs1 += p2 + p3;
            __nv_bfloat16 h0 = __float2bfloat16(p0), h1 = __float2bfloat16(p1);
            __nv_bfloat16 h2 = __float2bfloat16(p2), h3 = __float2bfloat16(p3);
            pH[nc][0] = packbf(h0, h1);
            pH[nc][1] = packbf(h2, h3);
            pL[nc][0] = packbf(__float2bfloat16(p0 - __bfloat162float(h0)),
                               __float2bfloat16(p1 - __bfloat162float(h1)));
            pL[nc][1] = packbf(__float2bfloat16(p2 - __bfloat162float(h2)),
                               __float2bfloat16(p3 - __bfloat162float(h3)));
        }
        rs0 += __shfl_xor_sync(0xffffffffu, rs0, 1);
        rs0 += __shfl_xor_sync(0xffffffffu, rs0, 2);
        rs1 += __shfl_xor_sync(0xffffffffu, rs1, 1);
        rs1 += __shfl_xor_sync(0xffffffffu, rs1, 2);
        l0 = l0 * cor0 + rs0;
        l1 = l1 * cor1 + rs1;

        #pragma unroll
        for (int nc = 0; nc < 16; nc++) {
            Oacc[nc][0] *= cor0; Oacc[nc][1] *= cor0;
            Oacc[nc][2] *= cor1; Oacc[nc][3] *= cor1;
        }

        // ---- O += P V (3-pass split), V via ldmatrix.trans ----
        #pragma unroll
        for (int kc = 0; kc < 4; kc++) {
            uint32_t aH[4] = { pH[2*kc][0], pH[2*kc][1], pH[2*kc+1][0], pH[2*kc+1][1] };
            uint32_t aL[4] = { pL[2*kc][0], pL[2*kc][1], pL[2*kc+1][0], pL[2*kc+1][1] };
            uint32_t vrow = (uint32_t)(kc * 16 + ((lane >> 3) & 1) * 8 + (lane & 7));
            #pragma unroll
            for (int dp = 0; dp < 8; dp++) {
                uint32_t voff = vrow * 128 + (uint32_t)((dp & 3) * 32 + ((lane >> 4) & 1) * 16);
                uint32_t va = stage + 32768u + (uint32_t)(dp >> 2) * 8192 + SMEM_SWIZZLE_128B(voff);
                uint32_t vh[4], vl[4];
                ldm_x4t(vh, va);
                ldm_x4t(vl, va + 16384);
                mma_bf16(Oacc[2*dp],   aH, vh);     mma_bf16(Oacc[2*dp],   aL, vh);
                mma_bf16(Oacc[2*dp],   aH, vl);
                mma_bf16(Oacc[2*dp+1], aH, vh + 2); mma_bf16(Oacc[2*dp+1], aL, vh + 2);
                mma_bf16(Oacc[2*dp+1], aH, vl + 2);
            }
        }
        __syncthreads();
    }

    // ---- epilogue ----
    float i0 = 1.0f / l0, i1 = 1.0f / l1;
    const int rowa = q0 + w16 + r0;
    #pragma unroll
    for (int nc = 0; nc < 16; nc++) {
        int col = h * HDIM + nc * 8 + (lane & 3) * 2;
        *(float2*)(Out + (size_t)rowa * HID + col) =
            make_float2(Oacc[nc][0] * i0, Oacc[nc][1] * i0);
        *(float2*)(Out + (size_t)(rowa + 8) * HID + col) =
            make_float2(Oacc[nc][2] * i1, Oacc[nc][3] * i1);
    }
}

// ---------------------------------------------------------------------------
// Launch
// ---------------------------------------------------------------------------
extern "C" void kernel_launch(void* const* d_in, const int* in_sizes, int n_in,
                              void* d_out, int out_size)
{
    const float* hid = (const float*)d_in[0];
    const float* kc  = (const float*)d_in[1];
    const float* vc  = (const float*)d_in[2];
    const float* Wq  = (const float*)d_in[3];
    const float* bq  = (const float*)d_in[4];
    const float* Wk  = (const float*)d_in[5];
    const float* bk  = (const float*)d_in[6];
    const float* Wv  = (const float*)d_in[7];
    const float* bv  = (const float*)d_in[8];
    const float* Wo  = (const float*)d_in[9];
    const int*   pos = (const int*)d_in[10];
    float* out = (float*)d_out;

    float *gQ, *gK, *gV, *gA;
    cudaGetSymbolAddress((void**)&gQ, g_Q);
    cudaGetSymbolAddress((void**)&gK, g_K);
    cudaGetSymbolAddress((void**)&gV, g_V);
    cudaGetSymbolAddress((void**)&gA, g_A);
    __nv_bfloat16 *hHi, *hLo, *aHi, *aLo;
    __nv_bfloat16 *qHi, *qLo, *kHi, *kLo, *vHi, *vLo, *oHi, *oLo;
    __nv_bfloat16 *QbH, *QbL, *KbH, *KbL, *VbH, *VbL;
    cudaGetSymbolAddress((void**)&hHi, g_hid_hi);
    cudaGetSymbolAddress((void**)&hLo, g_hid_lo);
    cudaGetSymbolAddress((void**)&aHi, g_att_hi);
    cudaGetSymbolAddress((void**)&aLo, g_att_lo);
    cudaGetSymbolAddress((void**)&qHi, g_WqT_hi);
    cudaGetSymbolAddress((void**)&qLo, g_WqT_lo);
    cudaGetSymbolAddress((void**)&kHi, g_WkT_hi);
    cudaGetSymbolAddress((void**)&kLo, g_WkT_lo);
    cudaGetSymbolAddress((void**)&vHi, g_WvT_hi);
    cudaGetSymbolAddress((void**)&vLo, g_WvT_lo);
    cudaGetSymbolAddress((void**)&oHi, g_WoT_hi);
    cudaGetSymbolAddress((void**)&oLo, g_WoT_lo);
    cudaGetSymbolAddress((void**)&QbH, g_Qb_hi);
    cudaGetSymbolAddress((void**)&QbL, g_Qb_lo);
    cudaGetSymbolAddress((void**)&KbH, g_Kb_hi);
    cudaGetSymbolAddress((void**)&KbL, g_Kb_lo);
    cudaGetSymbolAddress((void**)&VbH, g_Vb_hi);
    cudaGetSymbolAddress((void**)&VbL, g_Vb_lo);

    cudaFuncSetAttribute(mm_kernel, cudaFuncAttributeMaxDynamicSharedMemorySize, MM_SMEM);
    cudaFuncSetAttribute(flash_mma_kernel, cudaFuncAttributeMaxDynamicSharedMemorySize, FL_SMEM);

    // 1. operand preparation
    const int n4 = QLEN * HID / 4;
    split_kernel<<<(n4 + 255) / 256, 256>>>(hid, hHi, hLo, n4);
    dim3 tb(32, 8);
    transpose_split_kernel<<<dim3(HID/32, HID/32), tb>>>(Wq, HID, HID, qHi, qLo);
    transpose_split_kernel<<<dim3((NKV*HDIM)/32, HID/32), tb>>>(Wk, HID, NKV*HDIM, kHi, kLo);
    transpose_split_kernel<<<dim3((NKV*HDIM)/32, HID/32), tb>>>(Wv, HID, NKV*HDIM, vHi, vLo);
    transpose_split_kernel<<<dim3(HID/32, HID/32), tb>>>(Wo, HID, HID, oHi, oLo);

    // 2. projections
    mm_kernel<<<dim3(28, 8), 256, MM_SMEM>>>(hHi, hLo, qHi, qLo, bq, gQ, HID);
    mm_kernel<<<dim3(4, 8),  256, MM_SMEM>>>(hHi, hLo, kHi, kLo, bk, gK, NKV*HDIM);
    mm_kernel<<<dim3(4, 8),  256, MM_SMEM>>>(hHi, hLo, vHi, vLo, bv, gV, NKV*HDIM);

    // 3. RoPE
    rope_kernel<<<QLEN, 256>>>(gQ, pos, HID, NHEADS);
    rope_kernel<<<QLEN, 256>>>(gK, pos, NKV*HDIM, NKV);

    // 4. pack attention operands (split bf16)
    split_kernel<<<(n4 + 255) / 256, 256>>>(gQ, QbH, QbL, n4);
    const int pk = NKV * KVTOT * (HDIM / 4);
    pack_kv_kernel<<<(pk + 255) / 256, 256>>>(kc, gK, KbH, KbL);
    pack_kv_kernel<<<(pk + 255) / 256, 256>>>(vc, gV, VbH, VbL);

    // 5. attention (tensorized)
    flash_mma_kernel<<<dim3(8, 28), 256, FL_SMEM>>>(QbH, QbL, KbH, KbL, VbH, VbL, gA);

    // 6. output projection
    split_kernel<<<(n4 + 255) / 256, 256>>>(gA, aHi, aLo, n4);
    mm_kernel<<<dim3(28, 8), 256, MM_SMEM>>>(aHi, aLo, oHi, oLo, nullptr, out, HID);
}

// round 7
// speedup vs baseline: 4.5307x; 1.3606x over previous
#include <cuda_runtime.h>
#include <cuda_bf16.h>
#include <cstdint>
#include <math.h>

// ---------------------------------------------------------------------------
// Problem constants
// ---------------------------------------------------------------------------
#define QLEN     1024
#define HID      3584
#define NHEADS   28
#define NKV      4
#define HDIM     128
#define PASTLEN  3072
#define KVTOT    4096
#define NREP     7

typedef unsigned long long ull;

// ---------------------------------------------------------------------------
// Scratch (device globals)
// ---------------------------------------------------------------------------
__device__ float g_Q[QLEN * HID];
__device__ float g_K[QLEN * (NKV*HDIM)];
__device__ float g_V[QLEN * (NKV*HDIM)];
__device__ float g_A[QLEN * HID];

__device__ __nv_bfloat16 g_hid_hi[QLEN * HID];
__device__ __nv_bfloat16 g_hid_lo[QLEN * HID];
__device__ __nv_bfloat16 g_att_hi[QLEN * HID];
__device__ __nv_bfloat16 g_att_lo[QLEN * HID];
__device__ __nv_bfloat16 g_WqT_hi[HID * HID];
__device__ __nv_bfloat16 g_WqT_lo[HID * HID];
__device__ __nv_bfloat16 g_WkT_hi[(NKV*HDIM) * HID];
__device__ __nv_bfloat16 g_WkT_lo[(NKV*HDIM) * HID];
__device__ __nv_bfloat16 g_WvT_hi[(NKV*HDIM) * HID];
__device__ __nv_bfloat16 g_WvT_lo[(NKV*HDIM) * HID];
__device__ __nv_bfloat16 g_WoT_hi[HID * HID];
__device__ __nv_bfloat16 g_WoT_lo[HID * HID];

// attention operands (split bf16)
__device__ __nv_bfloat16 g_Qb_hi[QLEN * HID];
__device__ __nv_bfloat16 g_Qb_lo[QLEN * HID];
__device__ __nv_bfloat16 g_Kb_hi[NKV * KVTOT * HDIM];
__device__ __nv_bfloat16 g_Kb_lo[NKV * KVTOT * HDIM];
__device__ __nv_bfloat16 g_Vb_hi[NKV * KVTOT * HDIM];
__device__ __nv_bfloat16 g_Vb_lo[NKV * KVTOT * HDIM];

// flash split-KV partials
__device__ float g_Op[2 * NHEADS * QLEN * HDIM];     // unnormalized O
__device__ float g_Ml[2 * NHEADS * QLEN * 2];        // (m, l) per row

// ---------------------------------------------------------------------------
// Helpers (plain-sm_103-legal: cp.async + ldmatrix + mma.sync only)
// ---------------------------------------------------------------------------
__device__ __forceinline__ uint32_t smem_to_u32(const void* p) {
    uint32_t a;
    asm("{ .reg .u64 t; cvta.to.shared.u64 t, %1; cvt.u32.u64 %0, t; }" : "=r"(a) : "l"(p));
    return a;
}
#define SMEM_SWIZZLE_128B(b) ((b) ^ (((b) >> 3) & 0x70))

__device__ __forceinline__ void cp_async16(uint32_t dst, const void* src) {
    asm volatile("cp.async.cg.shared.global [%0], [%1], 16;" :: "r"(dst), "l"(src) : "memory");
}
__device__ __forceinline__ void cp_commit() {
    asm volatile("cp.async.commit_group;" ::: "memory");
}
template <int N> __device__ __forceinline__ void cp_wait() {
    asm volatile("cp.async.wait_group %0;" :: "n"(N) : "memory");
}

__device__ __forceinline__ void ldm_x4(uint32_t* r, uint32_t addr) {
    asm volatile("ldmatrix.sync.aligned.m8n8.x4.shared.b16 {%0,%1,%2,%3}, [%4];"
                 : "=r"(r[0]), "=r"(r[1]), "=r"(r[2]), "=r"(r[3]) : "r"(addr));
}
__device__ __forceinline__ void ldm_x4t(uint32_t* r, uint32_t addr) {
    asm volatile("ldmatrix.sync.aligned.m8n8.x4.trans.shared.b16 {%0,%1,%2,%3}, [%4];"
                 : "=r"(r[0]), "=r"(r[1]), "=r"(r[2]), "=r"(r[3]) : "r"(addr));
}
__device__ __forceinline__ void mma_bf16(float* c, const uint32_t* a, const uint32_t* b) {
    asm volatile("mma.sync.aligned.m16n8k16.row.col.f32.bf16.bf16.f32 "
                 "{%0,%1,%2,%3}, {%4,%5,%6,%7}, {%8,%9}, {%0,%1,%2,%3};"
                 : "+f"(c[0]), "+f"(c[1]), "+f"(c[2]), "+f"(c[3])
                 : "r"(a[0]), "r"(a[1]), "r"(a[2]), "r"(a[3]), "r"(b[0]), "r"(b[1]));
}
__device__ __forceinline__ float fexp2(float x) {
    float y; asm("ex2.approx.ftz.f32 %0, %1;" : "=f"(y) : "f"(x)); return y;
}
__device__ __forceinline__ uint32_t packbf(__nv_bfloat16 a, __nv_bfloat16 b) {
    __nv_bfloat162 t(a, b);
    return *(uint32_t*)&t;
}

// ---------------------------------------------------------------------------
// f32 -> split bf16 (hi + lo)
// ---------------------------------------------------------------------------
__global__ void split_kernel(const float* __restrict__ X,
                             __nv_bfloat16* __restrict__ hi,
                             __nv_bfloat16* __restrict__ lo, int n4)
{
    int i = blockIdx.x * blockDim.x + threadIdx.x;
    if (i >= n4) return;
    float4 x = ((const float4*)X)[i];
    float v[4] = { x.x, x.y, x.z, x.w };
    __nv_bfloat16 h[4], l[4];
    #pragma unroll
    for (int j = 0; j < 4; j++) {
        h[j] = __float2bfloat16(v[j]);
        l[j] = __float2bfloat16(v[j] - __bfloat162float(h[j]));
    }
    __nv_bfloat162* H = (__nv_bfloat162*)hi;
    __nv_bfloat162* L = (__nv_bfloat162*)lo;
    H[2*i]   = __nv_bfloat162(h[0], h[1]);
    H[2*i+1] = __nv_bfloat162(h[2], h[3]);
    L[2*i]   = __nv_bfloat162(l[0], l[1]);
    L[2*i+1] = __nv_bfloat162(l[2], l[3]);
}

// W [K][N] f32  ->  T_hi/T_lo [N][K] bf16
__global__ void transpose_split_kernel(const float* __restrict__ W, int K, int N,
                                       __nv_bfloat16* __restrict__ Thi,
                                       __nv_bfloat16* __restrict__ Tlo)
{
    __shared__ float t[32][33];
    int n0 = blockIdx.x * 32, k0 = blockIdx.y * 32;
    int tx = threadIdx.x, ty = threadIdx.y;
    #pragma unroll
    for (int r = 0; r < 4; r++)
        t[ty + r*8][tx] = W[(size_t)(k0 + ty + r*8) * N + n0 + tx];
    __syncthreads();
    #pragma unroll
    for (int r = 0; r < 4; r++) {
        int n = n0 + ty + r*8;
        float v = t[tx][ty + r*8];
        __nv_bfloat16 h = __float2bfloat16(v);
        __nv_bfloat16 l = __float2bfloat16(v - __bfloat162float(h));
        Thi[(size_t)n * K + k0 + tx] = h;
        Tlo[(size_t)n * K + k0 + tx] = l;
    }
}

// Fused pack for K and V (blockIdx.y selects operand)
__global__ void pack_kv_kernel(const float* __restrict__ kcache,
                               const float* __restrict__ knew,
                               const float* __restrict__ vcache,
                               const float* __restrict__ vnew,
                               __nv_bfloat16* __restrict__ khi,
                               __nv_bfloat16* __restrict__ klo,
                               __nv_bfloat16* __restrict__ vhi,
                               __nv_bfloat16* __restrict__ vlo)
{
    int i = blockIdx.x * blockDim.x + threadIdx.x;
    const int total = NKV * KVTOT * (HDIM / 4);
    if (i >= total) return;
    const float* cache; const float* newb;
    __nv_bfloat16 *hi, *lo;
    if (blockIdx.y == 0) { cache = kcache; newb = knew; hi = khi; lo = klo; }
    else                 { cache = vcache; newb = vnew; hi = vhi; lo = vlo; }
    int kvh = i / (KVTOT * 32);
    int rem = i % (KVTOT * 32);
    int pos = rem >> 5;
    int d4  = (rem & 31) * 4;
    const float* src = (pos < PASTLEN)
        ? cache + ((size_t)(kvh * PASTLEN + pos) * HDIM + d4)
        : newb + ((size_t)(pos - PASTLEN) * (NKV * HDIM) + kvh * HDIM + d4);
    float4 v = *(const float4*)src;
    float a[4] = { v.x, v.y, v.z, v.w };
    __nv_bfloat16 h[4], l[4];
    #pragma unroll
    for (int j = 0; j < 4; j++) {
        h[j] = __float2bfloat16(a[j]);
        l[j] = __float2bfloat16(a[j] - __bfloat162float(h[j]));
    }
    size_t o = ((size_t)(kvh * KVTOT + pos) * HDIM + d4) >> 1;
    ((__nv_bfloat162*)hi)[o]     = __nv_bfloat162(h[0], h[1]);
    ((__nv_bfloat162*)hi)[o + 1] = __nv_bfloat162(h[2], h[3]);
    ((__nv_bfloat162*)lo)[o]     = __nv_bfloat162(l[0], l[1]);
    ((__nv_bfloat162*)lo)[o + 1] = __nv_bfloat162(l[2], l[3]);
}

// ---------------------------------------------------------------------------
// mma.sync split-precision GEMM core (device function)
// CTA tile 128x128, 8 warps of 64x32. K=3584 in 56 stages of 64, x3 segments.
// ---------------------------------------------------------------------------
#define MM_STAGES      4
#define MM_STAGE_BYTES 32768
#define MM_SMEM        (1024 + MM_STAGES * MM_STAGE_BYTES)
#define MM_NST         168

__device__ __forceinline__ void mm_tile(
    const __nv_bfloat16* __restrict__ Ahi, const __nv_bfloat16* __restrict__ Alo,
    const __nv_bfloat16* __restrict__ Bhi, const __nv_bfloat16* __restrict__ Blo,
    const float* __restrict__ bias, float* __restrict__ C, int ldc,
    int m0, int n0, char* smem)
{
    const uint32_t sb   = smem_to_u32(smem);
    const uint32_t DATA = (sb + 1023u) & ~1023u;
    const int tid = threadIdx.x, wid = tid >> 5, lane = tid & 31;
    const int wm = (wid & 1) * 64;
    const int wn = (wid >> 1) * 32;

    uint32_t offs[4]; int rr[4], cc[4];
    #pragma unroll
    for (int i = 0; i < 4; i++) {
        int c = tid + i * 256;
        rr[i] = c >> 3;
        cc[i] = (c & 7) * 8;
        offs[i] = SMEM_SWIZZLE_128B((uint32_t)(rr[i] * 128 + (c & 7) * 16));
    }

    auto load_stage = [&](int g) {
        int seg = g / 56, kk = (g % 56) * 64;
        const __nv_bfloat16* A = (seg == 2) ? Alo : Ahi;
        const __nv_bfloat16* B = (seg == 1) ? Blo : Bhi;
        uint32_t ab = DATA + (uint32_t)(g & 3) * MM_STAGE_BYTES;
        uint32_t bb = ab + 16384;
        #pragma unroll
        for (int i = 0; i < 4; i++) {
            cp_async16(ab + offs[i], A + (size_t)(m0 + rr[i]) * HID + kk + cc[i]);
            cp_async16(bb + offs[i], B + (size_t)(n0 + rr[i]) * HID + kk + cc[i]);
        }
        cp_commit();
    };

    float acc[4][4][4];
    #pragma unroll
    for (int a = 0; a < 4; a++)
        #pragma unroll
        for (int b = 0; b < 4; b++)
            #pragma unroll
            for (int c = 0; c < 4; c++) acc[a][b][c] = 0.0f;

    const int a_row = wm + (lane & 15);
    const int a_kb  = (lane >> 4) * 16;
    const int b_row = wn + ((lane >> 4) & 1) * 8 + (lane & 7);
    const int b_kb  = ((lane >> 3) & 1) * 16;

    load_stage(0); load_stage(1); load_stage(2);

    for (int g = 0; g < MM_NST; g++) {
        int spre = g + 3;
        if (spre < MM_NST) load_stage(spre);
        int committed = (spre < MM_NST) ? (spre + 1) : MM_NST;
        int nout = committed - (g + 1);
        if      (nout >= 3) cp_wait<3>();
        else if (nout == 2) cp_wait<2>();
        else if (nout == 1) cp_wait<1>();
        else                cp_wait<0>();
        __syncthreads();

        uint32_t ab = DATA + (uint32_t)(g & 3) * MM_STAGE_BYTES;
        uint32_t bb = ab + 16384;

        #pragma unroll
        for (int ks = 0; ks < 4; ks++) {
            uint32_t aF[4][4];
            #pragma unroll
            for (int mi = 0; mi < 4; mi++) {
                uint32_t byte = (uint32_t)((a_row + mi * 16) * 128 + ks * 32 + a_kb);
                ldm_x4(aF[mi], ab + SMEM_SWIZZLE_128B(byte));
            }
            uint32_t bF[4][2];
            #pragma unroll
            for (int nb2 = 0; nb2 < 2; nb2++) {
                uint32_t byte = (uint32_t)((b_row + nb2 * 16) * 128 + ks * 32 + b_kb);
                uint32_t r[4];
                ldm_x4(r, bb + SMEM_SWIZZLE_128B(byte));
                bF[nb2*2+0][0] = r[0]; bF[nb2*2+0][1] = r[1];
                bF[nb2*2+1][0] = r[2]; bF[nb2*2+1][1] = r[3];
            }
            #pragma unroll
            for (int mi = 0; mi < 4; mi++)
                #pragma unroll
                for (int ni = 0; ni < 4; ni++)
                    mma_bf16(acc[mi][ni], aF[mi], bF[ni]);
        }
        __syncthreads();
    }

    const int group = lane >> 2, tig = lane & 3;
    #pragma unroll
    for (int mi = 0; mi < 4; mi++) {
        #pragma unroll
        for (int ni = 0; ni < 4; ni++) {
            int r0 = m0 + wm + mi * 16 + group;
            int c0 = n0 + wn + ni * 8 + tig * 2;
            float b0 = 0.f, b1 = 0.f;
            if (bias) { b0 = bias[c0]; b1 = bias[c0 + 1]; }
            float2 v0 = make_float2(acc[mi][ni][0] + b0, acc[mi][ni][1] + b1);
            float2 v1 = make_float2(acc[mi][ni][2] + b0, acc[mi][ni][3] + b1);
            *(float2*)(C + (size_t)r0 * ldc + c0)       = v0;
            *(float2*)(C + (size_t)(r0 + 8) * ldc + c0) = v1;
        }
    }
}

// Fused QKV projection: grid (36, 8)
__global__ __launch_bounds__(256)
void qkv_mm_kernel(const __nv_bfloat16* __restrict__ Ahi, const __nv_bfloat16* __restrict__ Alo,
                   const __nv_bfloat16* __restrict__ qHi, const __nv_bfloat16* __restrict__ qLo,
                   const __nv_bfloat16* __restrict__ kHi, const __nv_bfloat16* __restrict__ kLo,
                   const __nv_bfloat16* __restrict__ vHi, const __nv_bfloat16* __restrict__ vLo,
                   const float* __restrict__ bq, const float* __restrict__ bk,
                   const float* __restrict__ bv,
                   float* __restrict__ gQ, float* __restrict__ gK, float* __restrict__ gV)
{
    extern __shared__ char smem[];
    const int bx = blockIdx.x, m0 = blockIdx.y * 128;
    if (bx < 28)
        mm_tile(Ahi, Alo, qHi, qLo, bq, gQ, HID, m0, bx * 128, smem);
    else if (bx < 32)
        mm_tile(Ahi, Alo, kHi, kLo, bk, gK, NKV*HDIM, m0, (bx - 28) * 128, smem);
    else
        mm_tile(Ahi, Alo, vHi, vLo, bv, gV, NKV*HDIM, m0, (bx - 32) * 128, smem);
}

// Output projection: grid (28, 8)
__global__ __launch_bounds__(256)
void mm_kernel(const __nv_bfloat16* __restrict__ Ahi, const __nv_bfloat16* __restrict__ Alo,
               const __nv_bfloat16* __restrict__ Bhi, const __nv_bfloat16* __restrict__ Blo,
               float* __restrict__ C)
{
    extern __shared__ char smem[];
    mm_tile(Ahi, Alo, Bhi, Blo, nullptr, C, HID, blockIdx.y * 128, blockIdx.x * 128, smem);
}

// ---------------------------------------------------------------------------
// RoPE fused (y=0: Q, y=1: K)
// ---------------------------------------------------------------------------
__global__ void rope_kernel(float* __restrict__ XQ, float* __restrict__ XK,
                            const int* __restrict__ pos)
{
    const int q = blockIdx.x;
    const float p = (float)pos[q];
    float* X = blockIdx.y ? XK : XQ;
    const int stride = blockIdx.y ? (NKV * HDIM) : HID;
    const int nh = blockIdx.y ? NKV : NHEADS;
    for (int t = threadIdx.x; t < nh * 64; t += blockDim.x) {
        int hh = t >> 6, i = t & 63;
        float e = (float)i * (1.0f / 64.0f);
        float invf = 1.0f / powf(1000000.0f, e);
        float ang = p * invf;
        float s, c;
        sincosf(ang, &s, &c);
        float* base = X + (size_t)q * stride + hh * HDIM;
        float x1 = base[i];
        float x2 = base[i + 64];
        base[i]      = x1 * c - x2 * s;
        base[i + 64] = x2 * c + x1 * s;
    }
}

// ---------------------------------------------------------------------------
// Tensorized flash attention, 2-way KV split.
// grid (8 q-tiles, 28 heads, 2 kv-splits), 256 threads = 8 warps x 16 q-rows.
// Writes unnormalized O partials + (m, l) per row; combine_kernel merges.
// ---------------------------------------------------------------------------
#define FL_SMEM (65536 * 3)

__global__ __launch_bounds__(256, 1)
void flash_mma_kernel(const __nv_bfloat16* __restrict__ Qhi,
                      const __nv_bfloat16* __restrict__ Qlo,
                      const __nv_bfloat16* __restrict__ Kbh,
                      const __nv_bfloat16* __restrict__ Kbl,
                      const __nv_bfloat16* __restrict__ Vbh,
                      const __nv_bfloat16* __restrict__ Vbl,
                      float* __restrict__ Op, float* __restrict__ Ml)
{
    extern __shared__ char smraw[];
    const uint32_t sb = smem_to_u32(smraw);
    const int tid = threadIdx.x, wid = tid >> 5, lane = tid & 31;
    const int qt = blockIdx.x, h = blockIdx.y, z = blockIdx.z;
    const int kvh = h / NREP;
    const int q0 = qt * 128;
    const int w16 = wid * 16;
    const int nt = 50 + 2 * qt;
    const int t0 = z ? (nt >> 1) : 0;
    const int t1 = z ? nt : (nt >> 1);

    // ---- Q tile load (once) ----
    #pragma unroll
    for (int i = 0; i < 16; i++) {
        int cg = tid + i * 256;
        int comp = i >> 3;
        int c = cg & 2047;
        int row = c >> 4, d8 = (c & 15) * 8;
        uint32_t dst = sb + (uint32_t)comp * 32768 + (uint32_t)((c >> 3) & 1) * 16384
                     + SMEM_SWIZZLE_128B((uint32_t)(row * 128 + (c & 7) * 16));
        const __nv_bfloat16* src = (comp ? Qlo : Qhi);
        cp_async16(dst, src + (size_t)(q0 + row) * HID + h * HDIM + d8);
    }
    cp_commit();

    auto load_stage = [&](int t) {
        uint32_t base = sb + 65536u + (uint32_t)(t & 1) * 65536u;
        int kvbase = t * 64;
        #pragma unroll
        for (int i = 0; i < 16; i++) {
            int comp = i >> 2;
            int c = (tid + i * 256) & 1023;
            int kv = c >> 4, d8 = (c & 15) * 8;
            uint32_t dst = base + (uint32_t)comp * 16384 + (uint32_t)((c >> 3) & 1) * 8192
                         + SMEM_SWIZZLE_128B((uint32_t)(kv * 128 + (c & 7) * 16));
            const __nv_bfloat16* src =
                (comp == 0) ? Kbh : (comp == 1) ? Kbl : (comp == 2) ? Vbh : Vbl;
            cp_async16(dst, src + ((size_t)(kvh * KVTOT + kvbase + kv) * HDIM + d8));
        }
        cp_commit();
    };

    load_stage(t0);

    float Oacc[16][4];
    #pragma unroll
    for (int i = 0; i < 16; i++)
        #pragma unroll
        for (int j = 0; j < 4; j++) Oacc[i][j] = 0.0f;
    float m0 = -INFINITY, m1 = -INFINITY, l0 = 0.0f, l1 = 0.0f;

    const float SL = 0.08838834764831845f * 1.4426950408889634f;
    const int r0 = lane >> 2;

    for (int t = t0; t < t1; t++) {
        if (t + 1 < t1) { load_stage(t + 1); cp_wait<1>(); }
        else            { cp_wait<0>(); }
        __syncthreads();

        const uint32_t stage = sb + 65536u + (uint32_t)(t & 1) * 65536u;
        const int kvbase = t * 64;

        // ---- S = Q K^T (3-pass split) ----
        float S[8][4];
        #pragma unroll
        for (int i = 0; i < 8; i++)
            #pragma unroll
            for (int j = 0; j < 4; j++) S[i][j] = 0.0f;

        #pragma unroll
        for (int kc = 0; kc < 8; kc++) {
            uint32_t qh[4], ql[4];
            uint32_t qoff = (uint32_t)((w16 + (lane & 15)) * 128 + (kc & 3) * 32 + (lane >> 4) * 16);
            uint32_t qa = sb + (uint32_t)(kc >> 2) * 16384 + SMEM_SWIZZLE_128B(qoff);
            ldm_x4(qh, qa);
            ldm_x4(ql, qa + 32768);
            uint32_t kcol = (uint32_t)((kc & 3) * 32 + ((lane >> 3) & 1) * 16);
            #pragma unroll
            for (int np = 0; np < 4; np++) {
                uint32_t koff = (uint32_t)((np * 16 + ((lane >> 4) & 1) * 8 + (lane & 7)) * 128) + kcol;
                uint32_t ka = stage + (uint32_t)(kc >> 2) * 8192 + SMEM_SWIZZLE_128B(koff);
                uint32_t kh[4], kl[4];
                ldm_x4(kh, ka);
                ldm_x4(kl, ka + 16384);
                mma_bf16(S[2*np],   qh, kh);     mma_bf16(S[2*np],   ql, kh);
                mma_bf16(S[2*np],   qh, kl);
                mma_bf16(S[2*np+1], qh, kh + 2); mma_bf16(S[2*np+1], ql, kh + 2);
                mma_bf16(S[2*np+1], qh, kl + 2);
            }
        }

        // ---- causal mask (only last two global tiles; z=1 only) ----
        if (t >= nt - 2) {
            const int lim0 = PASTLEN + q0 + w16 + r0;
            const int lim1 = lim0 + 8;
            #pragma unroll
            for (int nc = 0; nc < 8; nc++) {
                int col = kvbase + nc * 8 + (lane & 3) * 2;
                if (col     > lim0) S[nc][0] = -1e30f;
                if (col + 1 > lim0) S[nc][1] = -1e30f;
                if (col     > lim1) S[nc][2] = -1e30f;
                if (col + 1 > lim1) S[nc][3] = -1e30f;
            }
        }

        // ---- online softmax ----
        float mx0 = -INFINITY, mx1 = -INFINITY;
        #pragma unroll
        for (int nc = 0; nc < 8; nc++) {
            mx0 = fmaxf(mx0, fmaxf(S[nc][0], S[nc][1]));
            mx1 = fmaxf(mx1, fmaxf(S[nc][2], S[nc][3]));
        }
        mx0 = fmaxf(mx0, __shfl_xor_sync(0xffffffffu, mx0, 1));
        mx0 = fmaxf(mx0, __shfl_xor_sync(0xffffffffu, mx0, 2));
        mx1 = fmaxf(mx1, __shfl_xor_sync(0xffffffffu, mx1, 1));
        mx1 = fmaxf(mx1, __shfl_xor_sync(0xffffffffu, mx1, 2));
        float mn0 = fmaxf(m0, mx0 * SL);
        float mn1 = fmaxf(m1, mx1 * SL);
        float cor0 = fexp2(m0 - mn0);
        float cor1 = fexp2(m1 - mn1);
        m0 = mn0; m1 = mn1;

        uint32_t pH[8][2], pL[8][2];
        float rs0 = 0.0f, rs1 = 0.0f;
        #pragma unroll
        for (int nc = 0; nc < 8; nc++) {
            float p0 = fexp2(S[nc][0] * SL - mn0);
            float p1 = fexp2(S[nc][1] * SL - mn0);
            float p2 = fexp2(S[nc][2] * SL - mn1);
            float p3 = fexp2(S[nc][3] * SL - mn1);
            rs0 += p0 + p1;  rs1 += p2 + p3;
            __nv_bfloat16 h0 = __float2bfloat16(p0), h1 = __float2bfloat16(p1);
            __nv_bfloat16 h2 = __float2bfloat16(p2), h3 = __float2bfloat16(p3);
            pH[nc][0] = packbf(h0, h1);
            pH[nc][1] = packbf(h2, h3);
            pL[nc][0] = packbf(__float2bfloat16(p0 - __bfloat162float(h0)),
                               __float2bfloat16(p1 - __bfloat162float(h1)));
            pL[nc][1] = packbf(__float2bfloat16(p2 - __bfloat162float(h2)),
                               __float2bfloat16(p3 - __bfloat162float(h3)));
        }
        rs0 += __shfl_xor_sync(0xffffffffu, rs0, 1);
        rs0 += __shfl_xor_sync(0xffffffffu, rs0, 2);
        rs1 += __shfl_xor_sync(0xffffffffu, rs1, 1);
        rs1 += __shfl_xor_sync(0xffffffffu, rs1, 2);
        l0 = l0 * cor0 + rs0;
        l1 = l1 * cor1 + rs1;

        #pragma unroll
        for (int nc = 0; nc < 16; nc++) {
            Oacc[nc][0] *= cor0; Oacc[nc][1] *= cor0;
            Oacc[nc][2] *= cor1; Oacc[nc][3] *= cor1;
        }

        // ---- O += P V (3-pass split) ----
        #pragma unroll
        for (int kc = 0; kc < 4; kc++) {
            uint32_t aH[4] = { pH[2*kc][0], pH[2*kc][1], pH[2*kc+1][0], pH[2*kc+1][1] };
            uint32_t aL[4] = { pL[2*kc][0], pL[2*kc][1], pL[2*kc+1][0], pL[2*kc+1][1] };
            uint32_t vrow = (uint32_t)(kc * 16 + ((lane >> 3) & 1) * 8 + (lane & 7));
            #pragma unroll
            for (int dp = 0; dp < 8; dp++) {
                uint32_t voff = vrow * 128 + (uint32_t)((dp & 3) * 32 + ((lane >> 4) & 1) * 16);
                uint32_t va = stage + 32768u + (uint32_t)(dp >> 2) * 8192 + SMEM_SWIZZLE_128B(voff);
                uint32_t vh[4], vl[4];
                ldm_x4t(vh, va);
                ldm_x4t(vl, va + 16384);
                mma_bf16(Oacc[2*dp],   aH, vh);     mma_bf16(Oacc[2*dp],   aL, vh);
                mma_bf16(Oacc[2*dp],   aH, vl);
                mma_bf16(Oacc[2*dp+1], aH, vh + 2); mma_bf16(Oacc[2*dp+1], aL, vh + 2);
                mma_bf16(Oacc[2*dp+1], aH, vl + 2);
            }
        }
        __syncthreads();
    }

    // ---- epilogue: write raw partials ----
    const int rowa = q0 + w16 + r0;
    const size_t pb = ((size_t)(z * NHEADS + h) * QLEN);
    #pragma unroll
    for (int nc = 0; nc < 16; nc++) {
        int col = nc * 8 + (lane & 3) * 2;
        *(float2*)(Op + (pb + rowa) * HDIM + col) =
            make_float2(Oacc[nc][0], Oacc[nc][1]);
        *(float2*)(Op + (pb + rowa + 8) * HDIM + col) =
            make_float2(Oacc[nc][2], Oacc[nc][3]);
    }
    if ((lane & 3) == 0) {
        Ml[(pb + rowa) * 2]     = m0;
        Ml[(pb + rowa) * 2 + 1] = l0;
        Ml[(pb + rowa + 8) * 2]     = m1;
        Ml[(pb + rowa + 8) * 2 + 1] = l1;
    }
}

// Merge the two KV-split partials -> gA [q][h*128+d]
__global__ void combine_kernel(const float* __restrict__ Op,
                               const float* __restrict__ Ml,
                               float* __restrict__ Out)
{
    int i = blockIdx.x * blockDim.x + threadIdx.x;
    if (i >= NHEADS * QLEN * (HDIM / 4)) return;
    int hq = i >> 5;
    int d4 = (i & 31) * 4;
    int h = hq >> 10, q = hq & 1023;
    size_t p0 = (size_t)h * QLEN + q;
    size_t p1 = (size_t)(NHEADS + h) * QLEN + q;
    float m0 = Ml[p0 * 2], l0 = Ml[p0 * 2 + 1];
    float m1 = Ml[p1 * 2], l1 = Ml[p1 * 2 + 1];
    float m = fmaxf(m0, m1);
    float s0 = fexp2(m0 - m), s1 = fexp2(m1 - m);
    float inv = 1.0f / (l0 * s0 + l1 * s1);
    s0 *= inv; s1 *= inv;
    float4 a = *(const float4*)(Op + p0 * HDIM + d4);
    float4 b = *(const float4*)(Op + p1 * HDIM + d4);
    float4 o;
    o.x = a.x * s0 + b.x * s1;
    o.y = a.y * s0 + b.y * s1;
    o.z = a.z * s0 + b.z * s1;
    o.w = a.w * s0 + b.w * s1;
    *(float4*)(Out + (size_t)q * HID + h * HDIM + d4) = o;
}

// ---------------------------------------------------------------------------
// Launch
// ---------------------------------------------------------------------------
extern "C" void kernel_launch(void* const* d_in, const int* in_sizes, int n_in,
                              void* d_out, int out_size)
{
    const float* hid = (const float*)d_in[0];
    const float* kc  = (const float*)d_in[1];
    const float* vc  = (const float*)d_in[2];
    const float* Wq  = (const float*)d_in[3];
    const float* bq  = (const float*)d_in[4];
    const float* Wk  = (const float*)d_in[5];
    const float* bk  = (const float*)d_in[6];
    const float* Wv  = (const float*)d_in[7];
    const float* bv  = (const float*)d_in[8];
    const float* Wo  = (const float*)d_in[9];
    const int*   pos = (const int*)d_in[10];
    float* out = (float*)d_out;

    float *gQ, *gK, *gV, *gA, *gOp, *gMl;
    cudaGetSymbolAddress((void**)&gQ, g_Q);
    cudaGetSymbolAddress((void**)&gK, g_K);
    cudaGetSymbolAddress((void**)&gV, g_V);
    cudaGetSymbolAddress((void**)&gA, g_A);
    cudaGetSymbolAddress((void**)&gOp, g_Op);
    cudaGetSymbolAddress((void**)&gMl, g_Ml);
    __nv_bfloat16 *hHi, *hLo, *aHi, *aLo;
    __nv_bfloat16 *qHi, *qLo, *kHi, *kLo, *vHi, *vLo, *oHi, *oLo;
    __nv_bfloat16 *QbH, *QbL, *KbH, *KbL, *VbH, *VbL;
    cudaGetSymbolAddress((void**)&hHi, g_hid_hi);
    cudaGetSymbolAddress((void**)&hLo, g_hid_lo);
    cudaGetSymbolAddress((void**)&aHi, g_att_hi);
    cudaGetSymbolAddress((void**)&aLo, g_att_lo);
    cudaGetSymbolAddress((void**)&qHi, g_WqT_hi);
    cudaGetSymbolAddress((void**)&qLo, g_WqT_lo);
    cudaGetSymbolAddress((void**)&kHi, g_WkT_hi);
    cudaGetSymbolAddress((void**)&kLo, g_WkT_lo);
    cudaGetSymbolAddress((void**)&vHi, g_WvT_hi);
    cudaGetSymbolAddress((void**)&vLo, g_WvT_lo);
    cudaGetSymbolAddress((void**)&oHi, g_WoT_hi);
    cudaGetSymbolAddress((void**)&oLo, g_WoT_lo);
    cudaGetSymbolAddress((void**)&QbH, g_Qb_hi);
    cudaGetSymbolAddress((void**)&QbL, g_Qb_lo);
    cudaGetSymbolAddress((void**)&KbH, g_Kb_hi);
    cudaGetSymbolAddress((void**)&KbL, g_Kb_lo);
    cudaGetSymbolAddress((void**)&VbH, g_Vb_hi);
    cudaGetSymbolAddress((void**)&VbL, g_Vb_lo);

    cudaFuncSetAttribute(qkv_mm_kernel, cudaFuncAttributeMaxDynamicSharedMemorySize, MM_SMEM);
    cudaFuncSetAttribute(mm_kernel, cudaFuncAttributeMaxDynamicSharedMemorySize, MM_SMEM);
    cudaFuncSetAttribute(flash_mma_kernel, cudaFuncAttributeMaxDynamicSharedMemorySize, FL_SMEM);

    // 1. operand preparation
    const int n4 = QLEN * HID / 4;
    split_kernel<<<(n4 + 255) / 256, 256>>>(hid, hHi, hLo, n4);
    dim3 tb(32, 8);
    transpose_split_kernel<<<dim3(HID/32, HID/32), tb>>>(Wq, HID, HID, qHi, qLo);
    transpose_split_kernel<<<dim3((NKV*HDIM)/32, HID/32), tb>>>(Wk, HID, NKV*HDIM, kHi, kLo);
    transpose_split_kernel<<<dim3((NKV*HDIM)/32, HID/32), tb>>>(Wv, HID, NKV*HDIM, vHi, vLo);
    transpose_split_kernel<<<dim3(HID/32, HID/32), tb>>>(Wo, HID, HID, oHi, oLo);

    // 2. fused QKV projections (single wave-balanced grid)
    qkv_mm_kernel<<<dim3(36, 8), 256, MM_SMEM>>>(hHi, hLo, qHi, qLo, kHi, kLo, vHi, vLo,
                                                 bq, bk, bv, gQ, gK, gV);

    // 3. RoPE (Q and K in one launch)
    rope_kernel<<<dim3(QLEN, 2), 256>>>(gQ, gK, pos);

    // 4. pack attention operands
    split_kernel<<<(n4 + 255) / 256, 256>>>(gQ, QbH, QbL, n4);
    const int pk = NKV * KVTOT * (HDIM / 4);
    pack_kv_kernel<<<dim3((pk + 255) / 256, 2), 256>>>(kc, gK, vc, gV, KbH, KbL, VbH, VbL);

    // 5. attention (tensorized, 2-way KV split) + combine
    flash_mma_kernel<<<dim3(8, 28, 2), 256, FL_SMEM>>>(QbH, QbL, KbH, KbL, VbH, VbL, gOp, gMl);
    const int cn = NHEADS * QLEN * (HDIM / 4);
    combine_kernel<<<(cn + 255) / 256, 256>>>(gOp, gMl, gA);

    // 6. output projection
    split_kernel<<<(n4 + 255) / 256, 256>>>(gA, aHi, aLo, n4);
    mm_kernel<<<dim3(28, 8), 256, MM_SMEM>>>(aHi, aLo, oHi, oLo, out);
}

// round 8
// speedup vs baseline: 4.8001x; 1.0595x over previous
#include <cuda_runtime.h>
#include <cuda_bf16.h>
#include <cstdint>
#include <math.h>

// ---------------------------------------------------------------------------
// Problem constants
// ---------------------------------------------------------------------------
#define QLEN     1024
#define HID      3584
#define NHEADS   28
#define NKV      4
#define HDIM     128
#define PASTLEN  3072
#define KVTOT    4096
#define NREP     7

// ---------------------------------------------------------------------------
// Scratch (device globals)
// ---------------------------------------------------------------------------
__device__ float g_Q[QLEN * HID];               // QKV outputs (pre-rope, f32)
__device__ float g_K[QLEN * (NKV*HDIM)];
__device__ float g_V[QLEN * (NKV*HDIM)];

__device__ __nv_bfloat16 g_hid_hi[QLEN * HID];
__device__ __nv_bfloat16 g_hid_lo[QLEN * HID];
__device__ __nv_bfloat16 g_att_hi[QLEN * HID];
__device__ __nv_bfloat16 g_att_lo[QLEN * HID];
__device__ __nv_bfloat16 g_WqT_hi[HID * HID];
__device__ __nv_bfloat16 g_WqT_lo[HID * HID];
__device__ __nv_bfloat16 g_WkT_hi[(NKV*HDIM) * HID];
__device__ __nv_bfloat16 g_WkT_lo[(NKV*HDIM) * HID];
__device__ __nv_bfloat16 g_WvT_hi[(NKV*HDIM) * HID];
__device__ __nv_bfloat16 g_WvT_lo[(NKV*HDIM) * HID];
__device__ __nv_bfloat16 g_WoT_hi[HID * HID];
__device__ __nv_bfloat16 g_WoT_lo[HID * HID];

// attention operands (split bf16)
__device__ __nv_bfloat16 g_Qb_hi[QLEN * HID];
__device__ __nv_bfloat16 g_Qb_lo[QLEN * HID];
__device__ __nv_bfloat16 g_Kb_hi[NKV * KVTOT * HDIM];
__device__ __nv_bfloat16 g_Kb_lo[NKV * KVTOT * HDIM];
__device__ __nv_bfloat16 g_Vb_hi[NKV * KVTOT * HDIM];
__device__ __nv_bfloat16 g_Vb_lo[NKV * KVTOT * HDIM];

// flash split-KV partials; later reused as oproj split-K partials
// (flash: 2*28*1024*128 = 7.34M floats; oproj: 2*1024*3584 = 7.34M floats)
__device__ float g_Op[2 * NHEADS * QLEN * HDIM];
__device__ float g_Ml[2 * NHEADS * QLEN * 2];

// ---------------------------------------------------------------------------
// Helpers (plain-sm_103-legal: cp.async + ldmatrix + mma.sync only)
// ---------------------------------------------------------------------------
__device__ __forceinline__ uint32_t smem_to_u32(const void* p) {
    uint32_t a;
    asm("{ .reg .u64 t; cvta.to.shared.u64 t, %1; cvt.u32.u64 %0, t; }" : "=r"(a) : "l"(p));
    return a;
}
#define SMEM_SWIZZLE_128B(b) ((b) ^ (((b) >> 3) & 0x70))

__device__ __forceinline__ void cp_async16(uint32_t dst, const void* src) {
    asm volatile("cp.async.cg.shared.global [%0], [%1], 16;" :: "r"(dst), "l"(src) : "memory");
}
__device__ __forceinline__ void cp_commit() {
    asm volatile("cp.async.commit_group;" ::: "memory");
}
template <int N> __device__ __forceinline__ void cp_wait() {
    asm volatile("cp.async.wait_group %0;" :: "n"(N) : "memory");
}

__device__ __forceinline__ void ldm_x4(uint32_t* r, uint32_t addr) {
    asm volatile("ldmatrix.sync.aligned.m8n8.x4.shared.b16 {%0,%1,%2,%3}, [%4];"
                 : "=r"(r[0]), "=r"(r[1]), "=r"(r[2]), "=r"(r[3]) : "r"(addr));
}
__device__ __forceinline__ void ldm_x4t(uint32_t* r, uint32_t addr) {
    asm volatile("ldmatrix.sync.aligned.m8n8.x4.trans.shared.b16 {%0,%1,%2,%3}, [%4];"
                 : "=r"(r[0]), "=r"(r[1]), "=r"(r[2]), "=r"(r[3]) : "r"(addr));
}
__device__ __forceinline__ void mma_bf16(float* c, const uint32_t* a, const uint32_t* b) {
    asm volatile("mma.sync.aligned.m16n8k16.row.col.f32.bf16.bf16.f32 "
                 "{%0,%1,%2,%3}, {%4,%5,%6,%7}, {%8,%9}, {%0,%1,%2,%3};"
                 : "+f"(c[0]), "+f"(c[1]), "+f"(c[2]), "+f"(c[3])
                 : "r"(a[0]), "r"(a[1]), "r"(a[2]), "r"(a[3]), "r"(b[0]), "r"(b[1]));
}
__device__ __forceinline__ float fexp2(float x) {
    float y; asm("ex2.approx.ftz.f32 %0, %1;" : "=f"(y) : "f"(x)); return y;
}
__device__ __forceinline__ uint32_t packbf(__nv_bfloat16 a, __nv_bfloat16 b) {
    __nv_bfloat162 t(a, b);
    return *(uint32_t*)&t;
}

// ---------------------------------------------------------------------------
// f32 -> split bf16 (hi + lo)   (hidden states only)
// ---------------------------------------------------------------------------
__global__ void split_kernel(const float* __restrict__ X,
                             __nv_bfloat16* __restrict__ hi,
                             __nv_bfloat16* __restrict__ lo, int n4)
{
    int i = blockIdx.x * blockDim.x + threadIdx.x;
    if (i >= n4) return;
    float4 x = ((const float4*)X)[i];
    float v[4] = { x.x, x.y, x.z, x.w };
    __nv_bfloat16 h[4], l[4];
    #pragma unroll
    for (int j = 0; j < 4; j++) {
        h[j] = __float2bfloat16(v[j]);
        l[j] = __float2bfloat16(v[j] - __bfloat162float(h[j]));
    }
    __nv_bfloat162* H = (__nv_bfloat162*)hi;
    __nv_bfloat162* L = (__nv_bfloat162*)lo;
    H[2*i]   = __nv_bfloat162(h[0], h[1]);
    H[2*i+1] = __nv_bfloat162(h[2], h[3]);
    L[2*i]   = __nv_bfloat162(l[0], l[1]);
    L[2*i+1] = __nv_bfloat162(l[2], l[3]);
}

// All 4 weight transposes in one launch: W [K=3584][N] f32 -> T [N][K] bf16 hi/lo
__global__ void transpose_split_all(const float* __restrict__ Wq,
                                    const float* __restrict__ Wk,
                                    const float* __restrict__ Wv,
                                    const float* __restrict__ Wo,
                                    __nv_bfloat16* __restrict__ qhi, __nv_bfloat16* __restrict__ qlo,
                                    __nv_bfloat16* __restrict__ khi, __nv_bfloat16* __restrict__ klo,
                                    __nv_bfloat16* __restrict__ vhi, __nv_bfloat16* __restrict__ vlo,
                                    __nv_bfloat16* __restrict__ ohi, __nv_bfloat16* __restrict__ olo)
{
    const int z = blockIdx.z;
    const float* W; __nv_bfloat16 *Thi, *Tlo; int N;
    if      (z == 0) { W = Wq; Thi = qhi; Tlo = qlo; N = HID; }
    else if (z == 1) { W = Wk; Thi = khi; Tlo = klo; N = NKV*HDIM; }
    else if (z == 2) { W = Wv; Thi = vhi; Tlo = vlo; N = NKV*HDIM; }
    else             { W = Wo; Thi = ohi; Tlo = olo; N = HID; }
    if (blockIdx.x * 32 >= N) return;

    __shared__ float t[32][33];
    int n0 = blockIdx.x * 32, k0 = blockIdx.y * 32;
    int tx = threadIdx.x, ty = threadIdx.y;
    #pragma unroll
    for (int r = 0; r < 4; r++)
        t[ty + r*8][tx] = W[(size_t)(k0 + ty + r*8) * N + n0 + tx];
    __syncthreads();
    #pragma unroll
    for (int r = 0; r < 4; r++) {
        int n = n0 + ty + r*8;
        float v = t[tx][ty + r*8];
        __nv_bfloat16 h = __float2bfloat16(v);
        __nv_bfloat16 l = __float2bfloat16(v - __bfloat162float(h));
        Thi[(size_t)n * HID + k0 + tx] = h;
        Tlo[(size_t)n * HID + k0 + tx] = l;
    }
}

// Pack KV split-bf16: y=0 -> K cache rows only (new K rows written by rope_pack);
// y=1 -> V all rows (cache + new from gV).
__global__ void pack_kv_kernel(const float* __restrict__ kcache,
                               const float* __restrict__ vcache,
                               const float* __restrict__ vnew,
                               __nv_bfloat16* __restrict__ khi,
                               __nv_bfloat16* __restrict__ klo,
                               __nv_bfloat16* __restrict__ vhi,
                               __nv_bfloat16* __restrict__ vlo)
{
    int i = blockIdx.x * blockDim.x + threadIdx.x;
    const float* src; __nv_bfloat16 *hi, *lo;
    int kvh, pos, d4;
    if (blockIdx.y == 0) {
        if (i >= NKV * PASTLEN * 32) return;
        kvh = i / (PASTLEN * 32);
        int rem = i % (PASTLEN * 32);
        pos = rem >> 5; d4 = (rem & 31) * 4;
        src = kcache + ((size_t)(kvh * PASTLEN + pos) * HDIM + d4);
        hi = khi; lo = klo;
    } else {
        if (i >= NKV * KVTOT * 32) return;
        kvh = i / (KVTOT * 32);
        int rem = i % (KVTOT * 32);
        pos = rem >> 5; d4 = (rem & 31) * 4;
        src = (pos < PASTLEN)
            ? vcache + ((size_t)(kvh * PASTLEN + pos) * HDIM + d4)
            : vnew + ((size_t)(pos - PASTLEN) * (NKV * HDIM) + kvh * HDIM + d4);
        hi = vhi; lo = vlo;
    }
    float4 v = *(const float4*)src;
    float a[4] = { v.x, v.y, v.z, v.w };
    __nv_bfloat16 h[4], l[4];
    #pragma unroll
    for (int j = 0; j < 4; j++) {
        h[j] = __float2bfloat16(a[j]);
        l[j] = __float2bfloat16(a[j] - __bfloat162float(h[j]));
    }
    size_t o = ((size_t)(kvh * KVTOT + pos) * HDIM + d4) >> 1;
    ((__nv_bfloat162*)hi)[o]     = __nv_bfloat162(h[0], h[1]);
    ((__nv_bfloat162*)hi)[o + 1] = __nv_bfloat162(h[2], h[3]);
    ((__nv_bfloat162*)lo)[o]     = __nv_bfloat162(l[0], l[1]);
    ((__nv_bfloat162*)lo)[o + 1] = __nv_bfloat162(l[2], l[3]);
}

// ---------------------------------------------------------------------------
// mma.sync split-precision GEMM core. CTA tile 128x128, 8 warps of 64x32.
// K covered in `segst` stages of 64 starting at kbase, x3 precision segments.
// Single __syncthreads per stage (top barrier doubles as reuse guard).
// ---------------------------------------------------------------------------
#define MM_STAGES      4
#define MM_STAGE_BYTES 32768
#define MM_SMEM        (1024 + MM_STAGES * MM_STAGE_BYTES)

__device__ __forceinline__ void mm_tile(
    const __nv_bfloat16* __restrict__ Ahi, const __nv_bfloat16* __restrict__ Alo,
    const __nv_bfloat16* __restrict__ Bhi, const __nv_bfloat16* __restrict__ Blo,
    const float* __restrict__ bias, float* __restrict__ C, int ldc,
    int m0, int n0, int kbase, int segst, char* smem)
{
    const uint32_t sb   = smem_to_u32(smem);
    const uint32_t DATA = (sb + 1023u) & ~1023u;
    const int tid = threadIdx.x, wid = tid >> 5, lane = tid & 31;
    const int wm = (wid & 1) * 64;
    const int wn = (wid >> 1) * 32;
    const int NST = 3 * segst;

    uint32_t offs[4]; int rr[4], cc[4];
    #pragma unroll
    for (int i = 0; i < 4; i++) {
        int c = tid + i * 256;
        rr[i] = c >> 3;
        cc[i] = (c & 7) * 8;
        offs[i] = SMEM_SWIZZLE_128B((uint32_t)(rr[i] * 128 + (c & 7) * 16));
    }

    auto load_stage = [&](int g) {
        int seg = g / segst, kk = kbase + (g % segst) * 64;
        const __nv_bfloat16* A = (seg == 2) ? Alo : Ahi;
        const __nv_bfloat16* B = (seg == 1) ? Blo : Bhi;
        uint32_t ab = DATA + (uint32_t)(g & 3) * MM_STAGE_BYTES;
        uint32_t bb = ab + 16384;
        #pragma unroll
        for (int i = 0; i < 4; i++) {
            cp_async16(ab + offs[i], A + (size_t)(m0 + rr[i]) * HID + kk + cc[i]);
            cp_async16(bb + offs[i], B + (size_t)(n0 + rr[i]) * HID + kk + cc[i]);
        }
        cp_commit();
    };

    float acc[4][4][4];
    #pragma unroll
    for (int a = 0; a < 4; a++)
        #pragma unroll
        for (int b = 0; b < 4; b++)
            #pragma unroll
            for (int c = 0; c < 4; c++) acc[a][b][c] = 0.0f;

    const int a_row = wm + (lane & 15);
    const int a_kb  = (lane >> 4) * 16;
    const int b_row = wn + ((lane >> 4) & 1) * 8 + (lane & 7);
    const int b_kb  = ((lane >> 3) & 1) * 16;

    load_stage(0); load_stage(1); load_stage(2);

    for (int g = 0; g < NST; g++) {
        if      (g <  NST - 2) cp_wait<2>();
        else if (g == NST - 2) cp_wait<1>();
        else                   cp_wait<0>();
        __syncthreads();                 // stage g visible; all warps done stage g-1
        if (g + 3 < NST) load_stage(g + 3);

        uint32_t ab = DATA + (uint32_t)(g & 3) * MM_STAGE_BYTES;
        uint32_t bb = ab + 16384;

        #pragma unroll
        for (int ks = 0; ks < 4; ks++) {
            uint32_t aF[4][4];
            #pragma unroll
            for (int mi = 0; mi < 4; mi++) {
                uint32_t byte = (uint32_t)((a_row + mi * 16) * 128 + ks * 32 + a_kb);
                ldm_x4(aF[mi], ab + SMEM_SWIZZLE_128B(byte));
            }
            uint32_t bF[4][2];
            #pragma unroll
            for (int nb2 = 0; nb2 < 2; nb2++) {
                uint32_t byte = (uint32_t)((b_row + nb2 * 16) * 128 + ks * 32 + b_kb);
                uint32_t r[4];
                ldm_x4(r, bb + SMEM_SWIZZLE_128B(byte));
                bF[nb2*2+0][0] = r[0]; bF[nb2*2+0][1] = r[1];
                bF[nb2*2+1][0] = r[2]; bF[nb2*2+1][1] = r[3];
            }
            #pragma unroll
            for (int mi = 0; mi < 4; mi++)
                #pragma unroll
                for (int ni = 0; ni < 4; ni++)
                    mma_bf16(acc[mi][ni], aF[mi], bF[ni]);
        }
    }

    const int group = lane >> 2, tig = lane & 3;
    #pragma unroll
    for (int mi = 0; mi < 4; mi++) {
        #pragma unroll
        for (int ni = 0; ni < 4; ni++) {
            int r0 = m0 + wm + mi * 16 + group;
            int c0 = n0 + wn + ni * 8 + tig * 2;
            float b0 = 0.f, b1 = 0.f;
            if (bias) { b0 = bias[c0]; b1 = bias[c0 + 1]; }
            float2 v0 = make_float2(acc[mi][ni][0] + b0, acc[mi][ni][1] + b1);
            float2 v1 = make_float2(acc[mi][ni][2] + b0, acc[mi][ni][3] + b1);
            *(float2*)(C + (size_t)r0 * ldc + c0)       = v0;
            *(float2*)(C + (size_t)(r0 + 8) * ldc + c0) = v1;
        }
    }
}

// Fused QKV projection: grid (36, 8)
__global__ __launch_bounds__(256)
void qkv_mm_kernel(const __nv_bfloat16* __restrict__ Ahi, const __nv_bfloat16* __restrict__ Alo,
                   const __nv_bfloat16* __restrict__ qHi, const __nv_bfloat16* __restrict__ qLo,
                   const __nv_bfloat16* __restrict__ kHi, const __nv_bfloat16* __restrict__ kLo,
                   const __nv_bfloat16* __restrict__ vHi, const __nv_bfloat16* __restrict__ vLo,
                   const float* __restrict__ bq, const float* __restrict__ bk,
                   const float* __restrict__ bv,
                   float* __restrict__ gQ, float* __restrict__ gK, float* __restrict__ gV)
{
    extern __shared__ char smem[];
    const int bx = blockIdx.x, m0 = blockIdx.y * 128;
    if (bx < 28)
        mm_tile(Ahi, Alo, qHi, qLo, bq, gQ, HID, m0, bx * 128, 0, 56, smem);
    else if (bx < 32)
        mm_tile(Ahi, Alo, kHi, kLo, bk, gK, NKV*HDIM, m0, (bx - 28) * 128, 0, 56, smem);
    else
        mm_tile(Ahi, Alo, vHi, vLo, bv, gV, NKV*HDIM, m0, (bx - 32) * 128, 0, 56, smem);
}

// Output projection, split-K x2: grid (28, 8, 2) -> partial buffers
__global__ __launch_bounds__(256)
void oproj_kernel(const __nv_bfloat16* __restrict__ Ahi, const __nv_bfloat16* __restrict__ Alo,
                  const __nv_bfloat16* __restrict__ Bhi, const __nv_bfloat16* __restrict__ Blo,
                  float* __restrict__ P)
{
    extern __shared__ char smem[];
    const int z = blockIdx.z;
    mm_tile(Ahi, Alo, Bhi, Blo, nullptr, P + (size_t)z * QLEN * HID, HID,
            blockIdx.y * 128, blockIdx.x * 128, z * 1792, 28, smem);
}

// Sum the two split-K partials -> final output
__global__ void addout_kernel(const float* __restrict__ P, float* __restrict__ out)
{
    int i = blockIdx.x * blockDim.x + threadIdx.x;
    if (i >= QLEN * HID / 4) return;
    float4 a = ((const float4*)P)[i];
    float4 b = ((const float4*)(P + (size_t)QLEN * HID))[i];
    ((float4*)out)[i] = make_float4(a.x + b.x, a.y + b.y, a.z + b.z, a.w + b.w);
}

// ---------------------------------------------------------------------------
// RoPE fused with split-bf16 packing.
// y=0: Q rows -> Qb (layout [q][h*128+d]); y=1: K rows -> Kb rows PASTLEN+q.
// ---------------------------------------------------------------------------
__global__ void rope_pack_kernel(const float* __restrict__ gQ, const float* __restrict__ gK,
                                 const int* __restrict__ pos,
                                 __nv_bfloat16* __restrict__ QbH, __nv_bfloat16* __restrict__ QbL,
                                 __nv_bfloat16* __restrict__ KbH, __nv_bfloat16* __restrict__ KbL)
{
    const int q = blockIdx.x;
    const float p = (float)pos[q];
    const int isK = blockIdx.y;
    const int nh = isK ? NKV : NHEADS;
    const float* src = isK ? (gK + (size_t)q * (NKV*HDIM)) : (gQ + (size_t)q * HID);

    for (int t = threadIdx.x; t < nh * 64; t += blockDim.x) {
        int hh = t >> 6, i = t & 63;
        float e = (float)i * (1.0f / 64.0f);
        float invf = 1.0f / powf(1000000.0f, e);
        float ang = p * invf;
        float s, c;
        sincosf(ang, &s, &c);
        const float* base = src + hh * HDIM;
        float x1 = base[i];
        float x2 = base[i + 64];
        float o1 = x1 * c - x2 * s;
        float o2 = x2 * c + x1 * s;
        __nv_bfloat16 h1 = __float2bfloat16(o1);
        __nv_bfloat16 l1 = __float2bfloat16(o1 - __bfloat162float(h1));
        __nv_bfloat16 h2 = __float2bfloat16(o2);
        __nv_bfloat16 l2 = __float2bfloat16(o2 - __bfloat162float(h2));
        size_t d1, d2;
        if (isK) {
            size_t row = (size_t)hh * KVTOT + PASTLEN + q;
            d1 = row * HDIM + i; d2 = d1 + 64;
            KbH[d1] = h1; KbL[d1] = l1;
            KbH[d2] = h2; KbL[d2] = l2;
        } else {
            d1 = (size_t)q * HID + hh * HDIM + i; d2 = d1 + 64;
            QbH[d1] = h1; QbL[d1] = l1;
            QbH[d2] = h2; QbL[d2] = l2;
        }
    }
}

// ---------------------------------------------------------------------------
// Tensorized flash attention, 2-way KV split, single-sync pipeline.
// grid (8 q-tiles, 28 heads, 2 kv-splits), 256 threads = 8 warps x 16 q-rows.
// ---------------------------------------------------------------------------
#define FL_SMEM (65536 * 3)

__global__ __launch_bounds__(256, 1)
void flash_mma_kernel(const __nv_bfloat16* __restrict__ Qhi,
                      const __nv_bfloat16* __restrict__ Qlo,
                      const __nv_bfloat16* __restrict__ Kbh,
                      const __nv_bfloat16* __restrict__ Kbl,
                      const __nv_bfloat16* __restrict__ Vbh,
                      const __nv_bfloat16* __restrict__ Vbl,
                      float* __restrict__ Op, float* __restrict__ Ml)
{
    extern __shared__ char smraw[];
    const uint32_t sb = smem_to_u32(smraw);
    const int tid = threadIdx.x, wid = tid >> 5, lane = tid & 31;
    const int qt = blockIdx.x, h = blockIdx.y, z = blockIdx.z;
    const int kvh = h / NREP;
    const int q0 = qt * 128;
    const int w16 = wid * 16;
    const int nt = 50 + 2 * qt;
    const int t0 = z ? (nt >> 1) : 0;
    const int t1 = z ? nt : (nt >> 1);

    // ---- Q tile load (once) ----
    #pragma unroll
    for (int i = 0; i < 16; i++) {
        int cg = tid + i * 256;
        int comp = i >> 3;
        int c = cg & 2047;
        int row = c >> 4, d8 = (c & 15) * 8;
        uint32_t dst = sb + (uint32_t)comp * 32768 + (uint32_t)((c >> 3) & 1) * 16384
                     + SMEM_SWIZZLE_128B((uint32_t)(row * 128 + (c & 7) * 16));
        const __nv_bfloat16* src = (comp ? Qlo : Qhi);
        cp_async16(dst, src + (size_t)(q0 + row) * HID + h * HDIM + d8);
    }
    cp_commit();

    auto load_stage = [&](int t) {
        uint32_t base = sb + 65536u + (uint32_t)(t & 1) * 65536u;
        int kvbase = t * 64;
        #pragma unroll
        for (int i = 0; i < 16; i++) {
            int comp = i >> 2;
            int c = (tid + i * 256) & 1023;
            int kv = c >> 4, d8 = (c & 15) * 8;
            uint32_t dst = base + (uint32_t)comp * 16384 + (uint32_t)((c >> 3) & 1) * 8192
                         + SMEM_SWIZZLE_128B((uint32_t)(kv * 128 + (c & 7) * 16));
            const __nv_bfloat16* src =
                (comp == 0) ? Kbh : (comp == 1) ? Kbl : (comp == 2) ? Vbh : Vbl;
            cp_async16(dst, src + ((size_t)(kvh * KVTOT + kvbase + kv) * HDIM + d8));
        }
        cp_commit();
    };

    load_stage(t0);

    float Oacc[16][4];
    #pragma unroll
    for (int i = 0; i < 16; i++)
        #pragma unroll
        for (int j = 0; j < 4; j++) Oacc[i][j] = 0.0f;
    float m0 = -INFINITY, m1 = -INFINITY, l0 = 0.0f, l1 = 0.0f;

    const float SL = 0.08838834764831845f * 1.4426950408889634f;
    const int r0 = lane >> 2;

    for (int t = t0; t < t1; t++) {
        cp_wait<0>();
        __syncthreads();                 // data ready; all warps done previous tile
        if (t + 1 < t1) load_stage(t + 1);

        const uint32_t stage = sb + 65536u + (uint32_t)(t & 1) * 65536u;
        const int kvbase = t * 64;

        // ---- S = Q K^T (3-pass split) ----
        float S[8][4];
        #pragma unroll
        for (int i = 0; i < 8; i++)
            #pragma unroll
            for (int j = 0; j < 4; j++) S[i][j] = 0.0f;

        #pragma unroll
        for (int kc = 0; kc < 8; kc++) {
            uint32_t qh[4], ql[4];
            uint32_t qoff = (uint32_t)((w16 + (lane & 15)) * 128 + (kc & 3) * 32 + (lane >> 4) * 16);
            uint32_t qa = sb + (uint32_t)(kc >> 2) * 16384 + SMEM_SWIZZLE_128B(qoff);
            ldm_x4(qh, qa);
            ldm_x4(ql, qa + 32768);
            uint32_t kcol = (uint32_t)((kc & 3) * 32 + ((lane >> 3) & 1) * 16);
            #pragma unroll
            for (int np = 0; np < 4; np++) {
                uint32_t koff = (uint32_t)((np * 16 + ((lane >> 4) & 1) * 8 + (lane & 7)) * 128) + kcol;
                uint32_t ka = stage + (uint32_t)(kc >> 2) * 8192 + SMEM_SWIZZLE_128B(koff);
                uint32_t kh[4], kl[4];
                ldm_x4(kh, ka);
                ldm_x4(kl, ka + 16384);
                mma_bf16(S[2*np],   qh, kh);     mma_bf16(S[2*np],   ql, kh);
                mma_bf16(S[2*np],   qh, kl);
                mma_bf16(S[2*np+1], qh, kh + 2); mma_bf16(S[2*np+1], ql, kh + 2);
                mma_bf16(S[2*np+1], qh, kl + 2);
            }
        }

        // ---- causal mask (only last two global tiles; z=1 only) ----
        if (t >= nt - 2) {
            const int lim0 = PASTLEN + q0 + w16 + r0;
            const int lim1 = lim0 + 8;
            #pragma unroll
            for (int nc = 0; nc < 8; nc++) {
                int col = kvbase + nc * 8 + (lane & 3) * 2;
                if (col     > lim0) S[nc][0] = -1e30f;
                if (col + 1 > lim0) S[nc][1] = -1e30f;
                if (col     > lim1) S[nc][2] = -1e30f;
                if (col + 1 > lim1) S[nc][3] = -1e30f;
            }
        }

        // ---- online softmax ----
        float mx0 = -INFINITY, mx1 = -INFINITY;
        #pragma unroll
        for (int nc = 0; nc < 8; nc++) {
            mx0 = fmaxf(mx0, fmaxf(S[nc][0], S[nc][1]));
            mx1 = fmaxf(mx1, fmaxf(S[nc][2], S[nc][3]));
        }
        mx0 = fmaxf(mx0, __shfl_xor_sync(0xffffffffu, mx0, 1));
        mx0 = fmaxf(mx0, __shfl_xor_sync(0xffffffffu, mx0, 2));
        mx1 = fmaxf(mx1, __shfl_xor_sync(0xffffffffu, mx1, 1));
        mx1 = fmaxf(mx1, __shfl_xor_sync(0xffffffffu, mx1, 2));
        float mn0 = fmaxf(m0, mx0 * SL);
        float mn1 = fmaxf(m1, mx1 * SL);
        float cor0 = fexp2(m0 - mn0);
        float cor1 = fexp2(m1 - mn1);
        m0 = mn0; m1 = mn1;

        uint32_t pH[8][2], pL[8][2];
        float rs0 = 0.0f, rs1 = 0.0f;
        #pragma unroll
        for (int nc = 0; nc < 8; nc++) {
            float p0 = fexp2(S[nc][0] * SL - mn0);
            float p1 = fexp2(S[nc][1] * SL - mn0);
            float p2 = fexp2(S[nc][2] * SL - mn1);
            float p3 = fexp2(S[nc][3] * SL - mn1);
            rs0 += p0 + p1;  rs1 += p2 + p3;
            __nv_bfloat16 h0 = __float2bfloat16(p0), h1 = __float2bfloat16(p1);
            __nv_bfloat16 h2 = __float2bfloat16(p2), h3 = __float2bfloat16(p3);
            pH[nc][0] = packbf(h0, h1);
            pH[nc][1] = packbf(h2, h3);
            pL[nc][0] = packbf(__float2bfloat16(p0 - __bfloat162float(h0)),
                               __float2bfloat16(p1 - __bfloat162float(h1)));
            pL[nc][1] = packbf(__float2bfloat16(p2 - __bfloat162float(h2)),
                               __float2bfloat16(p3 - __bfloat162float(h3)));
        }
        rs0 += __shfl_xor_sync(0xffffffffu, rs0, 1);
        rs0 += __shfl_xor_sync(0xffffffffu, rs0, 2);
        rs1 += __shfl_xor_sync(0xffffffffu, rs1, 1);
        rs1 += __shfl_xor_sync(0xffffffffu, rs1, 2);
        l0 = l0 * cor0 + rs0;
        l1 = l1 * cor1 + rs1;

        #pragma unroll
        for (int nc = 0; nc < 16; nc++) {
            Oacc[nc][0] *= cor0; Oacc[nc][1] *= cor0;
            Oacc[nc][2] *= cor1; Oacc[nc][3] *= cor1;
        }

        // ---- O += P V (3-pass split) ----
        #pragma unroll
        for (int kc = 0; kc < 4; kc++) {
            uint32_t aH[4] = { pH[2*kc][0], pH[2*kc][1], pH[2*kc+1][0], pH[2*kc+1][1] };
            uint32_t aL[4] = { pL[2*kc][0], pL[2*kc][1], pL[2*kc+1][0], pL[2*kc+1][1] };
            uint32_t vrow = (uint32_t)(kc * 16 + ((lane >> 3) & 1) * 8 + (lane & 7));
            #pragma unroll
            for (int dp = 0; dp < 8; dp++) {
                uint32_t voff = vrow * 128 + (uint32_t)((dp & 3) * 32 + ((lane >> 4) & 1) * 16);
                uint32_t va = stage + 32768u + (uint32_t)(dp >> 2) * 8192 + SMEM_SWIZZLE_128B(voff);
                uint32_t vh[4], vl[4];
                ldm_x4t(vh, va);
                ldm_x4t(vl, va + 16384);
                mma_bf16(Oacc[2*dp],   aH, vh);     mma_bf16(Oacc[2*dp],   aL, vh);
                mma_bf16(Oacc[2*dp],   aH, vl);
                mma_bf16(Oacc[2*dp+1], aH, vh + 2); mma_bf16(Oacc[2*dp+1], aL, vh + 2);
                mma_bf16(Oacc[2*dp+1], aH, vl + 2);
            }
        }
    }

    // ---- epilogue: write raw partials ----
    const int rowa = q0 + w16 + r0;
    const size_t pb = ((size_t)(z * NHEADS + h) * QLEN);
    #pragma unroll
    for (int nc = 0; nc < 16; nc++) {
        int col = nc * 8 + (lane & 3) * 2;
        *(float2*)(Op + (pb + rowa) * HDIM + col) =
            make_float2(Oacc[nc][0], Oacc[nc][1]);
        *(float2*)(Op + (pb + rowa + 8) * HDIM + col) =
            make_float2(Oacc[nc][2], Oacc[nc][3]);
    }
    if ((lane & 3) == 0) {
        Ml[(pb + rowa) * 2]     = m0;
        Ml[(pb + rowa) * 2 + 1] = l0;
        Ml[(pb + rowa + 8) * 2]     = m1;
        Ml[(pb + rowa + 8) * 2 + 1] = l1;
    }
}

// Merge the two KV-split partials -> split-bf16 attention output (oproj A operand)
__global__ void combine_split_kernel(const float* __restrict__ Op,
                                     const float* __restrict__ Ml,
                                     __nv_bfloat16* __restrict__ aHi,
                                     __nv_bfloat16* __restrict__ aLo)
{
    int i = blockIdx.x * blockDim.x + threadIdx.x;
    if (i >= NHEADS * QLEN * (HDIM / 4)) return;
    int hq = i >> 5;
    int d4 = (i & 31) * 4;
    int h = hq >> 10, q = hq & 1023;
    size_t p0 = (size_t)h * QLEN + q;
    size_t p1 = (size_t)(NHEADS + h) * QLEN + q;
    float m0 = Ml[p0 * 2], l0 = Ml[p0 * 2 + 1];
    float m1 = Ml[p1 * 2], l1 = Ml[p1 * 2 + 1];
    float m = fmaxf(m0, m1);
    float s0 = fexp2(m0 - m), s1 = fexp2(m1 - m);
    float inv = 1.0f / (l0 * s0 + l1 * s1);
    s0 *= inv; s1 *= inv;
    float4 a = *(const float4*)(Op + p0 * HDIM + d4);
    float4 b = *(const float4*)(Op + p1 * HDIM + d4);
    float o[4] = { a.x * s0 + b.x * s1, a.y * s0 + b.y * s1,
                   a.z * s0 + b.z * s1, a.w * s0 + b.w * s1 };
    __nv_bfloat16 h4[4], l4[4];
    #pragma unroll
    for (int j = 0; j < 4; j++) {
        h4[j] = __float2bfloat16(o[j]);
        l4[j] = __float2bfloat16(o[j] - __bfloat162float(h4[j]));
    }
    size_t od = ((size_t)q * HID + h * HDIM + d4) >> 1;
    ((__nv_bfloat162*)aHi)[od]     = __nv_bfloat162(h4[0], h4[1]);
    ((__nv_bfloat162*)aHi)[od + 1] = __nv_bfloat162(h4[2], h4[3]);
    ((__nv_bfloat162*)aLo)[od]     = __nv_bfloat162(l4[0], l4[1]);
    ((__nv_bfloat162*)aLo)[od + 1] = __nv_bfloat162(l4[2], l4[3]);
}

// ---------------------------------------------------------------------------
// Launch
// ---------------------------------------------------------------------------
extern "C" void kernel_launch(void* const* d_in, const int* in_sizes, int n_in,
                              void* d_out, int out_size)
{
    const float* hid = (const float*)d_in[0];
    const float* kc  = (const float*)d_in[1];
    const float* vc  = (const float*)d_in[2];
    const float* Wq  = (const float*)d_in[3];
    const float* bq  = (const float*)d_in[4];
    const float* Wk  = (const float*)d_in[5];
    const float* bk  = (const float*)d_in[6];
    const float* Wv  = (const float*)d_in[7];
    const float* bv  = (const float*)d_in[8];
    const float* Wo  = (const float*)d_in[9];
    const int*   pos = (const int*)d_in[10];
    float* out = (float*)d_out;

    float *gQ, *gK, *gV, *gOp, *gMl;
    cudaGetSymbolAddress((void**)&gQ, g_Q);
    cudaGetSymbolAddress((void**)&gK, g_K);
    cudaGetSymbolAddress((void**)&gV, g_V);
    cudaGetSymbolAddress((void**)&gOp, g_Op);
    cudaGetSymbolAddress((void**)&gMl, g_Ml);
    __nv_bfloat16 *hHi, *hLo, *aHi, *aLo;
    __nv_bfloat16 *qHi, *qLo, *kHi, *kLo, *vHi, *vLo, *oHi, *oLo;
    __nv_bfloat16 *QbH, *QbL, *KbH, *KbL, *VbH, *VbL;
    cudaGetSymbolAddress((void**)&hHi, g_hid_hi);
    cudaGetSymbolAddress((void**)&hLo, g_hid_lo);
    cudaGetSymbolAddress((void**)&aHi, g_att_hi);
    cudaGetSymbolAddress((void**)&aLo, g_att_lo);
    cudaGetSymbolAddress((void**)&qHi, g_WqT_hi);
    cudaGetSymbolAddress((void**)&qLo, g_WqT_lo);
    cudaGetSymbolAddress((void**)&kHi, g_WkT_hi);
    cudaGetSymbolAddress((void**)&kLo, g_WkT_lo);
    cudaGetSymbolAddress((void**)&vHi, g_WvT_hi);
    cudaGetSymbolAddress((void**)&vLo, g_WvT_lo);
    cudaGetSymbolAddress((void**)&oHi, g_WoT_hi);
    cudaGetSymbolAddress((void**)&oLo, g_WoT_lo);
    cudaGetSymbolAddress((void**)&QbH, g_Qb_hi);
    cudaGetSymbolAddress((void**)&QbL, g_Qb_lo);
    cudaGetSymbolAddress((void**)&KbH, g_Kb_hi);
    cudaGetSymbolAddress((void**)&KbL, g_Kb_lo);
    cudaGetSymbolAddress((void**)&VbH, g_Vb_hi);
    cudaGetSymbolAddress((void**)&VbL, g_Vb_lo);

    cudaFuncSetAttribute(qkv_mm_kernel, cudaFuncAttributeMaxDynamicSharedMemorySize, MM_SMEM);
    cudaFuncSetAttribute(oproj_kernel, cudaFuncAttributeMaxDynamicSharedMemorySize, MM_SMEM);
    cudaFuncSetAttribute(flash_mma_kernel, cudaFuncAttributeMaxDynamicSharedMemorySize, FL_SMEM);

    // 1. operand preparation
    const int n4 = QLEN * HID / 4;
    split_kernel<<<(n4 + 255) / 256, 256>>>(hid, hHi, hLo, n4);
    transpose_split_all<<<dim3(112, 112, 4), dim3(32, 8)>>>(
        Wq, Wk, Wv, Wo, qHi, qLo, kHi, kLo, vHi, vLo, oHi, oLo);

    // 2. fused QKV projections
    qkv_mm_kernel<<<dim3(36, 8), 256, MM_SMEM>>>(hHi, hLo, qHi, qLo, kHi, kLo, vHi, vLo,
                                                 bq, bk, bv, gQ, gK, gV);

    // 3. RoPE + split packing of Q and new-K rows
    rope_pack_kernel<<<dim3(QLEN, 2), 256>>>(gQ, gK, pos, QbH, QbL, KbH, KbL);

    // 4. pack K cache rows + all V rows
    pack_kv_kernel<<<dim3((NKV * KVTOT * 32 + 255) / 256, 2), 256>>>(
        kc, vc, gV, KbH, KbL, VbH, VbL);

    // 5. attention (tensorized, 2-way KV split) + combine-with-split
    flash_mma_kernel<<<dim3(8, 28, 2), 256, FL_SMEM>>>(QbH, QbL, KbH, KbL, VbH, VbL, gOp, gMl);
    const int cn = NHEADS * QLEN * (HDIM / 4);
    combine_split_kernel<<<(cn + 255) / 256, 256>>>(gOp, gMl, aHi, aLo);

    // 6. output projection (split-K x2 into partials, then add)
    oproj_kernel<<<dim3(28, 8, 2), 256, MM_SMEM>>>(aHi, aLo, oHi, oLo, gOp);
    addout_kernel<<<(n4 + 255) / 256, 256>>>(gOp, out);
}

// round 9
// speedup vs baseline: 5.0108x; 1.0439x over previous
#include <cuda_runtime.h>
#include <cuda_bf16.h>
#include <cstdint>
#include <math.h>

// ---------------------------------------------------------------------------
// Problem constants
// ---------------------------------------------------------------------------
#define QLEN     1024
#define HID      3584
#define NHEADS   28
#define NKV      4
#define HDIM     128
#define PASTLEN  3072
#define KVTOT    4096
#define NREP     7

// ---------------------------------------------------------------------------
// Scratch (device globals)
// ---------------------------------------------------------------------------
__device__ float g_Q[QLEN * HID];               // QKV outputs (pre-rope, f32)
__device__ float g_K[QLEN * (NKV*HDIM)];
__device__ float g_V[QLEN * (NKV*HDIM)];

__device__ __nv_bfloat16 g_hid_hi[QLEN * HID];
__device__ __nv_bfloat16 g_hid_lo[QLEN * HID];
__device__ __nv_bfloat16 g_att_hi[QLEN * HID];
__device__ __nv_bfloat16 g_att_lo[QLEN * HID];
__device__ __nv_bfloat16 g_WqT_hi[HID * HID];
__device__ __nv_bfloat16 g_WqT_lo[HID * HID];
__device__ __nv_bfloat16 g_WkT_hi[(NKV*HDIM) * HID];
__device__ __nv_bfloat16 g_WkT_lo[(NKV*HDIM) * HID];
__device__ __nv_bfloat16 g_WvT_hi[(NKV*HDIM) * HID];
__device__ __nv_bfloat16 g_WvT_lo[(NKV*HDIM) * HID];
__device__ __nv_bfloat16 g_WoT_hi[HID * HID];
__device__ __nv_bfloat16 g_WoT_lo[HID * HID];

// attention operands (split bf16)
__device__ __nv_bfloat16 g_Qb_hi[QLEN * HID];
__device__ __nv_bfloat16 g_Qb_lo[QLEN * HID];
__device__ __nv_bfloat16 g_Kb_hi[NKV * KVTOT * HDIM];
__device__ __nv_bfloat16 g_Kb_lo[NKV * KVTOT * HDIM];
__device__ __nv_bfloat16 g_Vb_hi[NKV * KVTOT * HDIM];
__device__ __nv_bfloat16 g_Vb_lo[NKV * KVTOT * HDIM];

// flash split-KV partials; later reused as oproj split-K partials
__device__ float g_Op[2 * NHEADS * QLEN * HDIM];
__device__ float g_Ml[2 * NHEADS * QLEN * 2];

// ---------------------------------------------------------------------------
// Helpers (plain-sm_103-legal: cp.async + ldmatrix + mma.sync only)
// ---------------------------------------------------------------------------
__device__ __forceinline__ uint32_t smem_to_u32(const void* p) {
    uint32_t a;
    asm("{ .reg .u64 t; cvta.to.shared.u64 t, %1; cvt.u32.u64 %0, t; }" : "=r"(a) : "l"(p));
    return a;
}
#define SMEM_SWIZZLE_128B(b) ((b) ^ (((b) >> 3) & 0x70))

__device__ __forceinline__ void cp_async16(uint32_t dst, const void* src) {
    asm volatile("cp.async.cg.shared.global [%0], [%1], 16;" :: "r"(dst), "l"(src) : "memory");
}
__device__ __forceinline__ void cp_commit() {
    asm volatile("cp.async.commit_group;" ::: "memory");
}
template <int N> __device__ __forceinline__ void cp_wait() {
    asm volatile("cp.async.wait_group %0;" :: "n"(N) : "memory");
}

__device__ __forceinline__ void ldm_x4(uint32_t* r, uint32_t addr) {
    asm volatile("ldmatrix.sync.aligned.m8n8.x4.shared.b16 {%0,%1,%2,%3}, [%4];"
                 : "=r"(r[0]), "=r"(r[1]), "=r"(r[2]), "=r"(r[3]) : "r"(addr));
}
__device__ __forceinline__ void ldm_x4t(uint32_t* r, uint32_t addr) {
    asm volatile("ldmatrix.sync.aligned.m8n8.x4.trans.shared.b16 {%0,%1,%2,%3}, [%4];"
                 : "=r"(r[0]), "=r"(r[1]), "=r"(r[2]), "=r"(r[3]) : "r"(addr));
}
__device__ __forceinline__ void mma_bf16(float* c, const uint32_t* a, const uint32_t* b) {
    asm volatile("mma.sync.aligned.m16n8k16.row.col.f32.bf16.bf16.f32 "
                 "{%0,%1,%2,%3}, {%4,%5,%6,%7}, {%8,%9}, {%0,%1,%2,%3};"
                 : "+f"(c[0]), "+f"(c[1]), "+f"(c[2]), "+f"(c[3])
                 : "r"(a[0]), "r"(a[1]), "r"(a[2]), "r"(a[3]), "r"(b[0]), "r"(b[1]));
}
__device__ __forceinline__ float fexp2(float x) {
    float y; asm("ex2.approx.ftz.f32 %0, %1;" : "=f"(y) : "f"(x)); return y;
}
__device__ __forceinline__ uint32_t packbf(__nv_bfloat16 a, __nv_bfloat16 b) {
    __nv_bfloat162 t(a, b);
    return *(uint32_t*)&t;
}

// ---------------------------------------------------------------------------
// f32 -> split bf16 (hi + lo)   (hidden states only)
// ---------------------------------------------------------------------------
__global__ void split_kernel(const float* __restrict__ X,
                             __nv_bfloat16* __restrict__ hi,
                             __nv_bfloat16* __restrict__ lo, int n4)
{
    int i = blockIdx.x * blockDim.x + threadIdx.x;
    if (i >= n4) return;
    float4 x = ((const float4*)X)[i];
    float v[4] = { x.x, x.y, x.z, x.w };
    __nv_bfloat16 h[4], l[4];
    #pragma unroll
    for (int j = 0; j < 4; j++) {
        h[j] = __float2bfloat16(v[j]);
        l[j] = __float2bfloat16(v[j] - __bfloat162float(h[j]));
    }
    __nv_bfloat162* H = (__nv_bfloat162*)hi;
    __nv_bfloat162* L = (__nv_bfloat162*)lo;
    H[2*i]   = __nv_bfloat162(h[0], h[1]);
    H[2*i+1] = __nv_bfloat162(h[2], h[3]);
    L[2*i]   = __nv_bfloat162(l[0], l[1]);
    L[2*i+1] = __nv_bfloat162(l[2], l[3]);
}

// All 4 weight transposes in one launch: W [K=3584][N] f32 -> T [N][K] bf16 hi/lo
__global__ void transpose_split_all(const float* __restrict__ Wq,
                                    const float* __restrict__ Wk,
                                    const float* __restrict__ Wv,
                                    const float* __restrict__ Wo,
                                    __nv_bfloat16* __restrict__ qhi, __nv_bfloat16* __restrict__ qlo,
                                    __nv_bfloat16* __restrict__ khi, __nv_bfloat16* __restrict__ klo,
                                    __nv_bfloat16* __restrict__ vhi, __nv_bfloat16* __restrict__ vlo,
                                    __nv_bfloat16* __restrict__ ohi, __nv_bfloat16* __restrict__ olo)
{
    const int z = blockIdx.z;
    const float* W; __nv_bfloat16 *Thi, *Tlo; int N;
    if      (z == 0) { W = Wq; Thi = qhi; Tlo = qlo; N = HID; }
    else if (z == 1) { W = Wk; Thi = khi; Tlo = klo; N = NKV*HDIM; }
    else if (z == 2) { W = Wv; Thi = vhi; Tlo = vlo; N = NKV*HDIM; }
    else             { W = Wo; Thi = ohi; Tlo = olo; N = HID; }
    if (blockIdx.x * 32 >= N) return;

    __shared__ float t[32][33];
    int n0 = blockIdx.x * 32, k0 = blockIdx.y * 32;
    int tx = threadIdx.x, ty = threadIdx.y;
    #pragma unroll
    for (int r = 0; r < 4; r++)
        t[ty + r*8][tx] = W[(size_t)(k0 + ty + r*8) * N + n0 + tx];
    __syncthreads();
    #pragma unroll
    for (int r = 0; r < 4; r++) {
        int n = n0 + ty + r*8;
        float v = t[tx][ty + r*8];
        __nv_bfloat16 h = __float2bfloat16(v);
        __nv_bfloat16 l = __float2bfloat16(v - __bfloat162float(h));
        Thi[(size_t)n * HID + k0 + tx] = h;
        Tlo[(size_t)n * HID + k0 + tx] = l;
    }
}

// Pack KV cache rows only (new rows written by rope_pack): y=0 K-cache, y=1 V-cache
__global__ void pack_kv_kernel(const float* __restrict__ kcache,
                               const float* __restrict__ vcache,
                               __nv_bfloat16* __restrict__ khi,
                               __nv_bfloat16* __restrict__ klo,
                               __nv_bfloat16* __restrict__ vhi,
                               __nv_bfloat16* __restrict__ vlo)
{
    int i = blockIdx.x * blockDim.x + threadIdx.x;
    if (i >= NKV * PASTLEN * 32) return;
    const float* cache = blockIdx.y ? vcache : kcache;
    __nv_bfloat16* hi = blockIdx.y ? vhi : khi;
    __nv_bfloat16* lo = blockIdx.y ? vlo : klo;
    int kvh = i / (PASTLEN * 32);
    int rem = i % (PASTLEN * 32);
    int pos = rem >> 5;
    int d4  = (rem & 31) * 4;
    float4 v = *(const float4*)(cache + ((size_t)(kvh * PASTLEN + pos) * HDIM + d4));
    float a[4] = { v.x, v.y, v.z, v.w };
    __nv_bfloat16 h[4], l[4];
    #pragma unroll
    for (int j = 0; j < 4; j++) {
        h[j] = __float2bfloat16(a[j]);
        l[j] = __float2bfloat16(a[j] - __bfloat162float(h[j]));
    }
    size_t o = ((size_t)(kvh * KVTOT + pos) * HDIM + d4) >> 1;
    ((__nv_bfloat162*)hi)[o]     = __nv_bfloat162(h[0], h[1]);
    ((__nv_bfloat162*)hi)[o + 1] = __nv_bfloat162(h[2], h[3]);
    ((__nv_bfloat162*)lo)[o]     = __nv_bfloat162(l[0], l[1]);
    ((__nv_bfloat162*)lo)[o + 1] = __nv_bfloat162(l[2], l[3]);
}

// ---------------------------------------------------------------------------
// mma.sync split-precision GEMM core v2.
// CTA tile 128x128, 4 warps (128 threads) of 64x64 each -> halved smem frag
// re-reads (smem-BW bound). K-stage = 128 (2 panels of 64), 3 stages, single
// sync per stage. 3 precision passes (AhiBhi + AhiBlo + AloBhi).
// ---------------------------------------------------------------------------
#define MM_STAGES      3
#define MM_STAGE_BYTES 65536            // A 32KB (2 panels) + B 32KB
#define MM_SMEM        (1024 + MM_STAGES * MM_STAGE_BYTES)

__device__ __forceinline__ void mm_tile(
    const __nv_bfloat16* __restrict__ Ahi, const __nv_bfloat16* __restrict__ Alo,
    const __nv_bfloat16* __restrict__ Bhi, const __nv_bfloat16* __restrict__ Blo,
    const float* __restrict__ bias, float* __restrict__ C, int ldc,
    int m0, int n0, int kbase, int segst, char* smem)
{
    const uint32_t sb   = smem_to_u32(smem);
    const uint32_t DATA = (sb + 1023u) & ~1023u;
    const int tid = threadIdx.x, wid = tid >> 5, lane = tid & 31;
    const int wm = (wid & 1) * 64;
    const int wn = (wid >> 1) * 64;
    const int NST = 3 * segst;

    // loader precompute: thread covers chunks tid + i*128, i in [0,16)
    // chunk c: row = c>>4, k elems (c&15)*8, panel = (c>>3)&1
    uint32_t sw4[4]; int gr4[4], gc4[4];
    #pragma unroll
    for (int i = 0; i < 4; i++) {
        int c = tid + i * 128;
        gr4[i] = c >> 4;                 // 0..31
        gc4[i] = (c & 15) * 8;
        sw4[i] = (uint32_t)(((c >> 3) & 1) * 16384)
               + SMEM_SWIZZLE_128B((uint32_t)((c >> 4) * 128 + (c & 7) * 16));
    }

    auto load_stage = [&](int g) {
        int seg = g / segst, kk = kbase + (g % segst) * 128;
        const __nv_bfloat16* A = (seg == 2) ? Alo : Ahi;
        const __nv_bfloat16* B = (seg == 1) ? Blo : Bhi;
        uint32_t ab = DATA + (uint32_t)(g % 3) * MM_STAGE_BYTES;
        uint32_t bb = ab + 32768;
        #pragma unroll
        for (int i = 0; i < 16; i++) {
            int j = i & 3, ext = i >> 2;
            uint32_t sw = sw4[j] + (uint32_t)ext * 4096;       // +32 rows
            size_t go = (size_t)(gr4[j] + ext * 32);
            cp_async16(ab + sw, A + (size_t)(m0 + go) * HID + kk + gc4[j]);
            cp_async16(bb + sw, B + (size_t)(n0 + go) * HID + kk + gc4[j]);
        }
        cp_commit();
    };

    float acc[4][8][4];
    #pragma unroll
    for (int a = 0; a < 4; a++)
        #pragma unroll
        for (int b = 0; b < 8; b++)
            #pragma unroll
            for (int c = 0; c < 4; c++) acc[a][b][c] = 0.0f;

    const int a_row = wm + (lane & 15);
    const int a_kb  = (lane >> 4) * 16;
    const int b_row = wn + ((lane >> 4) & 1) * 8 + (lane & 7);
    const int b_kb  = ((lane >> 3) & 1) * 16;

    load_stage(0); load_stage(1);

    for (int g = 0; g < NST; g++) {
        if (g < NST - 1) cp_wait<1>();
        else             cp_wait<0>();
        __syncthreads();                 // stage g ready; all warps done stage g-1
        if (g + 2 < NST) load_stage(g + 2);

        uint32_t ab = DATA + (uint32_t)(g % 3) * MM_STAGE_BYTES;
        uint32_t bb = ab + 32768;

        #pragma unroll
        for (int ks = 0; ks < 8; ks++) {
            uint32_t pa = ab + (uint32_t)((ks >> 2) * 16384);
            uint32_t pb = bb + (uint32_t)((ks >> 2) * 16384);
            int kin = (ks & 3) * 32;
            uint32_t aF[4][4];
            #pragma unroll
            for (int mi = 0; mi < 4; mi++) {
                uint32_t byte = (uint32_t)((a_row + mi * 16) * 128 + kin + a_kb);
                ldm_x4(aF[mi], pa + SMEM_SWIZZLE_128B(byte));
            }
            uint32_t bF[8][2];
            #pragma unroll
            for (int nb = 0; nb < 4; nb++) {
                uint32_t byte = (uint32_t)((b_row + nb * 16) * 128 + kin + b_kb);
                uint32_t r[4];
                ldm_x4(r, pb + SMEM_SWIZZLE_128B(byte));
                bF[nb*2+0][0] = r[0]; bF[nb*2+0][1] = r[1];
                bF[nb*2+1][0] = r[2]; bF[nb*2+1][1] = r[3];
            }
            #pragma unroll
            for (int mi = 0; mi < 4; mi++)
                #pragma unroll
                for (int ni = 0; ni < 8; ni++)
                    mma_bf16(acc[mi][ni], aF[mi], bF[ni]);
        }
    }

    const int group = lane >> 2, tig = lane & 3;
    #pragma unroll
    for (int mi = 0; mi < 4; mi++) {
        #pragma unroll
        for (int ni = 0; ni < 8; ni++) {
            int r0 = m0 + wm + mi * 16 + group;
            int c0 = n0 + wn + ni * 8 + tig * 2;
            float b0 = 0.f, b1 = 0.f;
            if (bias) { b0 = bias[c0]; b1 = bias[c0 + 1]; }
            float2 v0 = make_float2(acc[mi][ni][0] + b0, acc[mi][ni][1] + b1);
            float2 v1 = make_float2(acc[mi][ni][2] + b0, acc[mi][ni][3] + b1);
            *(float2*)(C + (size_t)r0 * ldc + c0)       = v0;
            *(float2*)(C + (size_t)(r0 + 8) * ldc + c0) = v1;
        }
    }
}

// Fused QKV projection: grid (36, 8), 128 threads
__global__ __launch_bounds__(128)
void qkv_mm_kernel(const __nv_bfloat16* __restrict__ Ahi, const __nv_bfloat16* __restrict__ Alo,
                   const __nv_bfloat16* __restrict__ qHi, const __nv_bfloat16* __restrict__ qLo,
                   const __nv_bfloat16* __restrict__ kHi, const __nv_bfloat16* __restrict__ kLo,
                   const __nv_bfloat16* __restrict__ vHi, const __nv_bfloat16* __restrict__ vLo,
                   const float* __restrict__ bq, const float* __restrict__ bk,
                   const float* __restrict__ bv,
                   float* __restrict__ gQ, float* __restrict__ gK, float* __restrict__ gV)
{
    extern __shared__ char smem[];
    const int bx = blockIdx.x, m0 = blockIdx.y * 128;
    if (bx < 28)
        mm_tile(Ahi, Alo, qHi, qLo, bq, gQ, HID, m0, bx * 128, 0, 28, smem);
    else if (bx < 32)
        mm_tile(Ahi, Alo, kHi, kLo, bk, gK, NKV*HDIM, m0, (bx - 28) * 128, 0, 28, smem);
    else
        mm_tile(Ahi, Alo, vHi, vLo, bv, gV, NKV*HDIM, m0, (bx - 32) * 128, 0, 28, smem);
}

// Output projection, split-K x2: grid (28, 8, 2) -> partial buffers
__global__ __launch_bounds__(128)
void oproj_kernel(const __nv_bfloat16* __restrict__ Ahi, const __nv_bfloat16* __restrict__ Alo,
                  const __nv_bfloat16* __restrict__ Bhi, const __nv_bfloat16* __restrict__ Blo,
                  float* __restrict__ P)
{
    extern __shared__ char smem[];
    const int z = blockIdx.z;
    mm_tile(Ahi, Alo, Bhi, Blo, nullptr, P + (size_t)z * QLEN * HID, HID,
            blockIdx.y * 128, blockIdx.x * 128, z * 1792, 14, smem);
}

// Sum the two split-K partials -> final output
__global__ void addout_kernel(const float* __restrict__ P, float* __restrict__ out)
{
    int i = blockIdx.x * blockDim.x + threadIdx.x;
    if (i >= QLEN * HID / 4) return;
    float4 a = ((const float4*)P)[i];
    float4 b = ((const float4*)(P + (size_t)QLEN * HID))[i];
    ((float4*)out)[i] = make_float4(a.x + b.x, a.y + b.y, a.z + b.z, a.w + b.w);
}

// ---------------------------------------------------------------------------
// RoPE + split-bf16 packing. y=0: Q rows; y=1: K rows (-> Kb rows PASTLEN+q);
// y=2: V new rows (no rope, just split-pack into Vb).
// inv_freq/sincos hoisted to a per-block smem table (identical powf math).
// ---------------------------------------------------------------------------
__global__ void rope_pack_kernel(const float* __restrict__ gQ, const float* __restrict__ gK,
                                 const float* __restrict__ gV, const int* __restrict__ pos,
                                 __nv_bfloat16* __restrict__ QbH, __nv_bfloat16* __restrict__ QbL,
                                 __nv_bfloat16* __restrict__ KbH, __nv_bfloat16* __restrict__ KbL,
                                 __nv_bfloat16* __restrict__ VbH, __nv_bfloat16* __restrict__ VbL)
{
    const int q = blockIdx.x;
    const int mode = blockIdx.y;

    if (mode == 2) {           // V new rows
        for (int t = threadIdx.x; t < NKV * HDIM; t += blockDim.x) {
            int kvh = t >> 7, d = t & 127;
            float v = gV[(size_t)q * (NKV*HDIM) + t];
            __nv_bfloat16 h = __float2bfloat16(v);
            __nv_bfloat16 l = __float2bfloat16(v - __bfloat162float(h));
            size_t dd = ((size_t)kvh * KVTOT + PASTLEN + q) * HDIM + d;
            VbH[dd] = h; VbL[dd] = l;
        }
        return;
    }

    __shared__ float cs[64], sn[64];
    const float p = (float)pos[q];
    if (threadIdx.x < 64) {
        float e = (float)threadIdx.x * (1.0f / 64.0f);
        float invf = 1.0f / powf(1000000.0f, e);
        sincosf(p * invf, &sn[threadIdx.x], &cs[threadIdx.x]);
    }
    __syncthreads();

    const int isK = mode;
    const int nh = isK ? NKV : NHEADS;
    const float* src = isK ? (gK + (size_t)q * (NKV*HDIM)) : (gQ + (size_t)q * HID);

    for (int t = threadIdx.x; t < nh * 64; t += blockDim.x) {
        int hh = t >> 6, i = t & 63;
        float s = sn[i], c = cs[i];
        const float* base = src + hh * HDIM;
        float x1 = base[i];
        float x2 = base[i + 64];
        float o1 = x1 * c - x2 * s;
        float o2 = x2 * c + x1 * s;
        __nv_bfloat16 h1 = __float2bfloat16(o1);
        __nv_bfloat16 l1 = __float2bfloat16(o1 - __bfloat162float(h1));
        __nv_bfloat16 h2 = __float2bfloat16(o2);
        __nv_bfloat16 l2 = __float2bfloat16(o2 - __bfloat162float(h2));
        size_t d1, d2;
        if (isK) {
            size_t row = (size_t)hh * KVTOT + PASTLEN + q;
            d1 = row * HDIM + i; d2 = d1 + 64;
            KbH[d1] = h1; KbL[d1] = l1;
            KbH[d2] = h2; KbL[d2] = l2;
        } else {
            d1 = (size_t)q * HID + hh * HDIM + i; d2 = d1 + 64;
            QbH[d1] = h1; QbL[d1] = l1;
            QbH[d2] = h2; QbL[d2] = l2;
        }
    }
}

// ---------------------------------------------------------------------------
// Tensorized flash attention, 2-way KV split, single-sync pipeline.
// grid (8 q-tiles, 28 heads, 2 kv-splits), 256 threads = 8 warps x 16 q-rows.
// ---------------------------------------------------------------------------
#define FL_SMEM (65536 * 3)

__global__ __launch_bounds__(256, 1)
void flash_mma_kernel(const __nv_bfloat16* __restrict__ Qhi,
                      const __nv_bfloat16* __restrict__ Qlo,
                      const __nv_bfloat16* __restrict__ Kbh,
                      const __nv_bfloat16* __restrict__ Kbl,
                      const __nv_bfloat16* __restrict__ Vbh,
                      const __nv_bfloat16* __restrict__ Vbl,
                      float* __restrict__ Op, float* __restrict__ Ml)
{
    extern __shared__ char smraw[];
    const uint32_t sb = smem_to_u32(smraw);
    const int tid = threadIdx.x, wid = tid >> 5, lane = tid & 31;
    const int qt = blockIdx.x, h = blockIdx.y, z = blockIdx.z;
    const int kvh = h / NREP;
    const int q0 = qt * 128;
    const int w16 = wid * 16;
    const int nt = 50 + 2 * qt;
    const int t0 = z ? (nt >> 1) : 0;
    const int t1 = z ? nt : (nt >> 1);

    // ---- Q tile load (once) ----
    #pragma unroll
    for (int i = 0; i < 16; i++) {
        int cg = tid + i * 256;
        int comp = i >> 3;
        int c = cg & 2047;
        int row = c >> 4, d8 = (c & 15) * 8;
        uint32_t dst = sb + (uint32_t)comp * 32768 + (uint32_t)((c >> 3) & 1) * 16384
                     + SMEM_SWIZZLE_128B((uint32_t)(row * 128 + (c & 7) * 16));
        const __nv_bfloat16* src = (comp ? Qlo : Qhi);
        cp_async16(dst, src + (size_t)(q0 + row) * HID + h * HDIM + d8);
    }
    cp_commit();

    auto load_stage = [&](int t) {
        uint32_t base = sb + 65536u + (uint32_t)(t & 1) * 65536u;
        int kvbase = t * 64;
        #pragma unroll
        for (int i = 0; i < 16; i++) {
            int comp = i >> 2;
            int c = (tid + i * 256) & 1023;
            int kv = c >> 4, d8 = (c & 15) * 8;
            uint32_t dst = base + (uint32_t)comp * 16384 + (uint32_t)((c >> 3) & 1) * 8192
                         + SMEM_SWIZZLE_128B((uint32_t)(kv * 128 + (c & 7) * 16));
            const __nv_bfloat16* src =
                (comp == 0) ? Kbh : (comp == 1) ? Kbl : (comp == 2) ? Vbh : Vbl;
            cp_async16(dst, src + ((size_t)(kvh * KVTOT + kvbase + kv) * HDIM + d8));
        }
        cp_commit();
    };

    load_stage(t0);

    float Oacc[16][4];
    #pragma unroll
    for (int i = 0; i < 16; i++)
        #pragma unroll
        for (int j = 0; j < 4; j++) Oacc[i][j] = 0.0f;
    float m0 = -INFINITY, m1 = -INFINITY, l0 = 0.0f, l1 = 0.0f;

    const float SL = 0.08838834764831845f * 1.4426950408889634f;
    const int r0 = lane >> 2;

    for (int t = t0; t < t1; t++) {
        cp_wait<0>();
        __syncthreads();
        if (t + 1 < t1) load_stage(t + 1);

        const uint32_t stage = sb + 65536u + (uint32_t)(t & 1) * 65536u;
        const int kvbase = t * 64;

        // ---- S = Q K^T (3-pass split) ----
        float S[8][4];
        #pragma unroll
        for (int i = 0; i < 8; i++)
            #pragma unroll
            for (int j = 0; j < 4; j++) S[i][j] = 0.0f;

        #pragma unroll
        for (int kc = 0; kc < 8; kc++) {
            uint32_t qh[4], ql[4];
            uint32_t qoff = (uint32_t)((w16 + (lane & 15)) * 128 + (kc & 3) * 32 + (lane >> 4) * 16);
            uint32_t qa = sb + (uint32_t)(kc >> 2) * 16384 + SMEM_SWIZZLE_128B(qoff);
            ldm_x4(qh, qa);
            ldm_x4(ql, qa + 32768);
            uint32_t kcol = (uint32_t)((kc & 3) * 32 + ((lane >> 3) & 1) * 16);
            #pragma unroll
            for (int np = 0; np < 4; np++) {
                uint32_t koff = (uint32_t)((np * 16 + ((lane >> 4) & 1) * 8 + (lane & 7)) * 128) + kcol;
                uint32_t ka = stage + (uint32_t)(kc >> 2) * 8192 + SMEM_SWIZZLE_128B(koff);
                uint32_t kh[4], kl[4];
                ldm_x4(kh, ka);
                ldm_x4(kl, ka + 16384);
                mma_bf16(S[2*np],   qh, kh);     mma_bf16(S[2*np],   ql, kh);
                mma_bf16(S[2*np],   qh, kl);
                mma_bf16(S[2*np+1], qh, kh + 2); mma_bf16(S[2*np+1], ql, kh + 2);
                mma_bf16(S[2*np+1], qh, kl + 2);
            }
        }

        // ---- causal mask (last two global tiles; z=1 only) ----
        if (t >= nt - 2) {
            const int lim0 = PASTLEN + q0 + w16 + r0;
            const int lim1 = lim0 + 8;
            #pragma unroll
            for (int nc = 0; nc < 8; nc++) {
                int col = kvbase + nc * 8 + (lane & 3) * 2;
                if (col     > lim0) S[nc][0] = -1e30f;
                if (col + 1 > lim0) S[nc][1] = -1e30f;
                if (col     > lim1) S[nc][2] = -1e30f;
                if (col + 1 > lim1) S[nc][3] = -1e30f;
            }
        }

        // ---- online softmax ----
        float mx0 = -INFINITY, mx1 = -INFINITY;
        #pragma unroll
        for (int nc = 0; nc < 8; nc++) {
            mx0 = fmaxf(mx0, fmaxf(S[nc][0], S[nc][1]));
            mx1 = fmaxf(mx1, fmaxf(S[nc][2], S[nc][3]));
        }
        mx0 = fmaxf(mx0, __shfl_xor_sync(0xffffffffu, mx0, 1));
        mx0 = fmaxf(mx0, __shfl_xor_sync(0xffffffffu, mx0, 2));
        mx1 = fmaxf(mx1, __shfl_xor_sync(0xffffffffu, mx1, 1));
        mx1 = fmaxf(mx1, __shfl_xor_sync(0xffffffffu, mx1, 2));
        float mn0 = fmaxf(m0, mx0 * SL);
        float mn1 = fmaxf(m1, mx1 * SL);
        float cor0 = fexp2(m0 - mn0);
        float cor1 = fexp2(m1 - mn1);
        m0 = mn0; m1 = mn1;

        uint32_t pH[8][2], pL[8][2];
        float rs0 = 0.0f, rs1 = 0.0f;
        #pragma unroll
        for (int nc = 0; nc < 8; nc++) {
            float p0 = fexp2(S[nc][0] * SL - mn0);
            float p1 = fexp2(S[nc][1] * SL - mn0);
            float p2 = fexp2(S[nc][2] * SL - mn1);
            float p3 = fexp2(S[nc][3] * SL - mn1);
            rs0 += p0 + p1;  rs1 += p2 + p3;
            __nv_bfloat16 h0 = __float2bfloat16(p0), h1 = __float2bfloat16(p1);
            __nv_bfloat16 h2 = __float2bfloat16(p2), h3 = __float2bfloat16(p3);
            pH[nc][0] = packbf(h0, h1);
            pH[nc][1] = packbf(h2, h3);
            pL[nc][0] = packbf(__float2bfloat16(p0 - __bfloat162float(h0)),
                               __float2bfloat16(p1 - __bfloat162float(h1)));
            pL[nc][1] = packbf(__float2bfloat16(p2 - __bfloat162float(h2)),
                               __float2bfloat16(p3 - __bfloat162float(h3)));
        }
        rs0 += __shfl_xor_sync(0xffffffffu, rs0, 1);
        rs0 += __shfl_xor_sync(0xffffffffu, rs0, 2);
        rs1 += __shfl_xor_sync(0xffffffffu, rs1, 1);
        rs1 += __shfl_xor_sync(0xffffffffu, rs1, 2);
        l0 = l0 * cor0 + rs0;
        l1 = l1 * cor1 + rs1;

        #pragma unroll
        for (int nc = 0; nc < 16; nc++) {
            Oacc[nc][0] *= cor0; Oacc[nc][1] *= cor0;
            Oacc[nc][2] *= cor1; Oacc[nc][3] *= cor1;
        }

        // ---- O += P V (3-pass split) ----
        #pragma unroll
        for (int kc = 0; kc < 4; kc++) {
            uint32_t aH[4] = { pH[2*kc][0], pH[2*kc][1], pH[2*kc+1][0], pH[2*kc+1][1] };
            uint32_t aL[4] = { pL[2*kc][0], pL[2*kc][1], pL[2*kc+1][0], pL[2*kc+1][1] };
            uint32_t vrow = (uint32_t)(kc * 16 + ((lane >> 3) & 1) * 8 + (lane & 7));
            #pragma unroll
            for (int dp = 0; dp < 8; dp++) {
                uint32_t voff = vrow * 128 + (uint32_t)((dp & 3) * 32 + ((lane >> 4) & 1) * 16);
                uint32_t va = stage + 32768u + (uint32_t)(dp >> 2) * 8192 + SMEM_SWIZZLE_128B(voff);
                uint32_t vh[4], vl[4];
                ldm_x4t(vh, va);
                ldm_x4t(vl, va + 16384);
                mma_bf16(Oacc[2*dp],   aH, vh);     mma_bf16(Oacc[2*dp],   aL, vh);
                mma_bf16(Oacc[2*dp],   aH, vl);
                mma_bf16(Oacc[2*dp+1], aH, vh + 2); mma_bf16(Oacc[2*dp+1], aL, vh + 2);
                mma_bf16(Oacc[2*dp+1], aH, vl + 2);
            }
        }
    }

    // ---- epilogue: write raw partials ----
    const int rowa = q0 + w16 + r0;
    const size_t pb = ((size_t)(z * NHEADS + h) * QLEN);
    #pragma unroll
    for (int nc = 0; nc < 16; nc++) {
        int col = nc * 8 + (lane & 3) * 2;
        *(float2*)(Op + (pb + rowa) * HDIM + col) =
            make_float2(Oacc[nc][0], Oacc[nc][1]);
        *(float2*)(Op + (pb + rowa + 8) * HDIM + col) =
            make_float2(Oacc[nc][2], Oacc[nc][3]);
    }
    if ((lane & 3) == 0) {
        Ml[(pb + rowa) * 2]     = m0;
        Ml[(pb + rowa) * 2 + 1] = l0;
        Ml[(pb + rowa + 8) * 2]     = m1;
        Ml[(pb + rowa + 8) * 2 + 1] = l1;
    }
}

// Merge the two KV-split partials -> split-bf16 attention output (oproj A operand)
__global__ void combine_split_kernel(const float* __restrict__ Op,
                                     const float* __restrict__ Ml,
                                     __nv_bfloat16* __restrict__ aHi,
                                     __nv_bfloat16* __restrict__ aLo)
{
    int i = blockIdx.x * blockDim.x + threadIdx.x;
    if (i >= NHEADS * QLEN * (HDIM / 4)) return;
    int hq = i >> 5;
    int d4 = (i & 31) * 4;
    int h = hq >> 10, q = hq & 1023;
    size_t p0 = (size_t)h * QLEN + q;
    size_t p1 = (size_t)(NHEADS + h) * QLEN + q;
    float m0 = Ml[p0 * 2], l0 = Ml[p0 * 2 + 1];
    float m1 = Ml[p1 * 2], l1 = Ml[p1 * 2 + 1];
    float m = fmaxf(m0, m1);
    float s0 = fexp2(m0 - m), s1 = fexp2(m1 - m);
    float inv = 1.0f / (l0 * s0 + l1 * s1);
    s0 *= inv; s1 *= inv;
    float4 a = *(const float4*)(Op + p0 * HDIM + d4);
    float4 b = *(const float4*)(Op + p1 * HDIM + d4);
    float o[4] = { a.x * s0 + b.x * s1, a.y * s0 + b.y * s1,
                   a.z * s0 + b.z * s1, a.w * s0 + b.w * s1 };
    __nv_bfloat16 h4[4], l4[4];
    #pragma unroll
    for (int j = 0; j < 4; j++) {
        h4[j] = __float2bfloat16(o[j]);
        l4[j] = __float2bfloat16(o[j] - __bfloat162float(h4[j]));
    }
    size_t od = ((size_t)q * HID + h * HDIM + d4) >> 1;
    ((__nv_bfloat162*)aHi)[od]     = __nv_bfloat162(h4[0], h4[1]);
    ((__nv_bfloat162*)aHi)[od + 1] = __nv_bfloat162(h4[2], h4[3]);
    ((__nv_bfloat162*)aLo)[od]     = __nv_bfloat162(l4[0], l4[1]);
    ((__nv_bfloat162*)aLo)[od + 1] = __nv_bfloat162(l4[2], l4[3]);
}

// ---------------------------------------------------------------------------
// Launch
// ---------------------------------------------------------------------------
extern "C" void kernel_launch(void* const* d_in, const int* in_sizes, int n_in,
                              void* d_out, int out_size)
{
    const float* hid = (const float*)d_in[0];
    const float* kc  = (const float*)d_in[1];
    const float* vc  = (const float*)d_in[2];
    const float* Wq  = (const float*)d_in[3];
    const float* bq  = (const float*)d_in[4];
    const float* Wk  = (const float*)d_in[5];
    const float* bk  = (const float*)d_in[6];
    const float* Wv  = (const float*)d_in[7];
    const float* bv  = (const float*)d_in[8];
    const float* Wo  = (const float*)d_in[9];
    const int*   pos = (const int*)d_in[10];
    float* out = (float*)d_out;

    float *gQ, *gK, *gV, *gOp, *gMl;
    cudaGetSymbolAddress((void**)&gQ, g_Q);
    cudaGetSymbolAddress((void**)&gK, g_K);
    cudaGetSymbolAddress((void**)&gV, g_V);
    cudaGetSymbolAddress((void**)&gOp, g_Op);
    cudaGetSymbolAddress((void**)&gMl, g_Ml);
    __nv_bfloat16 *hHi, *hLo, *aHi, *aLo;
    __nv_bfloat16 *qHi, *qLo, *kHi, *kLo, *vHi, *vLo, *oHi, *oLo;
    __nv_bfloat16 *QbH, *QbL, *KbH, *KbL, *VbH, *VbL;
    cudaGetSymbolAddress((void**)&hHi, g_hid_hi);
    cudaGetSymbolAddress((void**)&hLo, g_hid_lo);
    cudaGetSymbolAddress((void**)&aHi, g_att_hi);
    cudaGetSymbolAddress((void**)&aLo, g_att_lo);
    cudaGetSymbolAddress((void**)&qHi, g_WqT_hi);
    cudaGetSymbolAddress((void**)&qLo, g_WqT_lo);
    cudaGetSymbolAddress((void**)&kHi, g_WkT_hi);
    cudaGetSymbolAddress((void**)&kLo, g_WkT_lo);
    cudaGetSymbolAddress((void**)&vHi, g_WvT_hi);
    cudaGetSymbolAddress((void**)&vLo, g_WvT_lo);
    cudaGetSymbolAddress((void**)&oHi, g_WoT_hi);
    cudaGetSymbolAddress((void**)&oLo, g_WoT_lo);
    cudaGetSymbolAddress((void**)&QbH, g_Qb_hi);
    cudaGetSymbolAddress((void**)&QbL, g_Qb_lo);
    cudaGetSymbolAddress((void**)&KbH, g_Kb_hi);
    cudaGetSymbolAddress((void**)&KbL, g_Kb_lo);
    cudaGetSymbolAddress((void**)&VbH, g_Vb_hi);
    cudaGetSymbolAddress((void**)&VbL, g_Vb_lo);

    cudaFuncSetAttribute(qkv_mm_kernel, cudaFuncAttributeMaxDynamicSharedMemorySize, MM_SMEM);
    cudaFuncSetAttribute(oproj_kernel, cudaFuncAttributeMaxDynamicSharedMemorySize, MM_SMEM);
    cudaFuncSetAttribute(flash_mma_kernel, cudaFuncAttributeMaxDynamicSharedMemorySize, FL_SMEM);

    // 1. operand preparation (all independent of each other)
    const int n4 = QLEN * HID / 4;
    split_kernel<<<(n4 + 255) / 256, 256>>>(hid, hHi, hLo, n4);
    transpose_split_all<<<dim3(112, 112, 4), dim3(32, 8)>>>(
        Wq, Wk, Wv, Wo, qHi, qLo, kHi, kLo, vHi, vLo, oHi, oLo);
    pack_kv_kernel<<<dim3((NKV * PASTLEN * 32 + 255) / 256, 2), 256>>>(
        kc, vc, KbH, KbL, VbH, VbL);

    // 2. fused QKV projections (4-warp 64x64 tiles)
    qkv_mm_kernel<<<dim3(36, 8), 128, MM_SMEM>>>(hHi, hLo, qHi, qLo, kHi, kLo, vHi, vLo,
                                                 bq, bk, bv, gQ, gK, gV);

    // 3. RoPE + split packing of Q, new-K, new-V
    rope_pack_kernel<<<dim3(QLEN, 3), 256>>>(gQ, gK, gV, pos, QbH, QbL, KbH, KbL, VbH, VbL);

    // 4. attention (tensorized, 2-way KV split) + combine-with-split
    flash_mma_kernel<<<dim3(8, 28, 2), 256, FL_SMEM>>>(QbH, QbL, KbH, KbL, VbH, VbL, gOp, gMl);
    const int cn = NHEADS * QLEN * (HDIM / 4);
    combine_split_kernel<<<(cn + 255) / 256, 256>>>(gOp, gMl, aHi, aLo);

    // 5. output projection (split-K x2 into partials, then add)
    oproj_kernel<<<dim3(28, 8, 2), 128, MM_SMEM>>>(aHi, aLo, oHi, oLo, gOp);
    addout_kernel<<<(n4 + 255) / 256, 256>>>(gOp, out);
}

// round 10
// speedup vs baseline: 5.0424x; 1.0063x over previous
#include <cuda_runtime.h>
#include <cuda_bf16.h>
#include <cstdint>
#include <math.h>

// ---------------------------------------------------------------------------
// Problem constants
// ---------------------------------------------------------------------------
#define QLEN     1024
#define HID      3584
#define NHEADS   28
#define NKV      4
#define HDIM     128
#define PASTLEN  3072
#define KVTOT    4096
#define NREP     7

// ---------------------------------------------------------------------------
// Scratch (device globals)
// ---------------------------------------------------------------------------
__device__ float g_Q[QLEN * HID];               // QKV outputs (pre-rope, f32)
__device__ float g_K[QLEN * (NKV*HDIM)];
__device__ float g_V[QLEN * (NKV*HDIM)];

__device__ __nv_bfloat16 g_hid_hi[QLEN * HID];
__device__ __nv_bfloat16 g_hid_lo[QLEN * HID];
__device__ __nv_bfloat16 g_att_hi[QLEN * HID];
__device__ __nv_bfloat16 g_att_lo[QLEN * HID];
__device__ __nv_bfloat16 g_WqT_hi[HID * HID];
__device__ __nv_bfloat16 g_WqT_lo[HID * HID];
__device__ __nv_bfloat16 g_WkT_hi[(NKV*HDIM) * HID];
__device__ __nv_bfloat16 g_WkT_lo[(NKV*HDIM) * HID];
__device__ __nv_bfloat16 g_WvT_hi[(NKV*HDIM) * HID];
__device__ __nv_bfloat16 g_WvT_lo[(NKV*HDIM) * HID];
__device__ __nv_bfloat16 g_WoT_hi[HID * HID];
__device__ __nv_bfloat16 g_WoT_lo[HID * HID];

// attention operands (split bf16)
__device__ __nv_bfloat16 g_Qb_hi[QLEN * HID];
__device__ __nv_bfloat16 g_Qb_lo[QLEN * HID];
__device__ __nv_bfloat16 g_Kb_hi[NKV * KVTOT * HDIM];
__device__ __nv_bfloat16 g_Kb_lo[NKV * KVTOT * HDIM];
__device__ __nv_bfloat16 g_Vb_hi[NKV * KVTOT * HDIM];
__device__ __nv_bfloat16 g_Vb_lo[NKV * KVTOT * HDIM];

// flash split-KV partials; later reused as oproj split-K partials
__device__ float g_Op[2 * NHEADS * QLEN * HDIM];
__device__ float g_Ml[2 * NHEADS * QLEN * 2];

// ---------------------------------------------------------------------------
// Helpers (plain-sm_103-legal: cp.async + ldmatrix + mma.sync only)
// ---------------------------------------------------------------------------
__device__ __forceinline__ uint32_t smem_to_u32(const void* p) {
    uint32_t a;
    asm("{ .reg .u64 t; cvta.to.shared.u64 t, %1; cvt.u32.u64 %0, t; }" : "=r"(a) : "l"(p));
    return a;
}
#define SMEM_SWIZZLE_128B(b) ((b) ^ (((b) >> 3) & 0x70))

__device__ __forceinline__ void cp_async16(uint32_t dst, const void* src) {
    asm volatile("cp.async.cg.shared.global [%0], [%1], 16;" :: "r"(dst), "l"(src) : "memory");
}
__device__ __forceinline__ void cp_commit() {
    asm volatile("cp.async.commit_group;" ::: "memory");
}
template <int N> __device__ __forceinline__ void cp_wait() {
    asm volatile("cp.async.wait_group %0;" :: "n"(N) : "memory");
}

__device__ __forceinline__ void ldm_x4(uint32_t* r, uint32_t addr) {
    asm volatile("ldmatrix.sync.aligned.m8n8.x4.shared.b16 {%0,%1,%2,%3}, [%4];"
                 : "=r"(r[0]), "=r"(r[1]), "=r"(r[2]), "=r"(r[3]) : "r"(addr));
}
__device__ __forceinline__ void ldm_x4t(uint32_t* r, uint32_t addr) {
    asm volatile("ldmatrix.sync.aligned.m8n8.x4.trans.shared.b16 {%0,%1,%2,%3}, [%4];"
                 : "=r"(r[0]), "=r"(r[1]), "=r"(r[2]), "=r"(r[3]) : "r"(addr));
}
__device__ __forceinline__ void mma_bf16(float* c, const uint32_t* a, const uint32_t* b) {
    asm volatile("mma.sync.aligned.m16n8k16.row.col.f32.bf16.bf16.f32 "
                 "{%0,%1,%2,%3}, {%4,%5,%6,%7}, {%8,%9}, {%0,%1,%2,%3};"
                 : "+f"(c[0]), "+f"(c[1]), "+f"(c[2]), "+f"(c[3])
                 : "r"(a[0]), "r"(a[1]), "r"(a[2]), "r"(a[3]), "r"(b[0]), "r"(b[1]));
}
__device__ __forceinline__ float fexp2(float x) {
    float y; asm("ex2.approx.ftz.f32 %0, %1;" : "=f"(y) : "f"(x)); return y;
}
__device__ __forceinline__ uint32_t packbf(__nv_bfloat16 a, __nv_bfloat16 b) {
    __nv_bfloat162 t(a, b);
    return *(uint32_t*)&t;
}

// ---------------------------------------------------------------------------
// f32 -> split bf16 (hi + lo)   (hidden states only)
// ---------------------------------------------------------------------------
__global__ void split_kernel(const float* __restrict__ X,
                             __nv_bfloat16* __restrict__ hi,
                             __nv_bfloat16* __restrict__ lo, int n4)
{
    int i = blockIdx.x * blockDim.x + threadIdx.x;
    if (i >= n4) return;
    float4 x = ((const float4*)X)[i];
    float v[4] = { x.x, x.y, x.z, x.w };
    __nv_bfloat16 h[4], l[4];
    #pragma unroll
    for (int j = 0; j < 4; j++) {
        h[j] = __float2bfloat16(v[j]);
        l[j] = __float2bfloat16(v[j] - __bfloat162float(h[j]));
    }
    __nv_bfloat162* H = (__nv_bfloat162*)hi;
    __nv_bfloat162* L = (__nv_bfloat162*)lo;
    H[2*i]   = __nv_bfloat162(h[0], h[1]);
    H[2*i+1] = __nv_bfloat162(h[2], h[3]);
    L[2*i]   = __nv_bfloat162(l[0], l[1]);
    L[2*i+1] = __nv_bfloat162(l[2], l[3]);
}

// All 4 weight transposes in one launch: W [K=3584][N] f32 -> T [N][K] bf16 hi/lo
__global__ void transpose_split_all(const float* __restrict__ Wq,
                                    const float* __restrict__ Wk,
                                    const float* __restrict__ Wv,
                                    const float* __restrict__ Wo,
                                    __nv_bfloat16* __restrict__ qhi, __nv_bfloat16* __restrict__ qlo,
                                    __nv_bfloat16* __restrict__ khi, __nv_bfloat16* __restrict__ klo,
                                    __nv_bfloat16* __restrict__ vhi, __nv_bfloat16* __restrict__ vlo,
                                    __nv_bfloat16* __restrict__ ohi, __nv_bfloat16* __restrict__ olo)
{
    const int z = blockIdx.z;
    const float* W; __nv_bfloat16 *Thi, *Tlo; int N;
    if      (z == 0) { W = Wq; Thi = qhi; Tlo = qlo; N = HID; }
    else if (z == 1) { W = Wk; Thi = khi; Tlo = klo; N = NKV*HDIM; }
    else if (z == 2) { W = Wv; Thi = vhi; Tlo = vlo; N = NKV*HDIM; }
    else             { W = Wo; Thi = ohi; Tlo = olo; N = HID; }
    if (blockIdx.x * 32 >= N) return;

    __shared__ float t[32][33];
    int n0 = blockIdx.x * 32, k0 = blockIdx.y * 32;
    int tx = threadIdx.x, ty = threadIdx.y;
    #pragma unroll
    for (int r = 0; r < 4; r++)
        t[ty + r*8][tx] = W[(size_t)(k0 + ty + r*8) * N + n0 + tx];
    __syncthreads();
    #pragma unroll
    for (int r = 0; r < 4; r++) {
        int n = n0 + ty + r*8;
        float v = t[tx][ty + r*8];
        __nv_bfloat16 h = __float2bfloat16(v);
        __nv_bfloat16 l = __float2bfloat16(v - __bfloat162float(h));
        Thi[(size_t)n * HID + k0 + tx] = h;
        Tlo[(size_t)n * HID + k0 + tx] = l;
    }
}

// Pack KV cache rows only (new rows written by rope_pack): y=0 K-cache, y=1 V-cache
__global__ void pack_kv_kernel(const float* __restrict__ kcache,
                               const float* __restrict__ vcache,
                               __nv_bfloat16* __restrict__ khi,
                               __nv_bfloat16* __restrict__ klo,
                               __nv_bfloat16* __restrict__ vhi,
                               __nv_bfloat16* __restrict__ vlo)
{
    int i = blockIdx.x * blockDim.x + threadIdx.x;
    if (i >= NKV * PASTLEN * 32) return;
    const float* cache = blockIdx.y ? vcache : kcache;
    __nv_bfloat16* hi = blockIdx.y ? vhi : khi;
    __nv_bfloat16* lo = blockIdx.y ? vlo : klo;
    int kvh = i / (PASTLEN * 32);
    int rem = i % (PASTLEN * 32);
    int pos = rem >> 5;
    int d4  = (rem & 31) * 4;
    float4 v = *(const float4*)(cache + ((size_t)(kvh * PASTLEN + pos) * HDIM + d4));
    float a[4] = { v.x, v.y, v.z, v.w };
    __nv_bfloat16 h[4], l[4];
    #pragma unroll
    for (int j = 0; j < 4; j++) {
        h[j] = __float2bfloat16(a[j]);
        l[j] = __float2bfloat16(a[j] - __bfloat162float(h[j]));
    }
    size_t o = ((size_t)(kvh * KVTOT + pos) * HDIM + d4) >> 1;
    ((__nv_bfloat162*)hi)[o]     = __nv_bfloat162(h[0], h[1]);
    ((__nv_bfloat162*)hi)[o + 1] = __nv_bfloat162(h[2], h[3]);
    ((__nv_bfloat162*)lo)[o]     = __nv_bfloat162(l[0], l[1]);
    ((__nv_bfloat162*)lo)[o + 1] = __nv_bfloat162(l[2], l[3]);
}

// ---------------------------------------------------------------------------
// mma.sync split-precision GEMM core v3.
// CTA tile 128x128, 4 warps of 64x64. K-stage = 64 (32KB/stage), 3-stage ring
// -> 97KB smem -> 2 CTAs/SM (8 warps) for HMMA latency hiding.
// 3 precision passes (AhiBhi + AhiBlo + AloBhi). Single sync per stage.
// ---------------------------------------------------------------------------
#define MM_STAGES      3
#define MM_STAGE_BYTES 32768            // A 16KB + B 16KB per stage
#define MM_SMEM        (1024 + MM_STAGES * MM_STAGE_BYTES)

__device__ __forceinline__ void mm_tile(
    const __nv_bfloat16* __restrict__ Ahi, const __nv_bfloat16* __restrict__ Alo,
    const __nv_bfloat16* __restrict__ Bhi, const __nv_bfloat16* __restrict__ Blo,
    const float* __restrict__ bias, float* __restrict__ C, int ldc,
    int m0, int n0, int kbase, int segst, char* smem)
{
    const uint32_t sb   = smem_to_u32(smem);
    const uint32_t DATA = (sb + 1023u) & ~1023u;
    const int tid = threadIdx.x, wid = tid >> 5, lane = tid & 31;
    const int wm = (wid & 1) * 64;
    const int wn = (wid >> 1) * 64;
    const int NST = 3 * segst;

    // loader: 1024 16B-chunks per operand, 8 per thread
    uint32_t sw8[8]; int gr8[8], gc8[8];
    #pragma unroll
    for (int i = 0; i < 8; i++) {
        int c = tid + i * 128;
        gr8[i] = c >> 3;                 // row 0..127
        gc8[i] = (c & 7) * 8;            // bf16 col within 64-wide row
        sw8[i] = SMEM_SWIZZLE_128B((uint32_t)((c >> 3) * 128 + (c & 7) * 16));
    }

    auto load_stage = [&](int g) {
        int seg = g / segst, kk = kbase + (g % segst) * 64;
        const __nv_bfloat16* A = (seg == 2) ? Alo : Ahi;
        const __nv_bfloat16* B = (seg == 1) ? Blo : Bhi;
        uint32_t ab = DATA + (uint32_t)(g % 3) * MM_STAGE_BYTES;
        uint32_t bb = ab + 16384;
        #pragma unroll
        for (int i = 0; i < 8; i++) {
            cp_async16(ab + sw8[i], A + (size_t)(m0 + gr8[i]) * HID + kk + gc8[i]);
            cp_async16(bb + sw8[i], B + (size_t)(n0 + gr8[i]) * HID + kk + gc8[i]);
        }
        cp_commit();
    };

    float acc[4][8][4];
    #pragma unroll
    for (int a = 0; a < 4; a++)
        #pragma unroll
        for (int b = 0; b < 8; b++)
            #pragma unroll
            for (int c = 0; c < 4; c++) acc[a][b][c] = 0.0f;

    const int a_row = wm + (lane & 15);
    const int a_kb  = (lane >> 4) * 16;
    const int b_row = wn + ((lane >> 4) & 1) * 8 + (lane & 7);
    const int b_kb  = ((lane >> 3) & 1) * 16;

    load_stage(0); load_stage(1);

    for (int g = 0; g < NST; g++) {
        if (g < NST - 1) cp_wait<1>();
        else             cp_wait<0>();
        __syncthreads();                 // stage g ready; all warps done stage g-1
        if (g + 2 < NST) load_stage(g + 2);

        uint32_t ab = DATA + (uint32_t)(g % 3) * MM_STAGE_BYTES;
        uint32_t bb = ab + 16384;

        #pragma unroll
        for (int ks = 0; ks < 4; ks++) {
            int kin = ks * 32;           // bytes: 16 bf16 per ks
            uint32_t aF[4][4];
            #pragma unroll
            for (int mi = 0; mi < 4; mi++) {
                uint32_t byte = (uint32_t)((a_row + mi * 16) * 128 + kin + a_kb);
                ldm_x4(aF[mi], ab + SMEM_SWIZZLE_128B(byte));
            }
            uint32_t bF[8][2];
            #pragma unroll
            for (int nb = 0; nb < 4; nb++) {
                uint32_t byte = (uint32_t)((b_row + nb * 16) * 128 + kin + b_kb);
                uint32_t r[4];
                ldm_x4(r, bb + SMEM_SWIZZLE_128B(byte));
                bF[nb*2+0][0] = r[0]; bF[nb*2+0][1] = r[1];
                bF[nb*2+1][0] = r[2]; bF[nb*2+1][1] = r[3];
            }
            #pragma unroll
            for (int mi = 0; mi < 4; mi++)
                #pragma unroll
                for (int ni = 0; ni < 8; ni++)
                    mma_bf16(acc[mi][ni], aF[mi], bF[ni]);
        }
    }

    const int group = lane >> 2, tig = lane & 3;
    #pragma unroll
    for (int mi = 0; mi < 4; mi++) {
        #pragma unroll
        for (int ni = 0; ni < 8; ni++) {
            int r0 = m0 + wm + mi * 16 + group;
            int c0 = n0 + wn + ni * 8 + tig * 2;
            float b0 = 0.f, b1 = 0.f;
            if (bias) { b0 = bias[c0]; b1 = bias[c0 + 1]; }
            float2 v0 = make_float2(acc[mi][ni][0] + b0, acc[mi][ni][1] + b1);
            float2 v1 = make_float2(acc[mi][ni][2] + b0, acc[mi][ni][3] + b1);
            *(float2*)(C + (size_t)r0 * ldc + c0)       = v0;
            *(float2*)(C + (size_t)(r0 + 8) * ldc + c0) = v1;
        }
    }
}

// Fused QKV projection: grid (36, 8), 128 threads, 2 CTAs/SM
__global__ __launch_bounds__(128)
void qkv_mm_kernel(const __nv_bfloat16* __restrict__ Ahi, const __nv_bfloat16* __restrict__ Alo,
                   const __nv_bfloat16* __restrict__ qHi, const __nv_bfloat16* __restrict__ qLo,
                   const __nv_bfloat16* __restrict__ kHi, const __nv_bfloat16* __restrict__ kLo,
                   const __nv_bfloat16* __restrict__ vHi, const __nv_bfloat16* __restrict__ vLo,
                   const float* __restrict__ bq, const float* __restrict__ bk,
                   const float* __restrict__ bv,
                   float* __restrict__ gQ, float* __restrict__ gK, float* __restrict__ gV)
{
    extern __shared__ char smem[];
    const int bx = blockIdx.x, m0 = blockIdx.y * 128;
    if (bx < 28)
        mm_tile(Ahi, Alo, qHi, qLo, bq, gQ, HID, m0, bx * 128, 0, 56, smem);
    else if (bx < 32)
        mm_tile(Ahi, Alo, kHi, kLo, bk, gK, NKV*HDIM, m0, (bx - 28) * 128, 0, 56, smem);
    else
        mm_tile(Ahi, Alo, vHi, vLo, bv, gV, NKV*HDIM, m0, (bx - 32) * 128, 0, 56, smem);
}

// Output projection, split-K x2: grid (28, 8, 2) -> partial buffers
__global__ __launch_bounds__(128)
void oproj_kernel(const __nv_bfloat16* __restrict__ Ahi, const __nv_bfloat16* __restrict__ Alo,
                  const __nv_bfloat16* __restrict__ Bhi, const __nv_bfloat16* __restrict__ Blo,
                  float* __restrict__ P)
{
    extern __shared__ char smem[];
    const int z = blockIdx.z;
    mm_tile(Ahi, Alo, Bhi, Blo, nullptr, P + (size_t)z * QLEN * HID, HID,
            blockIdx.y * 128, blockIdx.x * 128, z * 1792, 28, smem);
}

// Sum the two split-K partials -> final output
__global__ void addout_kernel(const float* __restrict__ P, float* __restrict__ out)
{
    int i = blockIdx.x * blockDim.x + threadIdx.x;
    if (i >= QLEN * HID / 4) return;
    float4 a = ((const float4*)P)[i];
    float4 b = ((const float4*)(P + (size_t)QLEN * HID))[i];
    ((float4*)out)[i] = make_float4(a.x + b.x, a.y + b.y, a.z + b.z, a.w + b.w);
}

// ---------------------------------------------------------------------------
// RoPE + split-bf16 packing. y=0: Q rows; y=1: K rows (-> Kb rows PASTLEN+q);
// y=2: V new rows (no rope, just split-pack into Vb).
// ---------------------------------------------------------------------------
__global__ void rope_pack_kernel(const float* __restrict__ gQ, const float* __restrict__ gK,
                                 const float* __restrict__ gV, const int* __restrict__ pos,
                                 __nv_bfloat16* __restrict__ QbH, __nv_bfloat16* __restrict__ QbL,
                                 __nv_bfloat16* __restrict__ KbH, __nv_bfloat16* __restrict__ KbL,
                                 __nv_bfloat16* __restrict__ VbH, __nv_bfloat16* __restrict__ VbL)
{
    const int q = blockIdx.x;
    const int mode = blockIdx.y;

    if (mode == 2) {           // V new rows
        for (int t = threadIdx.x; t < NKV * HDIM; t += blockDim.x) {
            int kvh = t >> 7, d = t & 127;
            float v = gV[(size_t)q * (NKV*HDIM) + t];
            __nv_bfloat16 h = __float2bfloat16(v);
            __nv_bfloat16 l = __float2bfloat16(v - __bfloat162float(h));
            size_t dd = ((size_t)kvh * KVTOT + PASTLEN + q) * HDIM + d;
            VbH[dd] = h; VbL[dd] = l;
        }
        return;
    }

    __shared__ float cs[64], sn[64];
    const float p = (float)pos[q];
    if (threadIdx.x < 64) {
        float e = (float)threadIdx.x * (1.0f / 64.0f);
        float invf = 1.0f / powf(1000000.0f, e);
        sincosf(p * invf, &sn[threadIdx.x], &cs[threadIdx.x]);
    }
    __syncthreads();

    const int isK = mode;
    const int nh = isK ? NKV : NHEADS;
    const float* src = isK ? (gK + (size_t)q * (NKV*HDIM)) : (gQ + (size_t)q * HID);

    for (int t = threadIdx.x; t < nh * 64; t += blockDim.x) {
        int hh = t >> 6, i = t & 63;
        float s = sn[i], c = cs[i];
        const float* base = src + hh * HDIM;
        float x1 = base[i];
        float x2 = base[i + 64];
        float o1 = x1 * c - x2 * s;
        float o2 = x2 * c + x1 * s;
        __nv_bfloat16 h1 = __float2bfloat16(o1);
        __nv_bfloat16 l1 = __float2bfloat16(o1 - __bfloat162float(h1));
        __nv_bfloat16 h2 = __float2bfloat16(o2);
        __nv_bfloat16 l2 = __float2bfloat16(o2 - __bfloat162float(h2));
        size_t d1, d2;
        if (isK) {
            size_t row = (size_t)hh * KVTOT + PASTLEN + q;
            d1 = row * HDIM + i; d2 = d1 + 64;
            KbH[d1] = h1; KbL[d1] = l1;
            KbH[d2] = h2; KbL[d2] = l2;
        } else {
            d1 = (size_t)q * HID + hh * HDIM + i; d2 = d1 + 64;
            QbH[d1] = h1; QbL[d1] = l1;
            QbH[d2] = h2; QbL[d2] = l2;
        }
    }
}

// ---------------------------------------------------------------------------
// Tensorized flash attention, 2-way KV split, single-sync pipeline,
// Q fragments register-cached (loaded once in prologue).
// grid (8 q-tiles, 28 heads, 2 kv-splits), 256 threads = 8 warps x 16 q-rows.
// ---------------------------------------------------------------------------
#define FL_SMEM (65536 * 3)

__global__ __launch_bounds__(256, 1)
void flash_mma_kernel(const __nv_bfloat16* __restrict__ Qhi,
                      const __nv_bfloat16* __restrict__ Qlo,
                      const __nv_bfloat16* __restrict__ Kbh,
                      const __nv_bfloat16* __restrict__ Kbl,
                      const __nv_bfloat16* __restrict__ Vbh,
                      const __nv_bfloat16* __restrict__ Vbl,
                      float* __restrict__ Op, float* __restrict__ Ml)
{
    extern __shared__ char smraw[];
    const uint32_t sb = smem_to_u32(smraw);
    const int tid = threadIdx.x, wid = tid >> 5, lane = tid & 31;
    const int qt = blockIdx.x, h = blockIdx.y, z = blockIdx.z;
    const int kvh = h / NREP;
    const int q0 = qt * 128;
    const int w16 = wid * 16;
    const int nt = 50 + 2 * qt;
    const int t0 = z ? (nt >> 1) : 0;
    const int t1 = z ? nt : (nt >> 1);

    // ---- Q tile load (once) ----
    #pragma unroll
    for (int i = 0; i < 16; i++) {
        int cg = tid + i * 256;
        int comp = i >> 3;
        int c = cg & 2047;
        int row = c >> 4, d8 = (c & 15) * 8;
        uint32_t dst = sb + (uint32_t)comp * 32768 + (uint32_t)((c >> 3) & 1) * 16384
                     + SMEM_SWIZZLE_128B((uint32_t)(row * 128 + (c & 7) * 16));
        const __nv_bfloat16* src = (comp ? Qlo : Qhi);
        cp_async16(dst, src + (size_t)(q0 + row) * HID + h * HDIM + d8);
    }
    cp_commit();

    auto load_stage = [&](int t) {
        uint32_t base = sb + 65536u + (uint32_t)(t & 1) * 65536u;
        int kvbase = t * 64;
        #pragma unroll
        for (int i = 0; i < 16; i++) {
            int comp = i >> 2;
            int c = (tid + i * 256) & 1023;
            int kv = c >> 4, d8 = (c & 15) * 8;
            uint32_t dst = base + (uint32_t)comp * 16384 + (uint32_t)((c >> 3) & 1) * 8192
                         + SMEM_SWIZZLE_128B((uint32_t)(kv * 128 + (c & 7) * 16));
            const __nv_bfloat16* src =
                (comp == 0) ? Kbh : (comp == 1) ? Kbl : (comp == 2) ? Vbh : Vbl;
            cp_async16(dst, src + ((size_t)(kvh * KVTOT + kvbase + kv) * HDIM + d8));
        }
        cp_commit();
    };

    load_stage(t0);

    // ---- prologue: wait for Q (older group), register-cache all Q frags ----
    cp_wait<1>();
    __syncthreads();
    uint32_t qFh[8][4], qFl[8][4];
    #pragma unroll
    for (int kc = 0; kc < 8; kc++) {
        uint32_t qoff = (uint32_t)((w16 + (lane & 15)) * 128 + (kc & 3) * 32 + (lane >> 4) * 16);
        uint32_t qa = sb + (uint32_t)(kc >> 2) * 16384 + SMEM_SWIZZLE_128B(qoff);
        ldm_x4(qFh[kc], qa);
        ldm_x4(qFl[kc], qa + 32768);
    }

    float Oacc[16][4];
    #pragma unroll
    for (int i = 0; i < 16; i++)
        #pragma unroll
        for (int j = 0; j < 4; j++) Oacc[i][j] = 0.0f;
    float m0 = -INFINITY, m1 = -INFINITY, l0 = 0.0f, l1 = 0.0f;

    const float SL = 0.08838834764831845f * 1.4426950408889634f;
    const int r0 = lane >> 2;

    for (int t = t0; t < t1; t++) {
        cp_wait<0>();
        __syncthreads();
        if (t + 1 < t1) load_stage(t + 1);

        const uint32_t stage = sb + 65536u + (uint32_t)(t & 1) * 65536u;
        const int kvbase = t * 64;

        // ---- S = Q K^T (3-pass split; Q frags from registers) ----
        float S[8][4];
        #pragma unroll
        for (int i = 0; i < 8; i++)
            #pragma unroll
            for (int j = 0; j < 4; j++) S[i][j] = 0.0f;

        #pragma unroll
        for (int kc = 0; kc < 8; kc++) {
            uint32_t kcol = (uint32_t)((kc & 3) * 32 + ((lane >> 3) & 1) * 16);
            #pragma unroll
            for (int np = 0; np < 4; np++) {
                uint32_t koff = (uint32_t)((np * 16 + ((lane >> 4) & 1) * 8 + (lane & 7)) * 128) + kcol;
                uint32_t ka = stage + (uint32_t)(kc >> 2) * 8192 + SMEM_SWIZZLE_128B(koff);
                uint32_t kh[4], kl[4];
                ldm_x4(kh, ka);
                ldm_x4(kl, ka + 16384);
                mma_bf16(S[2*np],   qFh[kc], kh);     mma_bf16(S[2*np],   qFl[kc], kh);
                mma_bf16(S[2*np],   qFh[kc], kl);
                mma_bf16(S[2*np+1], qFh[kc], kh + 2); mma_bf16(S[2*np+1], qFl[kc], kh + 2);
                mma_bf16(S[2*np+1], qFh[kc], kl + 2);
            }
        }

        // ---- causal mask (last two global tiles; z=1 only) ----
        if (t >= nt - 2) {
            const int lim0 = PASTLEN + q0 + w16 + r0;
            const int lim1 = lim0 + 8;
            #pragma unroll
            for (int nc = 0; nc < 8; nc++) {
                int col = kvbase + nc * 8 + (lane & 3) * 2;
                if (col     > lim0) S[nc][0] = -1e30f;
                if (col + 1 > lim0) S[nc][1] = -1e30f;
                if (col     > lim1) S[nc][2] = -1e30f;
                if (col + 1 > lim1) S[nc][3] = -1e30f;
            }
        }

        // ---- online softmax ----
        float mx0 = -INFINITY, mx1 = -INFINITY;
        #pragma unroll
        for (int nc = 0; nc < 8; nc++) {
            mx0 = fmaxf(mx0, fmaxf(S[nc][0], S[nc][1]));
            mx1 = fmaxf(mx1, fmaxf(S[nc][2], S[nc][3]));
        }
        mx0 = fmaxf(mx0, __shfl_xor_sync(0xffffffffu, mx0, 1));
        mx0 = fmaxf(mx0, __shfl_xor_sync(0xffffffffu, mx0, 2));
        mx1 = fmaxf(mx1, __shfl_xor_sync(0xffffffffu, mx1, 1));
        mx1 = fmaxf(mx1, __shfl_xor_sync(0xffffffffu, mx1, 2));
        float mn0 = fmaxf(m0, mx0 * SL);
        float mn1 = fmaxf(m1, mx1 * SL);
        float cor0 = fexp2(m0 - mn0);
        float cor1 = fexp2(m1 - mn1);
        m0 = mn0; m1 = mn1;

        uint32_t pH[8][2], pL[8][2];
        float rs0 = 0.0f, rs1 = 0.0f;
        #pragma unroll
        for (int nc = 0; nc < 8; nc++) {
            float p0 = fexp2(S[nc][0] * SL - mn0);
            float p1 = fexp2(S[nc][1] * SL - mn0);
            float p2 = fexp2(S[nc][2] * SL - mn1);
            float p3 = fexp2(S[nc][3] * SL - mn1);
            rs0 += p0 + p1;  rs1 += p2 + p3;
            __nv_bfloat16 h0 = __float2bfloat16(p0), h1 = __float2bfloat16(p1);
            __nv_bfloat16 h2 = __float2bfloat16(p2), h3 = __float2bfloat16(p3);
            pH[nc][0] = packbf(h0, h1);
            pH[nc][1] = packbf(h2, h3);
            pL[nc][0] = packbf(__float2bfloat16(p0 - __bfloat162float(h0)),
                               __float2bfloat16(p1 - __bfloat162float(h1)));
            pL[nc][1] = packbf(__float2bfloat16(p2 - __bfloat162float(h2)),
                               __float2bfloat16(p3 - __bfloat162float(h3)));
        }
        rs0 += __shfl_xor_sync(0xffffffffu, rs0, 1);
        rs0 += __shfl_xor_sync(0xffffffffu, rs0, 2);
        rs1 += __shfl_xor_sync(0xffffffffu, rs1, 1);
        rs1 += __shfl_xor_sync(0xffffffffu, rs1, 2);
        l0 = l0 * cor0 + rs0;
        l1 = l1 * cor1 + rs1;

        #pragma unroll
        for (int nc = 0; nc < 16; nc++) {
            Oacc[nc][0] *= cor0; Oacc[nc][1] *= cor0;
            Oacc[nc][2] *= cor1; Oacc[nc][3] *= cor1;
        }

        // ---- O += P V (3-pass split) ----
        #pragma unroll
        for (int kc = 0; kc < 4; kc++) {
            uint32_t aH[4] = { pH[2*kc][0], pH[2*kc][1], pH[2*kc+1][0], pH[2*kc+1][1] };
            uint32_t aL[4] = { pL[2*kc][0], pL[2*kc][1], pL[2*kc+1][0], pL[2*kc+1][1] };
            uint32_t vrow = (uint32_t)(kc * 16 + ((lane >> 3) & 1) * 8 + (lane & 7));
            #pragma unroll
            for (int dp = 0; dp < 8; dp++) {
                uint32_t voff = vrow * 128 + (uint32_t)((dp & 3) * 32 + ((lane >> 4) & 1) * 16);
                uint32_t va = stage + 32768u + (uint32_t)(dp >> 2) * 8192 + SMEM_SWIZZLE_128B(voff);
                uint32_t vh[4], vl[4];
                ldm_x4t(vh, va);
                ldm_x4t(vl, va + 16384);
                mma_bf16(Oacc[2*dp],   aH, vh);     mma_bf16(Oacc[2*dp],   aL, vh);
                mma_bf16(Oacc[2*dp],   aH, vl);
                mma_bf16(Oacc[2*dp+1], aH, vh + 2); mma_bf16(Oacc[2*dp+1], aL, vh + 2);
                mma_bf16(Oacc[2*dp+1], aH, vl + 2);
            }
        }
    }

    // ---- epilogue: write raw partials ----
    const int rowa = q0 + w16 + r0;
    const size_t pb = ((size_t)(z * NHEADS + h) * QLEN);
    #pragma unroll
    for (int nc = 0; nc < 16; nc++) {
        int col = nc * 8 + (lane & 3) * 2;
        *(float2*)(Op + (pb + rowa) * HDIM + col) =
            make_float2(Oacc[nc][0], Oacc[nc][1]);
        *(float2*)(Op + (pb + rowa + 8) * HDIM + col) =
            make_float2(Oacc[nc][2], Oacc[nc][3]);
    }
    if ((lane & 3) == 0) {
        Ml[(pb + rowa) * 2]     = m0;
        Ml[(pb + rowa) * 2 + 1] = l0;
        Ml[(pb + rowa + 8) * 2]     = m1;
        Ml[(pb + rowa + 8) * 2 + 1] = l1;
    }
}

// Merge the two KV-split partials -> split-bf16 attention output (oproj A operand)
__global__ void combine_split_kernel(const float* __restrict__ Op,
                                     const float* __restrict__ Ml,
                                     __nv_bfloat16* __restrict__ aHi,
                                     __nv_bfloat16* __restrict__ aLo)
{
    int i = blockIdx.x * blockDim.x + threadIdx.x;
    if (i >= NHEADS * QLEN * (HDIM / 4)) return;
    int hq = i >> 5;
    int d4 = (i & 31) * 4;
    int h = hq >> 10, q = hq & 1023;
    size_t p0 = (size_t)h * QLEN + q;
    size_t p1 = (size_t)(NHEADS + h) * QLEN + q;
    float m0 = Ml[p0 * 2], l0 = Ml[p0 * 2 + 1];
    float m1 = Ml[p1 * 2], l1 = Ml[p1 * 2 + 1];
    float m = fmaxf(m0, m1);
    float s0 = fexp2(m0 - m), s1 = fexp2(m1 - m);
    float inv = 1.0f / (l0 * s0 + l1 * s1);
    s0 *= inv; s1 *= inv;
    float4 a = *(const float4*)(Op + p0 * HDIM + d4);
    float4 b = *(const float4*)(Op + p1 * HDIM + d4);
    float o[4] = { a.x * s0 + b.x * s1, a.y * s0 + b.y * s1,
                   a.z * s0 + b.z * s1, a.w * s0 + b.w * s1 };
    __nv_bfloat16 h4[4], l4[4];
    #pragma unroll
    for (int j = 0; j < 4; j++) {
        h4[j] = __float2bfloat16(o[j]);
        l4[j] = __float2bfloat16(o[j] - __bfloat162float(h4[j]));
    }
    size_t od = ((size_t)q * HID + h * HDIM + d4) >> 1;
    ((__nv_bfloat162*)aHi)[od]     = __nv_bfloat162(h4[0], h4[1]);
    ((__nv_bfloat162*)aHi)[od + 1] = __nv_bfloat162(h4[2], h4[3]);
    ((__nv_bfloat162*)aLo)[od]     = __nv_bfloat162(l4[0], l4[1]);
    ((__nv_bfloat162*)aLo)[od + 1] = __nv_bfloat162(l4[2], l4[3]);
}

// ---------------------------------------------------------------------------
// Launch
// ---------------------------------------------------------------------------
extern "C" void kernel_launch(void* const* d_in, const int* in_sizes, int n_in,
                              void* d_out, int out_size)
{
    const float* hid = (const float*)d_in[0];
    const float* kc  = (const float*)d_in[1];
    const float* vc  = (const float*)d_in[2];
    const float* Wq  = (const float*)d_in[3];
    const float* bq  = (const float*)d_in[4];
    const float* Wk  = (const float*)d_in[5];
    const float* bk  = (const float*)d_in[6];
    const float* Wv  = (const float*)d_in[7];
    const float* bv  = (const float*)d_in[8];
    const float* Wo  = (const float*)d_in[9];
    const int*   pos = (const int*)d_in[10];
    float* out = (float*)d_out;

    float *gQ, *gK, *gV, *gOp, *gMl;
    cudaGetSymbolAddress((void**)&gQ, g_Q);
    cudaGetSymbolAddress((void**)&gK, g_K);
    cudaGetSymbolAddress((void**)&gV, g_V);
    cudaGetSymbolAddress((void**)&gOp, g_Op);
    cudaGetSymbolAddress((void**)&gMl, g_Ml);
    __nv_bfloat16 *hHi, *hLo, *aHi, *aLo;
    __nv_bfloat16 *qHi, *qLo, *kHi, *kLo, *vHi, *vLo, *oHi, *oLo;
    __nv_bfloat16 *QbH, *QbL, *KbH, *KbL, *VbH, *VbL;
    cudaGetSymbolAddress((void**)&hHi, g_hid_hi);
    cudaGetSymbolAddress((void**)&hLo, g_hid_lo);
    cudaGetSymbolAddress((void**)&aHi, g_att_hi);
    cudaGetSymbolAddress((void**)&aLo, g_att_lo);
    cudaGetSymbolAddress((void**)&qHi, g_WqT_hi);
    cudaGetSymbolAddress((void**)&qLo, g_WqT_lo);
    cudaGetSymbolAddress((void**)&kHi, g_WkT_hi);
    cudaGetSymbolAddress((void**)&kLo, g_WkT_lo);
    cudaGetSymbolAddress((void**)&vHi, g_WvT_hi);
    cudaGetSymbolAddress((void**)&vLo, g_WvT_lo);
    cudaGetSymbolAddress((void**)&oHi, g_WoT_hi);
    cudaGetSymbolAddress((void**)&oLo, g_WoT_lo);
    cudaGetSymbolAddress((void**)&QbH, g_Qb_hi);
    cudaGetSymbolAddress((void**)&QbL, g_Qb_lo);
    cudaGetSymbolAddress((void**)&KbH, g_Kb_hi);
    cudaGetSymbolAddress((void**)&KbL, g_Kb_lo);
    cudaGetSymbolAddress((void**)&VbH, g_Vb_hi);
    cudaGetSymbolAddress((void**)&VbL, g_Vb_lo);

    cudaFuncSetAttribute(qkv_mm_kernel, cudaFuncAttributeMaxDynamicSharedMemorySize, MM_SMEM);
    cudaFuncSetAttribute(oproj_kernel, cudaFuncAttributeMaxDynamicSharedMemorySize, MM_SMEM);
    cudaFuncSetAttribute(flash_mma_kernel, cudaFuncAttributeMaxDynamicSharedMemorySize, FL_SMEM);

    // 1. operand preparation (all independent of each other)
    const int n4 = QLEN * HID / 4;
    split_kernel<<<(n4 + 255) / 256, 256>>>(hid, hHi, hLo, n4);
    transpose_split_all<<<dim3(112, 112, 4), dim3(32, 8)>>>(
        Wq, Wk, Wv, Wo, qHi, qLo, kHi, kLo, vHi, vLo, oHi, oLo);
    pack_kv_kernel<<<dim3((NKV * PASTLEN * 32 + 255) / 256, 2), 256>>>(
        kc, vc, KbH, KbL, VbH, VbL);

    // 2. fused QKV projections (2 CTAs/SM)
    qkv_mm_kernel<<<dim3(36, 8), 128, MM_SMEM>>>(hHi, hLo, qHi, qLo, kHi, kLo, vHi, vLo,
                                                 bq, bk, bv, gQ, gK, gV);

    // 3. RoPE + split packing of Q, new-K, new-V
    rope_pack_kernel<<<dim3(QLEN, 3), 256>>>(gQ, gK, gV, pos, QbH, QbL, KbH, KbL, VbH, VbL);

    // 4. attention (tensorized, 2-way KV split) + combine-with-split
    flash_mma_kernel<<<dim3(8, 28, 2), 256, FL_SMEM>>>(QbH, QbL, KbH, KbL, VbH, VbL, gOp, gMl);
    const int cn = NHEADS * QLEN * (HDIM / 4);
    combine_split_kernel<<<(cn + 255) / 256, 256>>>(gOp, gMl, aHi, aLo);

    // 5. output projection (split-K x2 into partials, then add)
    oproj_kernel<<<dim3(28, 8, 2), 128, MM_SMEM>>>(aHi, aLo, oHi, oLo, gOp);
    addout_kernel<<<(n4 + 255) / 256, 256>>>(gOp, out);
}